// round 2
// baseline (speedup 1.0000x reference)
#include <cuda_runtime.h>
#include <cstdint>

// MultiHeadAttention: B=4, I=J=2048, WIDTH=1024, HEADS=16, HEAD_DIM=64
// Outputs (concatenated): out [4,2048,1024] fp32, attn_weight [4,16,2048,2048] fp32
//
// Pipeline (tf32 mma.sync m16n8k8, rna-rounded):
//   0.   mask_any:     per-(b,128x128 tile) OR-flag so scores can skip mask loads
//   1-3. proj_kernel:  Qp/Kp/Vp = x @ W^T
//   4.   scores_kernel: E = exp(mask(Q K^T)/8), smem-staged coalesced stores,
//                       per-block rowsum partials
//   5.   reduce_sums:  rowsum = sum of 16 partials (deterministic order)
//   6.   pv_kernel:    normalizes E in place (write-back) AND X = softmax @ V
//   7.   out_kernel:   out = X @ Wo^T

#define IW 2097152ULL
#define HEADELEMS 131072ULL
#define ATTN_PER_HEAD 4194304ULL
#define NROWS 131072

__device__ float g_qp[8388608];
__device__ float g_kp[8388608];
__device__ float g_vp[8388608];
__device__ float g_x [8388608];
__device__ float g_sum[NROWS];
__device__ float g_part[NROWS * 16];
__device__ int   g_mflag[1024];   // (b*256 + iblk*16 + jblk)

__device__ __forceinline__ uint32_t f2tf(float x) {
    uint32_t u;
    asm("cvt.rna.tf32.f32 %0, %1;" : "=r"(u) : "f"(x));
    return u;
}

__device__ __forceinline__ void mma8(float* c, const uint32_t* a, const uint32_t* b) {
    asm("mma.sync.aligned.m16n8k8.row.col.f32.tf32.tf32.f32 "
        "{%0,%1,%2,%3}, {%4,%5,%6,%7}, {%8,%9}, {%0,%1,%2,%3};"
        : "+f"(c[0]), "+f"(c[1]), "+f"(c[2]), "+f"(c[3])
        : "r"(a[0]), "r"(a[1]), "r"(a[2]), "r"(a[3]), "r"(b[0]), "r"(b[1]));
}

// ---------------------------------------------------------------------------
// mask_any: OR-reduce each 128x128 mask tile into g_mflag. 1024 blocks.
// ---------------------------------------------------------------------------
__global__ void mask_any_kernel(const unsigned char* __restrict__ mask)
{
    int bid = blockIdx.x;
    int b = bid >> 8, rem = bid & 255, ib = rem >> 4, jb = rem & 15;
    const unsigned char* base = mask + (size_t)b * ATTN_PER_HEAD
                                     + (size_t)ib * 128 * 2048 + (size_t)jb * 128;
    unsigned acc = 0;
    #pragma unroll
    for (int v = 0; v < 4; v++) {
        int idx = threadIdx.x + v * 256;       // 1024 x uint4 = 128 rows x 8
        int r = idx >> 3, c = (idx & 7) * 16;
        uint4 m = *(const uint4*)(base + (size_t)r * 2048 + c);
        acc |= m.x | m.y | m.z | m.w;
    }
    int any = __syncthreads_or(acc != 0);
    if (threadIdx.x == 0) g_mflag[bid] = any;
}

// ---------------------------------------------------------------------------
// Generic 128x128-tile TN GEMM body, M=8192, N=1024, K=1024.
// ---------------------------------------------------------------------------
__device__ __forceinline__ void gemm1024_body(const float* __restrict__ A,
                                              const float* __restrict__ W,
                                              float* __restrict__ C)
{
    __shared__ uint32_t As[128 * 36];
    __shared__ uint32_t Bs[128 * 36];
    const int tid  = threadIdx.x;
    const int wid  = tid >> 5, lane = tid & 31;
    const int gid  = lane >> 2, tig = lane & 3;
    const int wrow = wid >> 2, wcol = wid & 3;
    const float* Ab = A + (size_t)blockIdx.y * 128 * 1024;
    const float* Bb = W + (size_t)blockIdx.x * 128 * 1024;

    float c[4][4][4];
    #pragma unroll
    for (int mi = 0; mi < 4; mi++)
        #pragma unroll
        for (int ni = 0; ni < 4; ni++)
            #pragma unroll
            for (int r = 0; r < 4; r++) c[mi][ni][r] = 0.f;

    for (int kt = 0; kt < 1024; kt += 32) {
        #pragma unroll
        for (int v = 0; v < 4; v++) {
            int i4 = tid + v * 256;
            int r = i4 >> 3, c4 = (i4 & 7) << 2;
            float4 fa = *(const float4*)(Ab + (size_t)r * 1024 + kt + c4);
            uint32_t* da = &As[r * 36 + c4];
            da[0] = f2tf(fa.x); da[1] = f2tf(fa.y); da[2] = f2tf(fa.z); da[3] = f2tf(fa.w);
            float4 fb = *(const float4*)(Bb + (size_t)r * 1024 + kt + c4);
            uint32_t* db = &Bs[r * 36 + c4];
            db[0] = f2tf(fb.x); db[1] = f2tf(fb.y); db[2] = f2tf(fb.z); db[3] = f2tf(fb.w);
        }
        __syncthreads();
        #pragma unroll
        for (int kk = 0; kk < 32; kk += 8) {
            uint32_t af[4][4], bf[4][2];
            #pragma unroll
            for (int mi = 0; mi < 4; mi++) {
                int m = wrow * 64 + mi * 16 + gid;
                af[mi][0] = As[m * 36 + kk + tig];
                af[mi][1] = As[(m + 8) * 36 + kk + tig];
                af[mi][2] = As[m * 36 + kk + tig + 4];
                af[mi][3] = As[(m + 8) * 36 + kk + tig + 4];
            }
            #pragma unroll
            for (int ni = 0; ni < 4; ni++) {
                int n = wcol * 32 + ni * 8 + gid;
                bf[ni][0] = Bs[n * 36 + kk + tig];
                bf[ni][1] = Bs[n * 36 + kk + tig + 4];
            }
            #pragma unroll
            for (int mi = 0; mi < 4; mi++)
                #pragma unroll
                for (int ni = 0; ni < 4; ni++)
                    mma8(c[mi][ni], af[mi], bf[ni]);
        }
        __syncthreads();
    }

    #pragma unroll
    for (int mi = 0; mi < 4; mi++)
        #pragma unroll
        for (int ni = 0; ni < 4; ni++) {
            int row = blockIdx.y * 128 + wrow * 64 + mi * 16 + gid;
            int col = blockIdx.x * 128 + wcol * 32 + ni * 8 + tig * 2;
            *(float2*)(C + (size_t)row * 1024 + col)       = make_float2(c[mi][ni][0], c[mi][ni][1]);
            *(float2*)(C + (size_t)(row + 8) * 1024 + col) = make_float2(c[mi][ni][2], c[mi][ni][3]);
        }
}

__global__ __launch_bounds__(256, 2)
void proj_kernel(const float* __restrict__ A, const float* __restrict__ W, int which)
{
    float* C = (which == 0) ? g_qp : (which == 1) ? g_kp : g_vp;
    gemm1024_body(A, W, C);
}

__global__ __launch_bounds__(256, 2)
void out_kernel(const float* __restrict__ W, float* __restrict__ C)
{
    gemm1024_body(g_x, W, C);
}

// ---------------------------------------------------------------------------
// Scores: per head z, E = exp(mask(Q K^T)/8). Epilogue stages through smem for
// coalesced STG.128; mask loads skipped when the tile flag is clear.
// Grid (16 jblk, 16 iblk, 64 heads).
// ---------------------------------------------------------------------------
__global__ __launch_bounds__(256, 2)
void scores_kernel(const unsigned char* __restrict__ mask, float* __restrict__ E)
{
    __shared__ uint32_t SH[2 * 128 * 36];
    __shared__ float swsum[4 * 128];
    uint32_t* As = SH;
    uint32_t* Bs = SH + 128 * 36;
    float*    Est = (float*)SH;          // staging after mainloop (64 rows x 132)

    const int tid  = threadIdx.x;
    const int wid  = tid >> 5, lane = tid & 31;
    const int gid  = lane >> 2, tig = lane & 3;
    const int wrow = wid >> 2, wcol = wid & 3;
    const int z = blockIdx.z;
    const float* Ab = g_qp + (size_t)z * HEADELEMS + (size_t)blockIdx.y * 128 * 64;
    const float* Bb = g_kp + (size_t)z * HEADELEMS + (size_t)blockIdx.x * 128 * 64;

    float c[4][4][4];
    #pragma unroll
    for (int mi = 0; mi < 4; mi++)
        #pragma unroll
        for (int ni = 0; ni < 4; ni++)
            #pragma unroll
            for (int r = 0; r < 4; r++) c[mi][ni][r] = 0.f;

    #pragma unroll
    for (int kt = 0; kt < 64; kt += 32) {
        #pragma unroll
        for (int v = 0; v < 4; v++) {
            int i4 = tid + v * 256;
            int r = i4 >> 3, c4 = (i4 & 7) << 2;
            float4 fa = *(const float4*)(Ab + (size_t)r * 64 + kt + c4);
            uint32_t* da = &As[r * 36 + c4];
            da[0] = f2tf(fa.x); da[1] = f2tf(fa.y); da[2] = f2tf(fa.z); da[3] = f2tf(fa.w);
            float4 fb = *(const float4*)(Bb + (size_t)r * 64 + kt + c4);
            uint32_t* db = &Bs[r * 36 + c4];
            db[0] = f2tf(fb.x); db[1] = f2tf(fb.y); db[2] = f2tf(fb.z); db[3] = f2tf(fb.w);
        }
        __syncthreads();
        #pragma unroll
        for (int kk = 0; kk < 32; kk += 8) {
            uint32_t af[4][4], bf[4][2];
            #pragma unroll
            for (int mi = 0; mi < 4; mi++) {
                int m = wrow * 64 + mi * 16 + gid;
                af[mi][0] = As[m * 36 + kk + tig];
                af[mi][1] = As[(m + 8) * 36 + kk + tig];
                af[mi][2] = As[m * 36 + kk + tig + 4];
                af[mi][3] = As[(m + 8) * 36 + kk + tig + 4];
            }
            #pragma unroll
            for (int ni = 0; ni < 4; ni++) {
                int n = wcol * 32 + ni * 8 + gid;
                bf[ni][0] = Bs[n * 36 + kk + tig];
                bf[ni][1] = Bs[n * 36 + kk + tig + 4];
            }
            #pragma unroll
            for (int mi = 0; mi < 4; mi++)
                #pragma unroll
                for (int ni = 0; ni < 4; ni++)
                    mma8(c[mi][ni], af[mi], bf[ni]);
        }
        __syncthreads();
    }

    // ---- epilogue: exp (+optional mask) in registers, rowsum partials ----
    const bool use_mask = g_mflag[((z >> 4) << 8) + blockIdx.y * 16 + blockIdx.x] != 0;
    const unsigned char* mb = mask + (size_t)(z >> 4) * ATTN_PER_HEAD;

    #pragma unroll
    for (int mi = 0; mi < 4; mi++) {
        #pragma unroll
        for (int h = 0; h < 2; h++) {
            int rl = wrow * 64 + mi * 16 + h * 8 + gid;
            size_t gi = (size_t)blockIdx.y * 128 + rl;
            float rs = 0.f;
            #pragma unroll
            for (int ni = 0; ni < 4; ni++) {
                int cl = wcol * 32 + ni * 8 + tig * 2;
                float s0 = c[mi][ni][h * 2 + 0];
                float s1 = c[mi][ni][h * 2 + 1];
                if (use_mask) {
                    size_t gj = (size_t)blockIdx.x * 128 + cl;
                    if (mb[gi * 2048 + gj])     s0 = -1e9f;
                    if (mb[gi * 2048 + gj + 1]) s1 = -1e9f;
                }
                float e0 = __expf(s0 * 0.125f);
                float e1 = __expf(s1 * 0.125f);
                c[mi][ni][h * 2 + 0] = e0;
                c[mi][ni][h * 2 + 1] = e1;
                rs += e0 + e1;
            }
            rs += __shfl_xor_sync(0xffffffffu, rs, 1);
            rs += __shfl_xor_sync(0xffffffffu, rs, 2);
            if (tig == 0) swsum[wcol * 128 + rl] = rs;
        }
    }
    __syncthreads();
    if (tid < 128) {
        float p = swsum[tid] + swsum[128 + tid] + swsum[256 + tid] + swsum[384 + tid];
        g_part[((size_t)z * 2048 + blockIdx.y * 128 + tid) * 16 + blockIdx.x] = p;
    }

    // ---- stage halves (64 rows) through smem, write coalesced float4 ----
    float* Eh = E + (size_t)z * ATTN_PER_HEAD
                  + (size_t)blockIdx.y * 128 * 2048 + (size_t)blockIdx.x * 128;
    #pragma unroll
    for (int h2 = 0; h2 < 2; h2++) {
        if (wrow == h2) {
            #pragma unroll
            for (int mi = 0; mi < 4; mi++)
                #pragma unroll
                for (int h = 0; h < 2; h++) {
                    int rloc = mi * 16 + h * 8 + gid;
                    #pragma unroll
                    for (int ni = 0; ni < 4; ni++) {
                        int cl = wcol * 32 + ni * 8 + tig * 2;
                        Est[rloc * 132 + cl]     = c[mi][ni][h * 2 + 0];
                        Est[rloc * 132 + cl + 1] = c[mi][ni][h * 2 + 1];
                    }
                }
        }
        __syncthreads();
        #pragma unroll
        for (int v = 0; v < 8; v++) {
            int idx = tid + v * 256;           // 2048 float4 = 64 rows x 32
            int r = idx >> 5, c4 = (idx & 31) * 4;
            float4 val = *(const float4*)&Est[r * 132 + c4];
            *(float4*)(Eh + (size_t)(h2 * 64 + r) * 2048 + c4) = val;
        }
        __syncthreads();
    }
}

__global__ void reduce_sums_kernel()
{
    int i = blockIdx.x * 256 + threadIdx.x;
    if (i < NROWS) {
        const float* p = &g_part[(size_t)i * 16];
        float s = 0.f;
        #pragma unroll
        for (int j = 0; j < 16; j++) s += p[j];
        g_sum[i] = s;
    }
}

// ---------------------------------------------------------------------------
// PV (+fused normalize): per head z, scales each E element by 1/rowsum at load,
// writes it back (normalized attn output), and accumulates X = softmax @ V.
// Grid (1, 16, 64).
// ---------------------------------------------------------------------------
__global__ __launch_bounds__(256, 2)
void pv_kernel(float* __restrict__ E)
{
    __shared__ uint32_t Es[128 * 36];
    __shared__ uint32_t Vs[32 * 72];
    __shared__ float sinv[128];
    const int tid  = threadIdx.x;
    const int wid  = tid >> 5, lane = tid & 31;
    const int gid  = lane >> 2, tig = lane & 3;
    const int wrow = wid >> 1, wcol = wid & 1;
    const int z = blockIdx.z;
    float* Eh = E + (size_t)z * ATTN_PER_HEAD + (size_t)blockIdx.y * 128 * 2048;
    const float* Vh = g_vp + (size_t)z * HEADELEMS;

    if (tid < 128) sinv[tid] = 1.0f / g_sum[(size_t)z * 2048 + blockIdx.y * 128 + tid];
    __syncthreads();

    float c[2][4][4];
    #pragma unroll
    for (int mi = 0; mi < 2; mi++)
        #pragma unroll
        for (int ni = 0; ni < 4; ni++)
            #pragma unroll
            for (int r = 0; r < 4; r++) c[mi][ni][r] = 0.f;

    for (int kt = 0; kt < 2048; kt += 32) {
        #pragma unroll
        for (int v = 0; v < 4; v++) {
            int i4 = tid + v * 256;
            int r = i4 >> 3, c4 = (i4 & 7) << 2;
            float4 fe = *(const float4*)(Eh + (size_t)r * 2048 + kt + c4);
            float iv = sinv[r];
            fe.x *= iv; fe.y *= iv; fe.z *= iv; fe.w *= iv;
            *(float4*)(Eh + (size_t)r * 2048 + kt + c4) = fe;   // normalized write-back
            uint32_t* de = &Es[r * 36 + c4];
            de[0] = f2tf(fe.x); de[1] = f2tf(fe.y); de[2] = f2tf(fe.z); de[3] = f2tf(fe.w);
        }
        #pragma unroll
        for (int v = 0; v < 2; v++) {
            int f = tid + v * 256;
            int r = f >> 4, c4 = (f & 15) << 2;
            float4 fv = *(const float4*)(Vh + (size_t)(kt + r) * 64 + c4);
            uint32_t* dv = &Vs[r * 72 + c4];
            dv[0] = f2tf(fv.x); dv[1] = f2tf(fv.y); dv[2] = f2tf(fv.z); dv[3] = f2tf(fv.w);
        }
        __syncthreads();
        #pragma unroll
        for (int kk = 0; kk < 32; kk += 8) {
            uint32_t af[2][4], bf[4][2];
            #pragma unroll
            for (int mi = 0; mi < 2; mi++) {
                int m = wrow * 32 + mi * 16 + gid;
                af[mi][0] = Es[m * 36 + kk + tig];
                af[mi][1] = Es[(m + 8) * 36 + kk + tig];
                af[mi][2] = Es[m * 36 + kk + tig + 4];
                af[mi][3] = Es[(m + 8) * 36 + kk + tig + 4];
            }
            #pragma unroll
            for (int ni = 0; ni < 4; ni++) {
                int n = wcol * 32 + ni * 8 + gid;
                bf[ni][0] = Vs[(kk + tig) * 72 + n];
                bf[ni][1] = Vs[(kk + tig + 4) * 72 + n];
            }
            #pragma unroll
            for (int mi = 0; mi < 2; mi++)
                #pragma unroll
                for (int ni = 0; ni < 4; ni++)
                    mma8(c[mi][ni], af[mi], bf[ni]);
        }
        __syncthreads();
    }

    const int b = z >> 4, n = z & 15;
    #pragma unroll
    for (int mi = 0; mi < 2; mi++) {
        #pragma unroll
        for (int h = 0; h < 2; h++) {
            int i = blockIdx.y * 128 + wrow * 32 + mi * 16 + h * 8 + gid;
            float* Xr = g_x + (size_t)b * IW + (size_t)i * 1024 + n * 64;
            #pragma unroll
            for (int ni = 0; ni < 4; ni++) {
                int d = wcol * 32 + ni * 8 + tig * 2;
                *(float2*)(Xr + d) = make_float2(c[mi][ni][h * 2], c[mi][ni][h * 2 + 1]);
            }
        }
    }
}

extern "C" void kernel_launch(void* const* d_in, const int* in_sizes, int n_in,
                              void* d_out, int out_size)
{
    const float* q  = (const float*)d_in[0];
    const float* k  = (const float*)d_in[1];
    const float* v  = (const float*)d_in[2];
    const unsigned char* mask = (const unsigned char*)d_in[3];
    const float* Wq = (const float*)d_in[4];
    const float* Wk = (const float*)d_in[5];
    const float* Wv = (const float*)d_in[6];
    const float* Wo = (const float*)d_in[7];

    float* out  = (float*)d_out;            // [4,2048,1024]
    float* attn = out + 8388608;            // [4,16,2048,2048]

    mask_any_kernel<<<1024, 256>>>(mask);

    dim3 gProj(8, 64, 1);
    proj_kernel<<<gProj, 256>>>(q, Wq, 0);
    proj_kernel<<<gProj, 256>>>(k, Wk, 1);
    proj_kernel<<<gProj, 256>>>(v, Wv, 2);

    scores_kernel<<<dim3(16, 16, 64), 256>>>(mask, attn);
    reduce_sums_kernel<<<512, 256>>>();
    pv_kernel<<<dim3(1, 16, 64), 256>>>(attn);
    out_kernel<<<gProj, 256>>>(Wo, out);
}

// round 3
// speedup vs baseline: 1.2773x; 1.2773x over previous
#include <cuda_runtime.h>
#include <cstdint>

// MultiHeadAttention: B=4, I=J=2048, WIDTH=1024, HEADS=16, HEAD_DIM=64
// Outputs: out [4,2048,1024] fp32, attn_weight [4,16,2048,2048] fp32 (normalized)
//
// Pipeline:
//   0.   mask_any:   per-(b,128x128) OR-flag (skip mask loads on clear tiles)
//   1-3. proj:       Qp/Kp/Vp = x @ W^T         (tf32 mma, unchanged)
//   4.   fused_attn: per (iblk=128 rows, head):
//          pass1: S=QK^T tiles (j-tile 64), exp, rowsums in regs/smem (no stores)
//          pass2: recompute S (bitwise identical), exp, *1/rowsum,
//                 Es smem tile -> coalesced STG.128 of normalized E,
//                 O += Es @ V accumulated in regs; write O into g_x
//   5.   out:        out = g_x @ Wo^T

#define IW 2097152ULL
#define HEADELEMS 131072ULL
#define ATTN_PER_HEAD 4194304ULL

__device__ float g_qp[8388608];
__device__ float g_kp[8388608];
__device__ float g_vp[8388608];
__device__ float g_x [8388608];
__device__ int   g_mflag[1024];   // (b*256 + iblk*16 + jblk128)

__device__ __forceinline__ uint32_t f2tf(float x) {
    uint32_t u;
    asm("cvt.rna.tf32.f32 %0, %1;" : "=r"(u) : "f"(x));
    return u;
}

__device__ __forceinline__ void mma8(float* c, const uint32_t* a, const uint32_t* b) {
    asm("mma.sync.aligned.m16n8k8.row.col.f32.tf32.tf32.f32 "
        "{%0,%1,%2,%3}, {%4,%5,%6,%7}, {%8,%9}, {%0,%1,%2,%3};"
        : "+f"(c[0]), "+f"(c[1]), "+f"(c[2]), "+f"(c[3])
        : "r"(a[0]), "r"(a[1]), "r"(a[2]), "r"(a[3]), "r"(b[0]), "r"(b[1]));
}

// ---------------------------------------------------------------------------
__global__ void mask_any_kernel(const unsigned char* __restrict__ mask)
{
    int bid = blockIdx.x;
    int b = bid >> 8, rem = bid & 255, ib = rem >> 4, jb = rem & 15;
    const unsigned char* base = mask + (size_t)b * ATTN_PER_HEAD
                                     + (size_t)ib * 128 * 2048 + (size_t)jb * 128;
    unsigned acc = 0;
    #pragma unroll
    for (int v = 0; v < 4; v++) {
        int idx = threadIdx.x + v * 256;
        int r = idx >> 3, c = (idx & 7) * 16;
        uint4 m = *(const uint4*)(base + (size_t)r * 2048 + c);
        acc |= m.x | m.y | m.z | m.w;
    }
    int any = __syncthreads_or(acc != 0);
    if (threadIdx.x == 0) g_mflag[bid] = any;
}

// ---------------------------------------------------------------------------
// Generic 128x128-tile TN GEMM, M=8192, N=1024, K=1024 (unchanged, proven).
// ---------------------------------------------------------------------------
__device__ __forceinline__ void gemm1024_body(const float* __restrict__ A,
                                              const float* __restrict__ W,
                                              float* __restrict__ C)
{
    __shared__ uint32_t As[128 * 36];
    __shared__ uint32_t Bs[128 * 36];
    const int tid  = threadIdx.x;
    const int wid  = tid >> 5, lane = tid & 31;
    const int gid  = lane >> 2, tig = lane & 3;
    const int wrow = wid >> 2, wcol = wid & 3;
    const float* Ab = A + (size_t)blockIdx.y * 128 * 1024;
    const float* Bb = W + (size_t)blockIdx.x * 128 * 1024;

    float c[4][4][4];
    #pragma unroll
    for (int mi = 0; mi < 4; mi++)
        #pragma unroll
        for (int ni = 0; ni < 4; ni++)
            #pragma unroll
            for (int r = 0; r < 4; r++) c[mi][ni][r] = 0.f;

    for (int kt = 0; kt < 1024; kt += 32) {
        #pragma unroll
        for (int v = 0; v < 4; v++) {
            int i4 = tid + v * 256;
            int r = i4 >> 3, c4 = (i4 & 7) << 2;
            float4 fa = *(const float4*)(Ab + (size_t)r * 1024 + kt + c4);
            uint32_t* da = &As[r * 36 + c4];
            da[0] = f2tf(fa.x); da[1] = f2tf(fa.y); da[2] = f2tf(fa.z); da[3] = f2tf(fa.w);
            float4 fb = *(const float4*)(Bb + (size_t)r * 1024 + kt + c4);
            uint32_t* db = &Bs[r * 36 + c4];
            db[0] = f2tf(fb.x); db[1] = f2tf(fb.y); db[2] = f2tf(fb.z); db[3] = f2tf(fb.w);
        }
        __syncthreads();
        #pragma unroll
        for (int kk = 0; kk < 32; kk += 8) {
            uint32_t af[4][4], bf[4][2];
            #pragma unroll
            for (int mi = 0; mi < 4; mi++) {
                int m = wrow * 64 + mi * 16 + gid;
                af[mi][0] = As[m * 36 + kk + tig];
                af[mi][1] = As[(m + 8) * 36 + kk + tig];
                af[mi][2] = As[m * 36 + kk + tig + 4];
                af[mi][3] = As[(m + 8) * 36 + kk + tig + 4];
            }
            #pragma unroll
            for (int ni = 0; ni < 4; ni++) {
                int n = wcol * 32 + ni * 8 + gid;
                bf[ni][0] = Bs[n * 36 + kk + tig];
                bf[ni][1] = Bs[n * 36 + kk + tig + 4];
            }
            #pragma unroll
            for (int mi = 0; mi < 4; mi++)
                #pragma unroll
                for (int ni = 0; ni < 4; ni++)
                    mma8(c[mi][ni], af[mi], bf[ni]);
        }
        __syncthreads();
    }

    #pragma unroll
    for (int mi = 0; mi < 4; mi++)
        #pragma unroll
        for (int ni = 0; ni < 4; ni++) {
            int row = blockIdx.y * 128 + wrow * 64 + mi * 16 + gid;
            int col = blockIdx.x * 128 + wcol * 32 + ni * 8 + tig * 2;
            *(float2*)(C + (size_t)row * 1024 + col)       = make_float2(c[mi][ni][0], c[mi][ni][1]);
            *(float2*)(C + (size_t)(row + 8) * 1024 + col) = make_float2(c[mi][ni][2], c[mi][ni][3]);
        }
}

__global__ __launch_bounds__(256, 2)
void proj_kernel(const float* __restrict__ A, const float* __restrict__ W, int which)
{
    float* C = (which == 0) ? g_qp : (which == 1) ? g_kp : g_vp;
    gemm1024_body(A, W, C);
}

__global__ __launch_bounds__(256, 2)
void out_kernel(const float* __restrict__ W, float* __restrict__ C)
{
    gemm1024_body(g_x, W, C);
}

// ---------------------------------------------------------------------------
// Fused attention. Block = 512 threads (16 warps, 4x4), per (iblk, head z).
// j-tile = 64. Dynamic smem layout (uint32 offsets):
//   Qs 128x68 | Ks 2x 64x68 | Vs 2x 64x72 | Es 128x68 (pass1: swsum scratch) | sinv 128
// ---------------------------------------------------------------------------
#define QS_OFF   0
#define KS_OFF   8704
#define KS_BUF   4352
#define VS_OFF   17408
#define VS_BUF   4608
#define ES_OFF   26624
#define SINV_OFF 35328
#define FUSED_SMEM_U32 (35328 + 128)
#define FUSED_SMEM_BYTES (FUSED_SMEM_U32 * 4)

// S = Q(128x64) x K(64rows x 64)^T, warp tile 32x16: c_s[2][2][4]
__device__ __forceinline__ void s_compute(const uint32_t* __restrict__ Qs,
                                          const uint32_t* __restrict__ Ksb,
                                          int wr, int wc, int gid, int tig,
                                          float c_s[2][2][4])
{
    #pragma unroll
    for (int mi = 0; mi < 2; mi++)
        #pragma unroll
        for (int ni = 0; ni < 2; ni++)
            #pragma unroll
            for (int r = 0; r < 4; r++) c_s[mi][ni][r] = 0.f;
    #pragma unroll
    for (int kk = 0; kk < 64; kk += 8) {
        uint32_t af[2][4], bf[2][2];
        #pragma unroll
        for (int mi = 0; mi < 2; mi++) {
            int m = wr * 32 + mi * 16 + gid;
            af[mi][0] = Qs[m * 68 + kk + tig];
            af[mi][1] = Qs[(m + 8) * 68 + kk + tig];
            af[mi][2] = Qs[m * 68 + kk + tig + 4];
            af[mi][3] = Qs[(m + 8) * 68 + kk + tig + 4];
        }
        #pragma unroll
        for (int ni = 0; ni < 2; ni++) {
            int n = wc * 16 + ni * 8 + gid;
            bf[ni][0] = Ksb[n * 68 + kk + tig];
            bf[ni][1] = Ksb[n * 68 + kk + tig + 4];
        }
        #pragma unroll
        for (int mi = 0; mi < 2; mi++)
            #pragma unroll
            for (int ni = 0; ni < 2; ni++)
                mma8(c_s[mi][ni], af[mi], bf[ni]);
    }
}

__global__ __launch_bounds__(512, 1)
void fused_attn_kernel(const unsigned char* __restrict__ mask, float* __restrict__ E)
{
    extern __shared__ uint32_t sh[];
    uint32_t* Qs = sh + QS_OFF;
    uint32_t* Es = sh + ES_OFF;
    float* sinv  = (float*)(sh + SINV_OFF);
    float* swsum = (float*)Es;                 // pass1 scratch (4x128)

    const int tid  = threadIdx.x;
    const int wid  = tid >> 5, lane = tid & 31;
    const int gid  = lane >> 2, tig = lane & 3;
    const int wr   = wid >> 2, wc = wid & 3;
    const int iblk = blockIdx.x;
    const int z    = blockIdx.y;
    const int b    = z >> 4, hd = z & 15;
    const int i0   = iblk * 128;

    const float* Qh = g_qp + (size_t)z * HEADELEMS + (size_t)i0 * 64;
    const float* Kh = g_kp + (size_t)z * HEADELEMS;
    const float* Vh = g_vp + (size_t)z * HEADELEMS;
    const unsigned char* mb = mask + (size_t)b * ATTN_PER_HEAD;
    const int* mf = &g_mflag[b * 256 + iblk * 16];
    float* Eh = E + (size_t)z * ATTN_PER_HEAD;

    // ---- load Q tile (128x64) ----
    #pragma unroll
    for (int v = 0; v < 4; v++) {
        int idx = tid + v * 512;               // 2048 float4
        int r = idx >> 4, c4 = (idx & 15) << 2;
        float4 f = *(const float4*)(Qh + (size_t)r * 64 + c4);
        uint32_t* d = &Qs[r * 68 + c4];
        d[0] = f2tf(f.x); d[1] = f2tf(f.y); d[2] = f2tf(f.z); d[3] = f2tf(f.w);
    }
    // ---- load K tile jt=0 into buf 0 ----
    #pragma unroll
    for (int v = 0; v < 2; v++) {
        int idx = tid + v * 512;               // 1024 float4 = 64x16
        int r = idx >> 4, c4 = (idx & 15) << 2;
        float4 f = *(const float4*)(Kh + (size_t)r * 64 + c4);
        uint32_t* d = &sh[KS_OFF + r * 68 + c4];
        d[0] = f2tf(f.x); d[1] = f2tf(f.y); d[2] = f2tf(f.z); d[3] = f2tf(f.w);
    }
    __syncthreads();

    // =======================  PASS 1: rowsums  =======================
    float rs[4] = {0.f, 0.f, 0.f, 0.f};
    int buf = 0;
    for (int ji = 0; ji < 32; ji++) {
        const int jt = ji * 64;
        float4 pk[2];
        if (ji < 31) {
            #pragma unroll
            for (int v = 0; v < 2; v++) {
                int idx = tid + v * 512;
                int r = idx >> 4, c4 = (idx & 15) << 2;
                pk[v] = *(const float4*)(Kh + (size_t)(jt + 64 + r) * 64 + c4);
            }
        }
        float c_s[2][2][4];
        s_compute(Qs, sh + KS_OFF + buf * KS_BUF, wr, wc, gid, tig, c_s);

        const bool use_mask = mf[jt >> 7] != 0;
        #pragma unroll
        for (int mi = 0; mi < 2; mi++)
            #pragma unroll
            for (int h = 0; h < 2; h++) {
                int row = wr * 32 + mi * 16 + h * 8 + gid;
                float acc = 0.f;
                #pragma unroll
                for (int ni = 0; ni < 2; ni++) {
                    int col = wc * 16 + ni * 8 + tig * 2;
                    float s0 = c_s[mi][ni][h * 2 + 0];
                    float s1 = c_s[mi][ni][h * 2 + 1];
                    if (use_mask) {
                        size_t gi = (size_t)(i0 + row) * 2048 + jt + col;
                        if (mb[gi])     s0 = -1e9f;
                        if (mb[gi + 1]) s1 = -1e9f;
                    }
                    acc += __expf(s0 * 0.125f) + __expf(s1 * 0.125f);
                }
                rs[mi * 2 + h] += acc;
            }

        if (ji < 31) {
            uint32_t* d0 = sh + KS_OFF + (buf ^ 1) * KS_BUF;
            #pragma unroll
            for (int v = 0; v < 2; v++) {
                int idx = tid + v * 512;
                int r = idx >> 4, c4 = (idx & 15) << 2;
                uint32_t* d = &d0[r * 68 + c4];
                d[0] = f2tf(pk[v].x); d[1] = f2tf(pk[v].y);
                d[2] = f2tf(pk[v].z); d[3] = f2tf(pk[v].w);
            }
        }
        __syncthreads();
        buf ^= 1;
    }

    // ---- reduce rowsums: tig (shfl) then wc (smem) ----
    #pragma unroll
    for (int p = 0; p < 4; p++) {
        rs[p] += __shfl_xor_sync(0xffffffffu, rs[p], 1);
        rs[p] += __shfl_xor_sync(0xffffffffu, rs[p], 2);
    }
    if (tig == 0) {
        #pragma unroll
        for (int mi = 0; mi < 2; mi++)
            #pragma unroll
            for (int h = 0; h < 2; h++)
                swsum[wc * 128 + wr * 32 + mi * 16 + h * 8 + gid] = rs[mi * 2 + h];
    }
    // preload K/V tile jt=0 into buf 0 for pass 2 (overlap with reduction)
    float4 pk0[2], pv0[2];
    #pragma unroll
    for (int v = 0; v < 2; v++) {
        int idx = tid + v * 512;
        int r = idx >> 4, c4 = (idx & 15) << 2;
        pk0[v] = *(const float4*)(Kh + (size_t)r * 64 + c4);
        pv0[v] = *(const float4*)(Vh + (size_t)r * 64 + c4);
    }
    __syncthreads();
    if (tid < 128)
        sinv[tid] = 1.0f / (swsum[tid] + swsum[128 + tid] + swsum[256 + tid] + swsum[384 + tid]);
    __syncthreads();
    #pragma unroll
    for (int v = 0; v < 2; v++) {
        int idx = tid + v * 512;
        int r = idx >> 4, c4 = (idx & 15) << 2;
        uint32_t* dk = &sh[KS_OFF + r * 68 + c4];
        dk[0] = f2tf(pk0[v].x); dk[1] = f2tf(pk0[v].y); dk[2] = f2tf(pk0[v].z); dk[3] = f2tf(pk0[v].w);
        uint32_t* dv = &sh[VS_OFF + r * 72 + c4];
        dv[0] = f2tf(pv0[v].x); dv[1] = f2tf(pv0[v].y); dv[2] = f2tf(pv0[v].z); dv[3] = f2tf(pv0[v].w);
    }
    __syncthreads();

    // ===================  PASS 2: E write + PV  ===================
    float c_o[2][2][4];
    #pragma unroll
    for (int mi = 0; mi < 2; mi++)
        #pragma unroll
        for (int ni = 0; ni < 2; ni++)
            #pragma unroll
            for (int r = 0; r < 4; r++) c_o[mi][ni][r] = 0.f;

    buf = 0;
    for (int ji = 0; ji < 32; ji++) {
        const int jt = ji * 64;
        float4 pk[2], pv[2];
        if (ji < 31) {
            #pragma unroll
            for (int v = 0; v < 2; v++) {
                int idx = tid + v * 512;
                int r = idx >> 4, c4 = (idx & 15) << 2;
                pk[v] = *(const float4*)(Kh + (size_t)(jt + 64 + r) * 64 + c4);
                pv[v] = *(const float4*)(Vh + (size_t)(jt + 64 + r) * 64 + c4);
            }
        }
        float c_s[2][2][4];
        s_compute(Qs, sh + KS_OFF + buf * KS_BUF, wr, wc, gid, tig, c_s);

        // exp, normalize, write fragments -> Es (prev PV finished before last sync)
        const bool use_mask = mf[jt >> 7] != 0;
        #pragma unroll
        for (int mi = 0; mi < 2; mi++)
            #pragma unroll
            for (int h = 0; h < 2; h++) {
                int row = wr * 32 + mi * 16 + h * 8 + gid;
                float iv = sinv[row];
                #pragma unroll
                for (int ni = 0; ni < 2; ni++) {
                    int col = wc * 16 + ni * 8 + tig * 2;
                    float s0 = c_s[mi][ni][h * 2 + 0];
                    float s1 = c_s[mi][ni][h * 2 + 1];
                    if (use_mask) {
                        size_t gi = (size_t)(i0 + row) * 2048 + jt + col;
                        if (mb[gi])     s0 = -1e9f;
                        if (mb[gi + 1]) s1 = -1e9f;
                    }
                    float e0 = __expf(s0 * 0.125f) * iv;
                    float e1 = __expf(s1 * 0.125f) * iv;
                    uint2 pkd = make_uint2(f2tf(e0), f2tf(e1));
                    // store fp32 for output AND tf32 for PV: keep fp32 in Es,
                    // convert at fragment load?  -> store fp32; PV converts.
                    *(float2*)((float*)&Es[row * 68 + col]) = make_float2(e0, e1);
                    (void)pkd;
                }
            }
        __syncthreads();

        // coalesced E output (normalized), 128x64 tile
        #pragma unroll
        for (int v = 0; v < 4; v++) {
            int idx = tid + v * 512;           // 2048 float4
            int r = idx >> 4, c4 = (idx & 15) << 2;
            float4 val = *(const float4*)((const float*)&Es[r * 68 + c4]);
            *(float4*)(Eh + (size_t)(i0 + r) * 2048 + jt + c4) = val;
        }

        // PV: O += Es(128x64) @ Vs(64x64), warp tile 32x16
        {
            const uint32_t* Vsb = sh + VS_OFF + buf * VS_BUF;
            #pragma unroll
            for (int kk = 0; kk < 64; kk += 8) {
                uint32_t af[2][4], bf[2][2];
                #pragma unroll
                for (int mi = 0; mi < 2; mi++) {
                    int m = wr * 32 + mi * 16 + gid;
                    af[mi][0] = f2tf(((const float*)Es)[m * 68 + kk + tig]);
                    af[mi][1] = f2tf(((const float*)Es)[(m + 8) * 68 + kk + tig]);
                    af[mi][2] = f2tf(((const float*)Es)[m * 68 + kk + tig + 4]);
                    af[mi][3] = f2tf(((const float*)Es)[(m + 8) * 68 + kk + tig + 4]);
                }
                #pragma unroll
                for (int ni = 0; ni < 2; ni++) {
                    int n = wc * 16 + ni * 8 + gid;
                    bf[ni][0] = Vsb[(kk + tig) * 72 + n];
                    bf[ni][1] = Vsb[(kk + tig + 4) * 72 + n];
                }
                #pragma unroll
                for (int mi = 0; mi < 2; mi++)
                    #pragma unroll
                    for (int ni = 0; ni < 2; ni++)
                        mma8(c_o[mi][ni], af[mi], bf[ni]);
            }
        }

        if (ji < 31) {
            uint32_t* dk0 = sh + KS_OFF + (buf ^ 1) * KS_BUF;
            uint32_t* dv0 = sh + VS_OFF + (buf ^ 1) * VS_BUF;
            #pragma unroll
            for (int v = 0; v < 2; v++) {
                int idx = tid + v * 512;
                int r = idx >> 4, c4 = (idx & 15) << 2;
                uint32_t* dk = &dk0[r * 68 + c4];
                dk[0] = f2tf(pk[v].x); dk[1] = f2tf(pk[v].y); dk[2] = f2tf(pk[v].z); dk[3] = f2tf(pk[v].w);
                uint32_t* dv = &dv0[r * 72 + c4];
                dv[0] = f2tf(pv[v].x); dv[1] = f2tf(pv[v].y); dv[2] = f2tf(pv[v].z); dv[3] = f2tf(pv[v].w);
            }
        }
        __syncthreads();
        buf ^= 1;
    }

    // ---- write O (already normalized) into g_x[b, i, hd*64+d] ----
    #pragma unroll
    for (int mi = 0; mi < 2; mi++)
        #pragma unroll
        for (int h = 0; h < 2; h++) {
            int i = i0 + wr * 32 + mi * 16 + h * 8 + gid;
            float* Xr = g_x + (size_t)b * IW + (size_t)i * 1024 + hd * 64;
            #pragma unroll
            for (int ni = 0; ni < 2; ni++) {
                int d = wc * 16 + ni * 8 + tig * 2;
                *(float2*)(Xr + d) = make_float2(c_o[mi][ni][h * 2], c_o[mi][ni][h * 2 + 1]);
            }
        }
}

extern "C" void kernel_launch(void* const* d_in, const int* in_sizes, int n_in,
                              void* d_out, int out_size)
{
    const float* q  = (const float*)d_in[0];
    const float* k  = (const float*)d_in[1];
    const float* v  = (const float*)d_in[2];
    const unsigned char* mask = (const unsigned char*)d_in[3];
    const float* Wq = (const float*)d_in[4];
    const float* Wk = (const float*)d_in[5];
    const float* Wv = (const float*)d_in[6];
    const float* Wo = (const float*)d_in[7];

    float* out  = (float*)d_out;            // [4,2048,1024]
    float* attn = out + 8388608;            // [4,16,2048,2048]

    cudaFuncSetAttribute(fused_attn_kernel,
                         cudaFuncAttributeMaxDynamicSharedMemorySize, FUSED_SMEM_BYTES);

    mask_any_kernel<<<1024, 256>>>(mask);

    dim3 gProj(8, 64, 1);
    proj_kernel<<<gProj, 256>>>(q, Wq, 0);
    proj_kernel<<<gProj, 256>>>(k, Wk, 1);
    proj_kernel<<<gProj, 256>>>(v, Wv, 2);

    fused_attn_kernel<<<dim3(16, 64), 512, FUSED_SMEM_BYTES>>>(mask, attn);

    out_kernel<<<gProj, 256>>>(Wo, out);
}

// round 4
// speedup vs baseline: 1.3145x; 1.0291x over previous
#include <cuda_runtime.h>
#include <cstdint>

// MultiHeadAttention: B=4, I=J=2048, WIDTH=1024, HEADS=16, HEAD_DIM=64
// Outputs: out [4,2048,1024] fp32, attn_weight [4,16,2048,2048] fp32 (normalized)
//
// Pipeline:
//   1. proj_all:   Qp/Kp/Vp = x @ W^T, single launch grid (8,64,3)
//   2. mask_any:   per-(b,128x128) OR-flag (backfills proj tail)
//   3. fused_attn: pass1 rowsums (QK^T+exp, no stores); pass2 recompute,
//                  normalize, coalesced E store (tf32-rounded), O += E@V
//   4. out:        out = g_x @ Wo^T

#define IW 2097152ULL
#define HEADELEMS 131072ULL
#define ATTN_PER_HEAD 4194304ULL

__device__ float g_qp[8388608];
__device__ float g_kp[8388608];
__device__ float g_vp[8388608];
__device__ float g_x [8388608];
__device__ int   g_mflag[1024];   // (b*256 + iblk*16 + jblk128)

__device__ __forceinline__ uint32_t f2tf(float x) {
    uint32_t u;
    asm("cvt.rna.tf32.f32 %0, %1;" : "=r"(u) : "f"(x));
    return u;
}

__device__ __forceinline__ void mma8(float* c, const uint32_t* a, const uint32_t* b) {
    asm("mma.sync.aligned.m16n8k8.row.col.f32.tf32.tf32.f32 "
        "{%0,%1,%2,%3}, {%4,%5,%6,%7}, {%8,%9}, {%0,%1,%2,%3};"
        : "+f"(c[0]), "+f"(c[1]), "+f"(c[2]), "+f"(c[3])
        : "r"(a[0]), "r"(a[1]), "r"(a[2]), "r"(a[3]), "r"(b[0]), "r"(b[1]));
}

// ---------------------------------------------------------------------------
__global__ void mask_any_kernel(const unsigned char* __restrict__ mask)
{
    int bid = blockIdx.x;
    int b = bid >> 8, rem = bid & 255, ib = rem >> 4, jb = rem & 15;
    const unsigned char* base = mask + (size_t)b * ATTN_PER_HEAD
                                     + (size_t)ib * 128 * 2048 + (size_t)jb * 128;
    unsigned acc = 0;
    #pragma unroll
    for (int v = 0; v < 4; v++) {
        int idx = threadIdx.x + v * 256;
        int r = idx >> 3, c = (idx & 7) * 16;
        uint4 m = *(const uint4*)(base + (size_t)r * 2048 + c);
        acc |= m.x | m.y | m.z | m.w;
    }
    int any = __syncthreads_or(acc != 0);
    if (threadIdx.x == 0) g_mflag[bid] = any;
}

// ---------------------------------------------------------------------------
// Generic 128x128-tile TN GEMM, M=8192, N=1024, K=1024.
// ---------------------------------------------------------------------------
__device__ __forceinline__ void gemm1024_body(const float* __restrict__ A,
                                              const float* __restrict__ W,
                                              float* __restrict__ C)
{
    __shared__ uint32_t As[128 * 36];
    __shared__ uint32_t Bs[128 * 36];
    const int tid  = threadIdx.x;
    const int wid  = tid >> 5, lane = tid & 31;
    const int gid  = lane >> 2, tig = lane & 3;
    const int wrow = wid >> 2, wcol = wid & 3;
    const float* Ab = A + (size_t)blockIdx.y * 128 * 1024;
    const float* Bb = W + (size_t)blockIdx.x * 128 * 1024;

    float c[4][4][4];
    #pragma unroll
    for (int mi = 0; mi < 4; mi++)
        #pragma unroll
        for (int ni = 0; ni < 4; ni++)
            #pragma unroll
            for (int r = 0; r < 4; r++) c[mi][ni][r] = 0.f;

    for (int kt = 0; kt < 1024; kt += 32) {
        #pragma unroll
        for (int v = 0; v < 4; v++) {
            int i4 = tid + v * 256;
            int r = i4 >> 3, c4 = (i4 & 7) << 2;
            float4 fa = *(const float4*)(Ab + (size_t)r * 1024 + kt + c4);
            uint32_t* da = &As[r * 36 + c4];
            da[0] = f2tf(fa.x); da[1] = f2tf(fa.y); da[2] = f2tf(fa.z); da[3] = f2tf(fa.w);
            float4 fb = *(const float4*)(Bb + (size_t)r * 1024 + kt + c4);
            uint32_t* db = &Bs[r * 36 + c4];
            db[0] = f2tf(fb.x); db[1] = f2tf(fb.y); db[2] = f2tf(fb.z); db[3] = f2tf(fb.w);
        }
        __syncthreads();
        #pragma unroll
        for (int kk = 0; kk < 32; kk += 8) {
            uint32_t af[4][4], bf[4][2];
            #pragma unroll
            for (int mi = 0; mi < 4; mi++) {
                int m = wrow * 64 + mi * 16 + gid;
                af[mi][0] = As[m * 36 + kk + tig];
                af[mi][1] = As[(m + 8) * 36 + kk + tig];
                af[mi][2] = As[m * 36 + kk + tig + 4];
                af[mi][3] = As[(m + 8) * 36 + kk + tig + 4];
            }
            #pragma unroll
            for (int ni = 0; ni < 4; ni++) {
                int n = wcol * 32 + ni * 8 + gid;
                bf[ni][0] = Bs[n * 36 + kk + tig];
                bf[ni][1] = Bs[n * 36 + kk + tig + 4];
            }
            #pragma unroll
            for (int mi = 0; mi < 4; mi++)
                #pragma unroll
                for (int ni = 0; ni < 4; ni++)
                    mma8(c[mi][ni], af[mi], bf[ni]);
        }
        __syncthreads();
    }

    #pragma unroll
    for (int mi = 0; mi < 4; mi++)
        #pragma unroll
        for (int ni = 0; ni < 4; ni++) {
            int row = blockIdx.y * 128 + wrow * 64 + mi * 16 + gid;
            int col = blockIdx.x * 128 + wcol * 32 + ni * 8 + tig * 2;
            *(float2*)(C + (size_t)row * 1024 + col)       = make_float2(c[mi][ni][0], c[mi][ni][1]);
            *(float2*)(C + (size_t)(row + 8) * 1024 + col) = make_float2(c[mi][ni][2], c[mi][ni][3]);
        }
}

// All three projections in ONE launch: grid (8, 64, 3). Eliminates two
// inter-launch serialization points (each proj is 1.73 waves at occ 2).
__global__ __launch_bounds__(256, 2)
void proj_all_kernel(const float* __restrict__ q, const float* __restrict__ k,
                     const float* __restrict__ v, const float* __restrict__ Wq,
                     const float* __restrict__ Wk, const float* __restrict__ Wv)
{
    const int which = blockIdx.z;
    const float* A = (which == 0) ? q : (which == 1) ? k : v;
    const float* W = (which == 0) ? Wq : (which == 1) ? Wk : Wv;
    float* C = (which == 0) ? g_qp : (which == 1) ? g_kp : g_vp;
    gemm1024_body(A, W, C);
}

__global__ __launch_bounds__(256, 2)
void out_kernel(const float* __restrict__ W, float* __restrict__ C)
{
    gemm1024_body(g_x, W, C);
}

// ---------------------------------------------------------------------------
// Fused attention. Block = 512 threads (16 warps, 4x4), per (iblk, head z).
// j-tile = 64. Dynamic smem (u32 offsets):
//   Qs 128x68 | Ks 2x 64x68 | Vs 2x 64x72 | Es 128x68 (pass1: swsum) | sinv 128
// ---------------------------------------------------------------------------
#define QS_OFF   0
#define KS_OFF   8704
#define KS_BUF   4352
#define VS_OFF   17408
#define VS_BUF   4608
#define ES_OFF   26624
#define SINV_OFF 35328
#define FUSED_SMEM_U32 (35328 + 128)
#define FUSED_SMEM_BYTES (FUSED_SMEM_U32 * 4)

__device__ __forceinline__ void s_compute(const uint32_t* __restrict__ Qs,
                                          const uint32_t* __restrict__ Ksb,
                                          int wr, int wc, int gid, int tig,
                                          float c_s[2][2][4])
{
    #pragma unroll
    for (int mi = 0; mi < 2; mi++)
        #pragma unroll
        for (int ni = 0; ni < 2; ni++)
            #pragma unroll
            for (int r = 0; r < 4; r++) c_s[mi][ni][r] = 0.f;
    #pragma unroll
    for (int kk = 0; kk < 64; kk += 8) {
        uint32_t af[2][4], bf[2][2];
        #pragma unroll
        for (int mi = 0; mi < 2; mi++) {
            int m = wr * 32 + mi * 16 + gid;
            af[mi][0] = Qs[m * 68 + kk + tig];
            af[mi][1] = Qs[(m + 8) * 68 + kk + tig];
            af[mi][2] = Qs[m * 68 + kk + tig + 4];
            af[mi][3] = Qs[(m + 8) * 68 + kk + tig + 4];
        }
        #pragma unroll
        for (int ni = 0; ni < 2; ni++) {
            int n = wc * 16 + ni * 8 + gid;
            bf[ni][0] = Ksb[n * 68 + kk + tig];
            bf[ni][1] = Ksb[n * 68 + kk + tig + 4];
        }
        #pragma unroll
        for (int mi = 0; mi < 2; mi++)
            #pragma unroll
            for (int ni = 0; ni < 2; ni++)
                mma8(c_s[mi][ni], af[mi], bf[ni]);
    }
}

__global__ __launch_bounds__(512, 1)
void fused_attn_kernel(const unsigned char* __restrict__ mask, float* __restrict__ E)
{
    extern __shared__ uint32_t sh[];
    uint32_t* Qs = sh + QS_OFF;
    uint32_t* Es = sh + ES_OFF;
    float* sinv  = (float*)(sh + SINV_OFF);
    float* swsum = (float*)Es;

    const int tid  = threadIdx.x;
    const int wid  = tid >> 5, lane = tid & 31;
    const int gid  = lane >> 2, tig = lane & 3;
    const int wr   = wid >> 2, wc = wid & 3;
    const int iblk = blockIdx.x;
    const int z    = blockIdx.y;
    const int b    = z >> 4, hd = z & 15;
    const int i0   = iblk * 128;

    const float* Qh = g_qp + (size_t)z * HEADELEMS + (size_t)i0 * 64;
    const float* Kh = g_kp + (size_t)z * HEADELEMS;
    const float* Vh = g_vp + (size_t)z * HEADELEMS;
    const unsigned char* mb = mask + (size_t)b * ATTN_PER_HEAD;
    const int* mf = &g_mflag[b * 256 + iblk * 16];
    float* Eh = E + (size_t)z * ATTN_PER_HEAD;

    // ---- load Q tile (128x64) ----
    #pragma unroll
    for (int v = 0; v < 4; v++) {
        int idx = tid + v * 512;
        int r = idx >> 4, c4 = (idx & 15) << 2;
        float4 f = *(const float4*)(Qh + (size_t)r * 64 + c4);
        uint32_t* d = &Qs[r * 68 + c4];
        d[0] = f2tf(f.x); d[1] = f2tf(f.y); d[2] = f2tf(f.z); d[3] = f2tf(f.w);
    }
    #pragma unroll
    for (int v = 0; v < 2; v++) {
        int idx = tid + v * 512;
        int r = idx >> 4, c4 = (idx & 15) << 2;
        float4 f = *(const float4*)(Kh + (size_t)r * 64 + c4);
        uint32_t* d = &sh[KS_OFF + r * 68 + c4];
        d[0] = f2tf(f.x); d[1] = f2tf(f.y); d[2] = f2tf(f.z); d[3] = f2tf(f.w);
    }
    __syncthreads();

    // =======================  PASS 1: rowsums  =======================
    float rs[4] = {0.f, 0.f, 0.f, 0.f};
    int buf = 0;
    for (int ji = 0; ji < 32; ji++) {
        const int jt = ji * 64;
        float4 pk[2];
        if (ji < 31) {
            #pragma unroll
            for (int v = 0; v < 2; v++) {
                int idx = tid + v * 512;
                int r = idx >> 4, c4 = (idx & 15) << 2;
                pk[v] = *(const float4*)(Kh + (size_t)(jt + 64 + r) * 64 + c4);
            }
        }
        float c_s[2][2][4];
        s_compute(Qs, sh + KS_OFF + buf * KS_BUF, wr, wc, gid, tig, c_s);

        const bool use_mask = mf[jt >> 7] != 0;
        #pragma unroll
        for (int mi = 0; mi < 2; mi++)
            #pragma unroll
            for (int h = 0; h < 2; h++) {
                int row = wr * 32 + mi * 16 + h * 8 + gid;
                float acc = 0.f;
                #pragma unroll
                for (int ni = 0; ni < 2; ni++) {
                    int col = wc * 16 + ni * 8 + tig * 2;
                    float s0 = c_s[mi][ni][h * 2 + 0];
                    float s1 = c_s[mi][ni][h * 2 + 1];
                    if (use_mask) {
                        size_t gi = (size_t)(i0 + row) * 2048 + jt + col;
                        if (mb[gi])     s0 = -1e9f;
                        if (mb[gi + 1]) s1 = -1e9f;
                    }
                    acc += __expf(s0 * 0.125f) + __expf(s1 * 0.125f);
                }
                rs[mi * 2 + h] += acc;
            }

        if (ji < 31) {
            uint32_t* d0 = sh + KS_OFF + (buf ^ 1) * KS_BUF;
            #pragma unroll
            for (int v = 0; v < 2; v++) {
                int idx = tid + v * 512;
                int r = idx >> 4, c4 = (idx & 15) << 2;
                uint32_t* d = &d0[r * 68 + c4];
                d[0] = f2tf(pk[v].x); d[1] = f2tf(pk[v].y);
                d[2] = f2tf(pk[v].z); d[3] = f2tf(pk[v].w);
            }
        }
        __syncthreads();
        buf ^= 1;
    }

    // ---- reduce rowsums ----
    #pragma unroll
    for (int p = 0; p < 4; p++) {
        rs[p] += __shfl_xor_sync(0xffffffffu, rs[p], 1);
        rs[p] += __shfl_xor_sync(0xffffffffu, rs[p], 2);
    }
    if (tig == 0) {
        #pragma unroll
        for (int mi = 0; mi < 2; mi++)
            #pragma unroll
            for (int h = 0; h < 2; h++)
                swsum[wc * 128 + wr * 32 + mi * 16 + h * 8 + gid] = rs[mi * 2 + h];
    }
    float4 pk0[2], pv0[2];
    #pragma unroll
    for (int v = 0; v < 2; v++) {
        int idx = tid + v * 512;
        int r = idx >> 4, c4 = (idx & 15) << 2;
        pk0[v] = *(const float4*)(Kh + (size_t)r * 64 + c4);
        pv0[v] = *(const float4*)(Vh + (size_t)r * 64 + c4);
    }
    __syncthreads();
    if (tid < 128)
        sinv[tid] = 1.0f / (swsum[tid] + swsum[128 + tid] + swsum[256 + tid] + swsum[384 + tid]);
    __syncthreads();
    #pragma unroll
    for (int v = 0; v < 2; v++) {
        int idx = tid + v * 512;
        int r = idx >> 4, c4 = (idx & 15) << 2;
        uint32_t* dk = &sh[KS_OFF + r * 68 + c4];
        dk[0] = f2tf(pk0[v].x); dk[1] = f2tf(pk0[v].y); dk[2] = f2tf(pk0[v].z); dk[3] = f2tf(pk0[v].w);
        uint32_t* dv = &sh[VS_OFF + r * 72 + c4];
        dv[0] = f2tf(pv0[v].x); dv[1] = f2tf(pv0[v].y); dv[2] = f2tf(pv0[v].z); dv[3] = f2tf(pv0[v].w);
    }
    __syncthreads();

    // ===================  PASS 2: E write + PV  ===================
    float c_o[2][2][4];
    #pragma unroll
    for (int mi = 0; mi < 2; mi++)
        #pragma unroll
        for (int ni = 0; ni < 2; ni++)
            #pragma unroll
            for (int r = 0; r < 4; r++) c_o[mi][ni][r] = 0.f;

    buf = 0;
    for (int ji = 0; ji < 32; ji++) {
        const int jt = ji * 64;
        float4 pk[2], pv[2];
        if (ji < 31) {
            #pragma unroll
            for (int v = 0; v < 2; v++) {
                int idx = tid + v * 512;
                int r = idx >> 4, c4 = (idx & 15) << 2;
                pk[v] = *(const float4*)(Kh + (size_t)(jt + 64 + r) * 64 + c4);
                pv[v] = *(const float4*)(Vh + (size_t)(jt + 64 + r) * 64 + c4);
            }
        }
        float c_s[2][2][4];
        s_compute(Qs, sh + KS_OFF + buf * KS_BUF, wr, wc, gid, tig, c_s);

        // exp, normalize; store tf32 BITS into Es (valid fp32 values, so the
        // staged STG writes them directly AND PV loads them as ready operands)
        const bool use_mask = mf[jt >> 7] != 0;
        #pragma unroll
        for (int mi = 0; mi < 2; mi++)
            #pragma unroll
            for (int h = 0; h < 2; h++) {
                int row = wr * 32 + mi * 16 + h * 8 + gid;
                float iv = sinv[row];
                #pragma unroll
                for (int ni = 0; ni < 2; ni++) {
                    int col = wc * 16 + ni * 8 + tig * 2;
                    float s0 = c_s[mi][ni][h * 2 + 0];
                    float s1 = c_s[mi][ni][h * 2 + 1];
                    if (use_mask) {
                        size_t gi = (size_t)(i0 + row) * 2048 + jt + col;
                        if (mb[gi])     s0 = -1e9f;
                        if (mb[gi + 1]) s1 = -1e9f;
                    }
                    float e0 = __expf(s0 * 0.125f) * iv;
                    float e1 = __expf(s1 * 0.125f) * iv;
                    *(uint2*)&Es[row * 68 + col] = make_uint2(f2tf(e0), f2tf(e1));
                }
            }
        __syncthreads();

        // coalesced normalized-E output (tf32-rounded fp32), 128x64 tile
        #pragma unroll
        for (int v = 0; v < 4; v++) {
            int idx = tid + v * 512;
            int r = idx >> 4, c4 = (idx & 15) << 2;
            float4 val = *(const float4*)((const float*)&Es[r * 68 + c4]);
            *(float4*)(Eh + (size_t)(i0 + r) * 2048 + jt + c4) = val;
        }

        // PV: O += Es(128x64) @ Vs(64x64); A-fragments are plain u32 LDS now
        {
            const uint32_t* Vsb = sh + VS_OFF + buf * VS_BUF;
            #pragma unroll
            for (int kk = 0; kk < 64; kk += 8) {
                uint32_t af[2][4], bf[2][2];
                #pragma unroll
                for (int mi = 0; mi < 2; mi++) {
                    int m = wr * 32 + mi * 16 + gid;
                    af[mi][0] = Es[m * 68 + kk + tig];
                    af[mi][1] = Es[(m + 8) * 68 + kk + tig];
                    af[mi][2] = Es[m * 68 + kk + tig + 4];
                    af[mi][3] = Es[(m + 8) * 68 + kk + tig + 4];
                }
                #pragma unroll
                for (int ni = 0; ni < 2; ni++) {
                    int n = wc * 16 + ni * 8 + gid;
                    bf[ni][0] = Vsb[(kk + tig) * 72 + n];
                    bf[ni][1] = Vsb[(kk + tig + 4) * 72 + n];
                }
                #pragma unroll
                for (int mi = 0; mi < 2; mi++)
                    #pragma unroll
                    for (int ni = 0; ni < 2; ni++)
                        mma8(c_o[mi][ni], af[mi], bf[ni]);
            }
        }

        if (ji < 31) {
            uint32_t* dk0 = sh + KS_OFF + (buf ^ 1) * KS_BUF;
            uint32_t* dv0 = sh + VS_OFF + (buf ^ 1) * VS_BUF;
            #pragma unroll
            for (int v = 0; v < 2; v++) {
                int idx = tid + v * 512;
                int r = idx >> 4, c4 = (idx & 15) << 2;
                uint32_t* dk = &dk0[r * 68 + c4];
                dk[0] = f2tf(pk[v].x); dk[1] = f2tf(pk[v].y); dk[2] = f2tf(pk[v].z); dk[3] = f2tf(pk[v].w);
                uint32_t* dv = &dv0[r * 72 + c4];
                dv[0] = f2tf(pv[v].x); dv[1] = f2tf(pv[v].y); dv[2] = f2tf(pv[v].z); dv[3] = f2tf(pv[v].w);
            }
        }
        __syncthreads();
        buf ^= 1;
    }

    // ---- write O into g_x[b, i, hd*64+d] ----
    #pragma unroll
    for (int mi = 0; mi < 2; mi++)
        #pragma unroll
        for (int h = 0; h < 2; h++) {
            int i = i0 + wr * 32 + mi * 16 + h * 8 + gid;
            float* Xr = g_x + (size_t)b * IW + (size_t)i * 1024 + hd * 64;
            #pragma unroll
            for (int ni = 0; ni < 2; ni++) {
                int d = wc * 16 + ni * 8 + tig * 2;
                *(float2*)(Xr + d) = make_float2(c_o[mi][ni][h * 2], c_o[mi][ni][h * 2 + 1]);
            }
        }
}

extern "C" void kernel_launch(void* const* d_in, const int* in_sizes, int n_in,
                              void* d_out, int out_size)
{
    const float* q  = (const float*)d_in[0];
    const float* k  = (const float*)d_in[1];
    const float* v  = (const float*)d_in[2];
    const unsigned char* mask = (const unsigned char*)d_in[3];
    const float* Wq = (const float*)d_in[4];
    const float* Wk = (const float*)d_in[5];
    const float* Wv = (const float*)d_in[6];
    const float* Wo = (const float*)d_in[7];

    float* out  = (float*)d_out;            // [4,2048,1024]
    float* attn = out + 8388608;            // [4,16,2048,2048]

    cudaFuncSetAttribute(fused_attn_kernel,
                         cudaFuncAttributeMaxDynamicSharedMemorySize, FUSED_SMEM_BYTES);

    proj_all_kernel<<<dim3(8, 64, 3), 256>>>(q, k, v, Wq, Wk, Wv);
    mask_any_kernel<<<1024, 256>>>(mask);   // backfills proj tail wave

    fused_attn_kernel<<<dim3(16, 64), 512, FUSED_SMEM_BYTES>>>(mask, attn);

    out_kernel<<<dim3(8, 64), 256>>>(Wo, out);
}

// round 5
// speedup vs baseline: 1.3170x; 1.0019x over previous
#include <cuda_runtime.h>
#include <cstdint>

// MultiHeadAttention: B=4, I=J=2048, WIDTH=1024, HEADS=16, HEAD_DIM=64
// Outputs: out [4,2048,1024] fp32, attn_weight [4,16,2048,2048] fp32
//
// Pipeline:
//   0. preround:   tf32-round q/k/v and weights into scratch (cp.async-ready)
//   1. mask_any:   per-(b,128x128) OR-flag
//   2. proj_all:   Qp/Kp/Vp = x @ W^T, cp.async 2-stage pipelined GEMM,
//                  outputs stored tf32-rounded
//   3. fused_attn: pass1 rowsums; pass2 recompute+normalize+E store+PV,
//                  K/V prefetch via cp.async (no cvt), O stored tf32-rounded
//   4. out:        out = g_x @ Wo^T (same pipelined GEMM, raw fp32 epilogue)

#define IW 2097152ULL
#define HEADELEMS 131072ULL
#define ATTN_PER_HEAD 4194304ULL

__device__ float g_qp[8388608];
__device__ float g_kp[8388608];
__device__ float g_vp[8388608];
__device__ float g_x [8388608];
__device__ float g_qr[8388608];
__device__ float g_kr[8388608];
__device__ float g_vr[8388608];
__device__ float g_wq[1048576];
__device__ float g_wk[1048576];
__device__ float g_wv[1048576];
__device__ float g_wo[1048576];
__device__ int   g_mflag[1024];

__device__ __forceinline__ uint32_t f2tf(float x) {
    uint32_t u;
    asm("cvt.rna.tf32.f32 %0, %1;" : "=r"(u) : "f"(x));
    return u;
}
__device__ __forceinline__ float rtf(float x) { return __uint_as_float(f2tf(x)); }

__device__ __forceinline__ void mma8(float* c, const uint32_t* a, const uint32_t* b) {
    asm("mma.sync.aligned.m16n8k8.row.col.f32.tf32.tf32.f32 "
        "{%0,%1,%2,%3}, {%4,%5,%6,%7}, {%8,%9}, {%0,%1,%2,%3};"
        : "+f"(c[0]), "+f"(c[1]), "+f"(c[2]), "+f"(c[3])
        : "r"(a[0]), "r"(a[1]), "r"(a[2]), "r"(a[3]), "r"(b[0]), "r"(b[1]));
}

__device__ __forceinline__ uint32_t s2u(const void* p) {
    return (uint32_t)__cvta_generic_to_shared(p);
}
__device__ __forceinline__ void cpa16(uint32_t dst, const void* src) {
    asm volatile("cp.async.cg.shared.global [%0], [%1], 16;" :: "r"(dst), "l"(src));
}
__device__ __forceinline__ void cpa_commit() { asm volatile("cp.async.commit_group;"); }
__device__ __forceinline__ void cpa_wait0()  { asm volatile("cp.async.wait_group 0;"); }
__device__ __forceinline__ void cpa_wait1()  { asm volatile("cp.async.wait_group 1;"); }

// ---------------------------------------------------------------------------
__global__ void preround_kernel(const float4* __restrict__ q, const float4* __restrict__ k,
                                const float4* __restrict__ v, const float4* __restrict__ wq,
                                const float4* __restrict__ wk, const float4* __restrict__ wv,
                                const float4* __restrict__ wo)
{
    const int stride = gridDim.x * blockDim.x;
    for (int i = blockIdx.x * blockDim.x + threadIdx.x; i < 2097152; i += stride) {
        float4 a = q[i];
        ((float4*)g_qr)[i] = make_float4(rtf(a.x), rtf(a.y), rtf(a.z), rtf(a.w));
        float4 b = k[i];
        ((float4*)g_kr)[i] = make_float4(rtf(b.x), rtf(b.y), rtf(b.z), rtf(b.w));
        float4 c = v[i];
        ((float4*)g_vr)[i] = make_float4(rtf(c.x), rtf(c.y), rtf(c.z), rtf(c.w));
        if (i < 262144) {
            float4 w0 = wq[i];
            ((float4*)g_wq)[i] = make_float4(rtf(w0.x), rtf(w0.y), rtf(w0.z), rtf(w0.w));
            float4 w1 = wk[i];
            ((float4*)g_wk)[i] = make_float4(rtf(w1.x), rtf(w1.y), rtf(w1.z), rtf(w1.w));
            float4 w2 = wv[i];
            ((float4*)g_wv)[i] = make_float4(rtf(w2.x), rtf(w2.y), rtf(w2.z), rtf(w2.w));
            float4 w3 = wo[i];
            ((float4*)g_wo)[i] = make_float4(rtf(w3.x), rtf(w3.y), rtf(w3.z), rtf(w3.w));
        }
    }
}

// ---------------------------------------------------------------------------
__global__ void mask_any_kernel(const unsigned char* __restrict__ mask)
{
    int bid = blockIdx.x;
    int b = bid >> 8, rem = bid & 255, ib = rem >> 4, jb = rem & 15;
    const unsigned char* base = mask + (size_t)b * ATTN_PER_HEAD
                                     + (size_t)ib * 128 * 2048 + (size_t)jb * 128;
    unsigned acc = 0;
    #pragma unroll
    for (int v = 0; v < 4; v++) {
        int idx = threadIdx.x + v * 256;
        int r = idx >> 3, c = (idx & 7) * 16;
        uint4 m = *(const uint4*)(base + (size_t)r * 2048 + c);
        acc |= m.x | m.y | m.z | m.w;
    }
    int any = __syncthreads_or(acc != 0);
    if (threadIdx.x == 0) g_mflag[bid] = any;
}

// ---------------------------------------------------------------------------
// 128x128-tile TN GEMM, M=8192, N=1024, K=1024. cp.async 2-stage pipeline.
// Inputs must be tf32-pre-rounded fp32. Dynamic smem: 2 stages x (A 4608 + B 4608) u32.
// ---------------------------------------------------------------------------
#define GEMM_SMEM_BYTES 73728

__device__ __forceinline__ void gemm1024_body(const float* __restrict__ A,
                                              const float* __restrict__ W,
                                              float* __restrict__ C, bool round_out)
{
    extern __shared__ uint32_t dsm[];
    const int tid  = threadIdx.x;
    const int wid  = tid >> 5, lane = tid & 31;
    const int gid  = lane >> 2, tig = lane & 3;
    const int wrow = wid >> 2, wcol = wid & 3;
    const float* Ab = A + (size_t)blockIdx.y * 128 * 1024;
    const float* Bb = W + (size_t)blockIdx.x * 128 * 1024;
    const uint32_t smb = s2u(dsm);

    float c[4][4][4];
    #pragma unroll
    for (int mi = 0; mi < 4; mi++)
        #pragma unroll
        for (int ni = 0; ni < 4; ni++)
            #pragma unroll
            for (int r = 0; r < 4; r++) c[mi][ni][r] = 0.f;

    // prologue: stage 0 <- kt 0
    #pragma unroll
    for (int v = 0; v < 4; v++) {
        int i = tid + v * 256;
        int r = i >> 3, cu = (i & 7) << 2;
        cpa16(smb + (r * 36 + cu) * 4,        Ab + (size_t)r * 1024 + cu);
        cpa16(smb + (4608 + r * 36 + cu) * 4, Bb + (size_t)r * 1024 + cu);
    }
    cpa_commit();

    for (int kti = 0; kti < 32; kti++) {
        if (kti < 31) {
            const int s = (kti + 1) & 1;
            const int kn = (kti + 1) * 32;
            #pragma unroll
            for (int v = 0; v < 4; v++) {
                int i = tid + v * 256;
                int r = i >> 3, cu = (i & 7) << 2;
                cpa16(smb + (s * 9216 + r * 36 + cu) * 4,        Ab + (size_t)r * 1024 + kn + cu);
                cpa16(smb + (s * 9216 + 4608 + r * 36 + cu) * 4, Bb + (size_t)r * 1024 + kn + cu);
            }
            cpa_commit();
            cpa_wait1();
        } else {
            cpa_wait0();
        }
        __syncthreads();

        const uint32_t* As = dsm + (kti & 1) * 9216;
        const uint32_t* Bs = As + 4608;
        #pragma unroll
        for (int kk = 0; kk < 32; kk += 8) {
            uint32_t af[4][4], bf[4][2];
            #pragma unroll
            for (int mi = 0; mi < 4; mi++) {
                int m = wrow * 64 + mi * 16 + gid;
                af[mi][0] = As[m * 36 + kk + tig];
                af[mi][1] = As[(m + 8) * 36 + kk + tig];
                af[mi][2] = As[m * 36 + kk + tig + 4];
                af[mi][3] = As[(m + 8) * 36 + kk + tig + 4];
            }
            #pragma unroll
            for (int ni = 0; ni < 4; ni++) {
                int n = wcol * 32 + ni * 8 + gid;
                bf[ni][0] = Bs[n * 36 + kk + tig];
                bf[ni][1] = Bs[n * 36 + kk + tig + 4];
            }
            #pragma unroll
            for (int mi = 0; mi < 4; mi++)
                #pragma unroll
                for (int ni = 0; ni < 4; ni++)
                    mma8(c[mi][ni], af[mi], bf[ni]);
        }
        __syncthreads();
    }

    #pragma unroll
    for (int mi = 0; mi < 4; mi++)
        #pragma unroll
        for (int ni = 0; ni < 4; ni++) {
            int row = blockIdx.y * 128 + wrow * 64 + mi * 16 + gid;
            int col = blockIdx.x * 128 + wcol * 32 + ni * 8 + tig * 2;
            if (round_out) {
                *(float2*)(C + (size_t)row * 1024 + col)       = make_float2(rtf(c[mi][ni][0]), rtf(c[mi][ni][1]));
                *(float2*)(C + (size_t)(row + 8) * 1024 + col) = make_float2(rtf(c[mi][ni][2]), rtf(c[mi][ni][3]));
            } else {
                *(float2*)(C + (size_t)row * 1024 + col)       = make_float2(c[mi][ni][0], c[mi][ni][1]);
                *(float2*)(C + (size_t)(row + 8) * 1024 + col) = make_float2(c[mi][ni][2], c[mi][ni][3]);
            }
        }
}

__global__ __launch_bounds__(256, 2)
void proj_all_kernel()
{
    const int which = blockIdx.z;
    const float* A = (which == 0) ? g_qr : (which == 1) ? g_kr : g_vr;
    const float* W = (which == 0) ? g_wq : (which == 1) ? g_wk : g_wv;
    float* C = (which == 0) ? g_qp : (which == 1) ? g_kp : g_vp;
    gemm1024_body(A, W, C, true);
}

__global__ __launch_bounds__(256, 2)
void out_kernel(float* __restrict__ C)
{
    gemm1024_body(g_x, g_wo, C, false);
}

// ---------------------------------------------------------------------------
// Fused attention. 512 threads (16 warps 4x4), per (iblk=128 rows, head z).
// j-tile 64, K/V prefetch via cp.async (operands pre-rounded by proj).
// smem u32: Qs 128x68 | Ks 2x64x68 | Vs 2x64x72 | Es 128x68 | sinv 128
// ---------------------------------------------------------------------------
#define QS_OFF   0
#define KS_OFF   8704
#define KS_BUF   4352
#define VS_OFF   17408
#define VS_BUF   4608
#define ES_OFF   26624
#define SINV_OFF 35328
#define FUSED_SMEM_U32 (35328 + 128)
#define FUSED_SMEM_BYTES (FUSED_SMEM_U32 * 4)

__device__ __forceinline__ void s_compute(const uint32_t* __restrict__ Qs,
                                          const uint32_t* __restrict__ Ksb,
                                          int wr, int wc, int gid, int tig,
                                          float c_s[2][2][4])
{
    #pragma unroll
    for (int mi = 0; mi < 2; mi++)
        #pragma unroll
        for (int ni = 0; ni < 2; ni++)
            #pragma unroll
            for (int r = 0; r < 4; r++) c_s[mi][ni][r] = 0.f;
    #pragma unroll
    for (int kk = 0; kk < 64; kk += 8) {
        uint32_t af[2][4], bf[2][2];
        #pragma unroll
        for (int mi = 0; mi < 2; mi++) {
            int m = wr * 32 + mi * 16 + gid;
            af[mi][0] = Qs[m * 68 + kk + tig];
            af[mi][1] = Qs[(m + 8) * 68 + kk + tig];
            af[mi][2] = Qs[m * 68 + kk + tig + 4];
            af[mi][3] = Qs[(m + 8) * 68 + kk + tig + 4];
        }
        #pragma unroll
        for (int ni = 0; ni < 2; ni++) {
            int n = wc * 16 + ni * 8 + gid;
            bf[ni][0] = Ksb[n * 68 + kk + tig];
            bf[ni][1] = Ksb[n * 68 + kk + tig + 4];
        }
        #pragma unroll
        for (int mi = 0; mi < 2; mi++)
            #pragma unroll
            for (int ni = 0; ni < 2; ni++)
                mma8(c_s[mi][ni], af[mi], bf[ni]);
    }
}

__global__ __launch_bounds__(512, 1)
void fused_attn_kernel(const unsigned char* __restrict__ mask, float* __restrict__ E)
{
    extern __shared__ uint32_t sh[];
    uint32_t* Qs = sh + QS_OFF;
    uint32_t* Es = sh + ES_OFF;
    float* sinv  = (float*)(sh + SINV_OFF);
    float* swsum = (float*)Es;
    const uint32_t smb = s2u(sh);

    const int tid  = threadIdx.x;
    const int wid  = tid >> 5, lane = tid & 31;
    const int gid  = lane >> 2, tig = lane & 3;
    const int wr   = wid >> 2, wc = wid & 3;
    const int iblk = blockIdx.x;
    const int z    = blockIdx.y;
    const int b    = z >> 4, hd = z & 15;
    const int i0   = iblk * 128;

    const float* Qh = g_qp + (size_t)z * HEADELEMS + (size_t)i0 * 64;
    const float* Kh = g_kp + (size_t)z * HEADELEMS;
    const float* Vh = g_vp + (size_t)z * HEADELEMS;
    const unsigned char* mb = mask + (size_t)b * ATTN_PER_HEAD;
    const int* mf = &g_mflag[b * 256 + iblk * 16];
    float* Eh = E + (size_t)z * ATTN_PER_HEAD;

    // ---- initial: Q (128x64) and K tile 0 via cp.async ----
    #pragma unroll
    for (int v = 0; v < 4; v++) {
        int idx = tid + v * 512;
        int r = idx >> 4, cu = (idx & 15) << 2;
        cpa16(smb + (QS_OFF + r * 68 + cu) * 4, Qh + (size_t)r * 64 + cu);
    }
    #pragma unroll
    for (int v = 0; v < 2; v++) {
        int idx = tid + v * 512;
        int r = idx >> 4, cu = (idx & 15) << 2;
        cpa16(smb + (KS_OFF + r * 68 + cu) * 4, Kh + (size_t)r * 64 + cu);
    }
    cpa_commit();
    cpa_wait0();
    __syncthreads();

    // =======================  PASS 1: rowsums  =======================
    float rs[4] = {0.f, 0.f, 0.f, 0.f};
    int buf = 0;
    for (int ji = 0; ji < 32; ji++) {
        const int jt = ji * 64;
        if (ji < 31) {
            #pragma unroll
            for (int v = 0; v < 2; v++) {
                int idx = tid + v * 512;
                int r = idx >> 4, cu = (idx & 15) << 2;
                cpa16(smb + (KS_OFF + (buf ^ 1) * KS_BUF + r * 68 + cu) * 4,
                      Kh + (size_t)(jt + 64 + r) * 64 + cu);
            }
            cpa_commit();
        }
        float c_s[2][2][4];
        s_compute(Qs, sh + KS_OFF + buf * KS_BUF, wr, wc, gid, tig, c_s);

        const bool use_mask = mf[jt >> 7] != 0;
        #pragma unroll
        for (int mi = 0; mi < 2; mi++)
            #pragma unroll
            for (int h = 0; h < 2; h++) {
                int row = wr * 32 + mi * 16 + h * 8 + gid;
                float acc = 0.f;
                #pragma unroll
                for (int ni = 0; ni < 2; ni++) {
                    int col = wc * 16 + ni * 8 + tig * 2;
                    float s0 = c_s[mi][ni][h * 2 + 0];
                    float s1 = c_s[mi][ni][h * 2 + 1];
                    if (use_mask) {
                        size_t gi = (size_t)(i0 + row) * 2048 + jt + col;
                        if (mb[gi])     s0 = -1e9f;
                        if (mb[gi + 1]) s1 = -1e9f;
                    }
                    acc += __expf(s0 * 0.125f) + __expf(s1 * 0.125f);
                }
                rs[mi * 2 + h] += acc;
            }
        if (ji < 31) cpa_wait0();
        __syncthreads();
        buf ^= 1;
    }

    // ---- reduce rowsums; preload K0/V0 for pass 2 ----
    #pragma unroll
    for (int p = 0; p < 4; p++) {
        rs[p] += __shfl_xor_sync(0xffffffffu, rs[p], 1);
        rs[p] += __shfl_xor_sync(0xffffffffu, rs[p], 2);
    }
    if (tig == 0) {
        #pragma unroll
        for (int mi = 0; mi < 2; mi++)
            #pragma unroll
            for (int h = 0; h < 2; h++)
                swsum[wc * 128 + wr * 32 + mi * 16 + h * 8 + gid] = rs[mi * 2 + h];
    }
    #pragma unroll
    for (int v = 0; v < 2; v++) {
        int idx = tid + v * 512;
        int r = idx >> 4, cu = (idx & 15) << 2;
        cpa16(smb + (KS_OFF + r * 68 + cu) * 4, Kh + (size_t)r * 64 + cu);
        cpa16(smb + (VS_OFF + r * 72 + cu) * 4, Vh + (size_t)r * 64 + cu);
    }
    cpa_commit();
    __syncthreads();
    if (tid < 128)
        sinv[tid] = 1.0f / (swsum[tid] + swsum[128 + tid] + swsum[256 + tid] + swsum[384 + tid]);
    cpa_wait0();
    __syncthreads();

    // ===================  PASS 2: E write + PV  ===================
    float c_o[2][2][4];
    #pragma unroll
    for (int mi = 0; mi < 2; mi++)
        #pragma unroll
        for (int ni = 0; ni < 2; ni++)
            #pragma unroll
            for (int r = 0; r < 4; r++) c_o[mi][ni][r] = 0.f;

    buf = 0;
    for (int ji = 0; ji < 32; ji++) {
        const int jt = ji * 64;
        if (ji < 31) {
            #pragma unroll
            for (int v = 0; v < 2; v++) {
                int idx = tid + v * 512;
                int r = idx >> 4, cu = (idx & 15) << 2;
                cpa16(smb + (KS_OFF + (buf ^ 1) * KS_BUF + r * 68 + cu) * 4,
                      Kh + (size_t)(jt + 64 + r) * 64 + cu);
                cpa16(smb + (VS_OFF + (buf ^ 1) * VS_BUF + r * 72 + cu) * 4,
                      Vh + (size_t)(jt + 64 + r) * 64 + cu);
            }
            cpa_commit();
        }
        float c_s[2][2][4];
        s_compute(Qs, sh + KS_OFF + buf * KS_BUF, wr, wc, gid, tig, c_s);

        const bool use_mask = mf[jt >> 7] != 0;
        #pragma unroll
        for (int mi = 0; mi < 2; mi++)
            #pragma unroll
            for (int h = 0; h < 2; h++) {
                int row = wr * 32 + mi * 16 + h * 8 + gid;
                float iv = sinv[row];
                #pragma unroll
                for (int ni = 0; ni < 2; ni++) {
                    int col = wc * 16 + ni * 8 + tig * 2;
                    float s0 = c_s[mi][ni][h * 2 + 0];
                    float s1 = c_s[mi][ni][h * 2 + 1];
                    if (use_mask) {
                        size_t gi = (size_t)(i0 + row) * 2048 + jt + col;
                        if (mb[gi])     s0 = -1e9f;
                        if (mb[gi + 1]) s1 = -1e9f;
                    }
                    float e0 = __expf(s0 * 0.125f) * iv;
                    float e1 = __expf(s1 * 0.125f) * iv;
                    *(uint2*)&Es[row * 68 + col] = make_uint2(f2tf(e0), f2tf(e1));
                }
            }
        __syncthreads();

        // coalesced normalized-E output (tf32-rounded fp32)
        #pragma unroll
        for (int v = 0; v < 4; v++) {
            int idx = tid + v * 512;
            int r = idx >> 4, cu = (idx & 15) << 2;
            float4 val = *(const float4*)((const float*)&Es[r * 68 + cu]);
            *(float4*)(Eh + (size_t)(i0 + r) * 2048 + jt + cu) = val;
        }

        // PV: O += Es(128x64) @ Vs(64x64)
        {
            const uint32_t* Vsb = sh + VS_OFF + buf * VS_BUF;
            #pragma unroll
            for (int kk = 0; kk < 64; kk += 8) {
                uint32_t af[2][4], bf[2][2];
                #pragma unroll
                for (int mi = 0; mi < 2; mi++) {
                    int m = wr * 32 + mi * 16 + gid;
                    af[mi][0] = Es[m * 68 + kk + tig];
                    af[mi][1] = Es[(m + 8) * 68 + kk + tig];
                    af[mi][2] = Es[m * 68 + kk + tig + 4];
                    af[mi][3] = Es[(m + 8) * 68 + kk + tig + 4];
                }
                #pragma unroll
                for (int ni = 0; ni < 2; ni++) {
                    int n = wc * 16 + ni * 8 + gid;
                    bf[ni][0] = Vsb[(kk + tig) * 72 + n];
                    bf[ni][1] = Vsb[(kk + tig + 4) * 72 + n];
                }
                #pragma unroll
                for (int mi = 0; mi < 2; mi++)
                    #pragma unroll
                    for (int ni = 0; ni < 2; ni++)
                        mma8(c_o[mi][ni], af[mi], bf[ni]);
            }
        }

        if (ji < 31) cpa_wait0();
        __syncthreads();
        buf ^= 1;
    }

    // ---- write O (tf32-rounded: feeds cp.async out-GEMM) ----
    #pragma unroll
    for (int mi = 0; mi < 2; mi++)
        #pragma unroll
        for (int h = 0; h < 2; h++) {
            int i = i0 + wr * 32 + mi * 16 + h * 8 + gid;
            float* Xr = g_x + (size_t)b * IW + (size_t)i * 1024 + hd * 64;
            #pragma unroll
            for (int ni = 0; ni < 2; ni++) {
                int d = wc * 16 + ni * 8 + tig * 2;
                *(float2*)(Xr + d) = make_float2(rtf(c_o[mi][ni][h * 2]),
                                                 rtf(c_o[mi][ni][h * 2 + 1]));
            }
        }
}

extern "C" void kernel_launch(void* const* d_in, const int* in_sizes, int n_in,
                              void* d_out, int out_size)
{
    const float* q  = (const float*)d_in[0];
    const float* k  = (const float*)d_in[1];
    const float* v  = (const float*)d_in[2];
    const unsigned char* mask = (const unsigned char*)d_in[3];
    const float* Wq = (const float*)d_in[4];
    const float* Wk = (const float*)d_in[5];
    const float* Wv = (const float*)d_in[6];
    const float* Wo = (const float*)d_in[7];

    float* out  = (float*)d_out;            // [4,2048,1024]
    float* attn = out + 8388608;            // [4,16,2048,2048]

    cudaFuncSetAttribute(fused_attn_kernel,
                         cudaFuncAttributeMaxDynamicSharedMemorySize, FUSED_SMEM_BYTES);
    cudaFuncSetAttribute(proj_all_kernel,
                         cudaFuncAttributeMaxDynamicSharedMemorySize, GEMM_SMEM_BYTES);
    cudaFuncSetAttribute(out_kernel,
                         cudaFuncAttributeMaxDynamicSharedMemorySize, GEMM_SMEM_BYTES);

    preround_kernel<<<2048, 256>>>((const float4*)q, (const float4*)k, (const float4*)v,
                                   (const float4*)Wq, (const float4*)Wk,
                                   (const float4*)Wv, (const float4*)Wo);
    mask_any_kernel<<<1024, 256>>>(mask);

    proj_all_kernel<<<dim3(8, 64, 3), 256, GEMM_SMEM_BYTES>>>();
    fused_attn_kernel<<<dim3(16, 64), 512, FUSED_SMEM_BYTES>>>(mask, attn);
    out_kernel<<<dim3(8, 64), 256, GEMM_SMEM_BYTES>>>(out);
}

// round 8
// speedup vs baseline: 1.4041x; 1.0661x over previous
#include <cuda_runtime.h>
#include <cstdint>

// MultiHeadAttention: B=4, I=J=2048, WIDTH=1024, HEADS=16, HEAD_DIM=64
// Outputs: out [4,2048,1024] fp32, attn_weight [4,16,2048,2048] fp32
//
//   0. preround:   tf32-round q/k/v and weights (cp.async-ready)
//   1. mask_any:   per-(b,128x128) OR-flag
//   2. proj_all:   Qp/Kp/Vp = x @ W^T (cp.async 2-stage GEMM, tf32-rounded out)
//   3. fused_attn: j-tile=128, QK^T warp tile 32x32 (2 LDS/mma);
//                  pass1 rowsums, pass2 recompute+normalize+E store+PV
//   4. out:        out = g_x @ Wo^T

#define IW 2097152ULL
#define HEADELEMS 131072ULL
#define ATTN_PER_HEAD 4194304ULL

__device__ float g_qp[8388608];
__device__ float g_kp[8388608];
__device__ float g_vp[8388608];
__device__ float g_x [8388608];
__device__ float g_qr[8388608];
__device__ float g_kr[8388608];
__device__ float g_vr[8388608];
__device__ float g_wq[1048576];
__device__ float g_wk[1048576];
__device__ float g_wv[1048576];
__device__ float g_wo[1048576];
__device__ int   g_mflag[1024];

__device__ __forceinline__ uint32_t f2tf(float x) {
    uint32_t u;
    asm("cvt.rna.tf32.f32 %0, %1;" : "=r"(u) : "f"(x));
    return u;
}
__device__ __forceinline__ float rtf(float x) { return __uint_as_float(f2tf(x)); }

__device__ __forceinline__ void mma8(float* c, const uint32_t* a, const uint32_t* b) {
    asm("mma.sync.aligned.m16n8k8.row.col.f32.tf32.tf32.f32 "
        "{%0,%1,%2,%3}, {%4,%5,%6,%7}, {%8,%9}, {%0,%1,%2,%3};"
        : "+f"(c[0]), "+f"(c[1]), "+f"(c[2]), "+f"(c[3])
        : "r"(a[0]), "r"(a[1]), "r"(a[2]), "r"(a[3]), "r"(b[0]), "r"(b[1]));
}

__device__ __forceinline__ uint32_t s2u(const void* p) {
    return (uint32_t)__cvta_generic_to_shared(p);
}
__device__ __forceinline__ void cpa16(uint32_t dst, const void* src) {
    asm volatile("cp.async.cg.shared.global [%0], [%1], 16;" :: "r"(dst), "l"(src));
}
__device__ __forceinline__ void cpa_commit() { asm volatile("cp.async.commit_group;"); }
__device__ __forceinline__ void cpa_wait0()  { asm volatile("cp.async.wait_group 0;"); }
__device__ __forceinline__ void cpa_wait1()  { asm volatile("cp.async.wait_group 1;"); }

// ---------------------------------------------------------------------------
__global__ void preround_kernel(const float4* __restrict__ q, const float4* __restrict__ k,
                                const float4* __restrict__ v, const float4* __restrict__ wq,
                                const float4* __restrict__ wk, const float4* __restrict__ wv,
                                const float4* __restrict__ wo)
{
    const int stride = gridDim.x * blockDim.x;
    for (int i = blockIdx.x * blockDim.x + threadIdx.x; i < 2097152; i += stride) {
        float4 a = q[i];
        ((float4*)g_qr)[i] = make_float4(rtf(a.x), rtf(a.y), rtf(a.z), rtf(a.w));
        float4 b = k[i];
        ((float4*)g_kr)[i] = make_float4(rtf(b.x), rtf(b.y), rtf(b.z), rtf(b.w));
        float4 c = v[i];
        ((float4*)g_vr)[i] = make_float4(rtf(c.x), rtf(c.y), rtf(c.z), rtf(c.w));
        if (i < 262144) {
            float4 w0 = wq[i];
            ((float4*)g_wq)[i] = make_float4(rtf(w0.x), rtf(w0.y), rtf(w0.z), rtf(w0.w));
            float4 w1 = wk[i];
            ((float4*)g_wk)[i] = make_float4(rtf(w1.x), rtf(w1.y), rtf(w1.z), rtf(w1.w));
            float4 w2 = wv[i];
            ((float4*)g_wv)[i] = make_float4(rtf(w2.x), rtf(w2.y), rtf(w2.z), rtf(w2.w));
            float4 w3 = wo[i];
            ((float4*)g_wo)[i] = make_float4(rtf(w3.x), rtf(w3.y), rtf(w3.z), rtf(w3.w));
        }
    }
}

// ---------------------------------------------------------------------------
__global__ void mask_any_kernel(const unsigned char* __restrict__ mask)
{
    int bid = blockIdx.x;
    int b = bid >> 8, rem = bid & 255, ib = rem >> 4, jb = rem & 15;
    const unsigned char* base = mask + (size_t)b * ATTN_PER_HEAD
                                     + (size_t)ib * 128 * 2048 + (size_t)jb * 128;
    unsigned acc = 0;
    #pragma unroll
    for (int v = 0; v < 4; v++) {
        int idx = threadIdx.x + v * 256;
        int r = idx >> 3, c = (idx & 7) * 16;
        uint4 m = *(const uint4*)(base + (size_t)r * 2048 + c);
        acc |= m.x | m.y | m.z | m.w;
    }
    int any = __syncthreads_or(acc != 0);
    if (threadIdx.x == 0) g_mflag[bid] = any;
}

// ---------------------------------------------------------------------------
// 128x128-tile TN GEMM, M=8192, N=1024, K=1024. cp.async 2-stage pipeline.
// ---------------------------------------------------------------------------
#define GEMM_SMEM_BYTES 73728

__device__ __forceinline__ void gemm1024_body(const float* __restrict__ A,
                                              const float* __restrict__ W,
                                              float* __restrict__ C, bool round_out)
{
    extern __shared__ uint32_t dsm[];
    const int tid  = threadIdx.x;
    const int wid  = tid >> 5, lane = tid & 31;
    const int gid  = lane >> 2, tig = lane & 3;
    const int wrow = wid >> 2, wcol = wid & 3;
    const float* Ab = A + (size_t)blockIdx.y * 128 * 1024;
    const float* Bb = W + (size_t)blockIdx.x * 128 * 1024;
    const uint32_t smb = s2u(dsm);

    float c[4][4][4];
    #pragma unroll
    for (int mi = 0; mi < 4; mi++)
        #pragma unroll
        for (int ni = 0; ni < 4; ni++)
            #pragma unroll
            for (int r = 0; r < 4; r++) c[mi][ni][r] = 0.f;

    #pragma unroll
    for (int v = 0; v < 4; v++) {
        int i = tid + v * 256;
        int r = i >> 3, cu = (i & 7) << 2;
        cpa16(smb + (r * 36 + cu) * 4,        Ab + (size_t)r * 1024 + cu);
        cpa16(smb + (4608 + r * 36 + cu) * 4, Bb + (size_t)r * 1024 + cu);
    }
    cpa_commit();

    for (int kti = 0; kti < 32; kti++) {
        if (kti < 31) {
            const int s = (kti + 1) & 1;
            const int kn = (kti + 1) * 32;
            #pragma unroll
            for (int v = 0; v < 4; v++) {
                int i = tid + v * 256;
                int r = i >> 3, cu = (i & 7) << 2;
                cpa16(smb + (s * 9216 + r * 36 + cu) * 4,        Ab + (size_t)r * 1024 + kn + cu);
                cpa16(smb + (s * 9216 + 4608 + r * 36 + cu) * 4, Bb + (size_t)r * 1024 + kn + cu);
            }
            cpa_commit();
            cpa_wait1();
        } else {
            cpa_wait0();
        }
        __syncthreads();

        const uint32_t* As = dsm + (kti & 1) * 9216;
        const uint32_t* Bs = As + 4608;
        #pragma unroll
        for (int kk = 0; kk < 32; kk += 8) {
            uint32_t af[4][4], bf[4][2];
            #pragma unroll
            for (int mi = 0; mi < 4; mi++) {
                int m = wrow * 64 + mi * 16 + gid;
                af[mi][0] = As[m * 36 + kk + tig];
                af[mi][1] = As[(m + 8) * 36 + kk + tig];
                af[mi][2] = As[m * 36 + kk + tig + 4];
                af[mi][3] = As[(m + 8) * 36 + kk + tig + 4];
            }
            #pragma unroll
            for (int ni = 0; ni < 4; ni++) {
                int n = wcol * 32 + ni * 8 + gid;
                bf[ni][0] = Bs[n * 36 + kk + tig];
                bf[ni][1] = Bs[n * 36 + kk + tig + 4];
            }
            #pragma unroll
            for (int mi = 0; mi < 4; mi++)
                #pragma unroll
                for (int ni = 0; ni < 4; ni++)
                    mma8(c[mi][ni], af[mi], bf[ni]);
        }
        __syncthreads();
    }

    #pragma unroll
    for (int mi = 0; mi < 4; mi++)
        #pragma unroll
        for (int ni = 0; ni < 4; ni++) {
            int row = blockIdx.y * 128 + wrow * 64 + mi * 16 + gid;
            int col = blockIdx.x * 128 + wcol * 32 + ni * 8 + tig * 2;
            if (round_out) {
                *(float2*)(C + (size_t)row * 1024 + col)       = make_float2(rtf(c[mi][ni][0]), rtf(c[mi][ni][1]));
                *(float2*)(C + (size_t)(row + 8) * 1024 + col) = make_float2(rtf(c[mi][ni][2]), rtf(c[mi][ni][3]));
            } else {
                *(float2*)(C + (size_t)row * 1024 + col)       = make_float2(c[mi][ni][0], c[mi][ni][1]);
                *(float2*)(C + (size_t)(row + 8) * 1024 + col) = make_float2(c[mi][ni][2], c[mi][ni][3]);
            }
        }
}

__global__ __launch_bounds__(256, 2)
void proj_all_kernel()
{
    const int which = blockIdx.z;
    const float* A = (which == 0) ? g_qr : (which == 1) ? g_kr : g_vr;
    const float* W = (which == 0) ? g_wq : (which == 1) ? g_wk : g_wv;
    float* C = (which == 0) ? g_qp : (which == 1) ? g_kp : g_vp;
    gemm1024_body(A, W, C, true);
}

__global__ __launch_bounds__(256, 2)
void out_kernel(float* __restrict__ C)
{
    gemm1024_body(g_x, g_wo, C, false);
}

// ---------------------------------------------------------------------------
// Fused attention v2. 512 threads (16 warps 4x4), per (iblk=128, head z).
// j-tile = 128. QK^T warp tile 32x32 (2 LDS.32/mma). PV warp tile 32x16.
// smem u32: Qs 128x68 | Ks 128x68 | Vs 128x72 (pass1: K buf 2) | Es 128x132 | sinv
// ---------------------------------------------------------------------------
#define QS_OFF   0
#define KS_OFF   8704
#define VS_OFF   17408
#define ES_OFF   26624
#define SINV_OFF 43520
#define FUSED_SMEM_U32 (43520 + 128)
#define FUSED_SMEM_BYTES (FUSED_SMEM_U32 * 4)

// S = Q(128x64) x K(128rows x 64)^T, warp tile 32x32: c_s[2][4][4]
__device__ __forceinline__ void s_compute128(const uint32_t* __restrict__ Qs,
                                             const uint32_t* __restrict__ Ksb,
                                             int wr, int wc, int gid, int tig,
                                             float c_s[2][4][4])
{
    #pragma unroll
    for (int mi = 0; mi < 2; mi++)
        #pragma unroll
        for (int ni = 0; ni < 4; ni++)
            #pragma unroll
            for (int r = 0; r < 4; r++) c_s[mi][ni][r] = 0.f;
    #pragma unroll
    for (int kk = 0; kk < 64; kk += 8) {
        uint32_t af[2][4], bf[4][2];
        #pragma unroll
        for (int mi = 0; mi < 2; mi++) {
            int m = wr * 32 + mi * 16 + gid;
            af[mi][0] = Qs[m * 68 + kk + tig];
            af[mi][1] = Qs[(m + 8) * 68 + kk + tig];
            af[mi][2] = Qs[m * 68 + kk + tig + 4];
            af[mi][3] = Qs[(m + 8) * 68 + kk + tig + 4];
        }
        #pragma unroll
        for (int ni = 0; ni < 4; ni++) {
            int n = wc * 32 + ni * 8 + gid;
            bf[ni][0] = Ksb[n * 68 + kk + tig];
            bf[ni][1] = Ksb[n * 68 + kk + tig + 4];
        }
        #pragma unroll
        for (int mi = 0; mi < 2; mi++)
            #pragma unroll
            for (int ni = 0; ni < 4; ni++)
                mma8(c_s[mi][ni], af[mi], bf[ni]);
    }
}

__global__ __launch_bounds__(512, 1)
void fused_attn_kernel(const unsigned char* __restrict__ mask, float* __restrict__ E)
{
    extern __shared__ uint32_t sh[];
    uint32_t* Qs = sh + QS_OFF;
    uint32_t* Es = sh + ES_OFF;
    float* sinv  = (float*)(sh + SINV_OFF);
    float* swsum = (float*)Es;
    const uint32_t smb = s2u(sh);

    const int tid  = threadIdx.x;
    const int wid  = tid >> 5, lane = tid & 31;
    const int gid  = lane >> 2, tig = lane & 3;
    const int wr   = wid >> 2, wc = wid & 3;
    const int iblk = blockIdx.x;
    const int z    = blockIdx.y;
    const int b    = z >> 4, hd = z & 15;
    const int i0   = iblk * 128;

    const float* Qh = g_qp + (size_t)z * HEADELEMS + (size_t)i0 * 64;
    const float* Kh = g_kp + (size_t)z * HEADELEMS;
    const float* Vh = g_vp + (size_t)z * HEADELEMS;
    const unsigned char* mb = mask + (size_t)b * ATTN_PER_HEAD;
    const int* mf = &g_mflag[b * 256 + iblk * 16];
    float* Eh = E + (size_t)z * ATTN_PER_HEAD;

    // ---- initial: Q (128x64) + K tile 0 -> KS ----
    #pragma unroll
    for (int v = 0; v < 4; v++) {
        int idx = tid + v * 512;
        int r = idx >> 4, cu = (idx & 15) << 2;
        cpa16(smb + (QS_OFF + r * 68 + cu) * 4, Qh + (size_t)r * 64 + cu);
        cpa16(smb + (KS_OFF + r * 68 + cu) * 4, Kh + (size_t)r * 64 + cu);
    }
    cpa_commit();
    cpa_wait0();
    __syncthreads();

    // =======================  PASS 1: rowsums  =======================
    // K double-buffered across KS and VS regions (both stride 68 here).
    float rs[4] = {0.f, 0.f, 0.f, 0.f};
    for (int ji = 0; ji < 16; ji++) {
        const int jt = ji * 128;
        const uint32_t kb = (ji & 1) ? VS_OFF : KS_OFF;
        const uint32_t nb = (ji & 1) ? KS_OFF : VS_OFF;
        if (ji < 15) {
            #pragma unroll
            for (int v = 0; v < 4; v++) {
                int idx = tid + v * 512;
                int r = idx >> 4, cu = (idx & 15) << 2;
                cpa16(smb + (nb + r * 68 + cu) * 4, Kh + (size_t)(jt + 128 + r) * 64 + cu);
            }
            cpa_commit();
        }
        float c_s[2][4][4];
        s_compute128(Qs, sh + kb, wr, wc, gid, tig, c_s);

        const bool use_mask = mf[ji] != 0;
        #pragma unroll
        for (int mi = 0; mi < 2; mi++)
            #pragma unroll
            for (int h = 0; h < 2; h++) {
                int row = wr * 32 + mi * 16 + h * 8 + gid;
                float acc = 0.f;
                #pragma unroll
                for (int ni = 0; ni < 4; ni++) {
                    int col = wc * 32 + ni * 8 + tig * 2;
                    float s0 = c_s[mi][ni][h * 2 + 0];
                    float s1 = c_s[mi][ni][h * 2 + 1];
                    if (use_mask) {
                        size_t gi = (size_t)(i0 + row) * 2048 + jt + col;
                        if (mb[gi])     s0 = -1e9f;
                        if (mb[gi + 1]) s1 = -1e9f;
                    }
                    acc += __expf(s0 * 0.125f) + __expf(s1 * 0.125f);
                }
                rs[mi * 2 + h] += acc;
            }
        if (ji < 15) cpa_wait0();
        __syncthreads();
    }

    // ---- reduce rowsums; preload K0/V0 for pass 2 ----
    #pragma unroll
    for (int p = 0; p < 4; p++) {
        rs[p] += __shfl_xor_sync(0xffffffffu, rs[p], 1);
        rs[p] += __shfl_xor_sync(0xffffffffu, rs[p], 2);
    }
    if (tig == 0) {
        #pragma unroll
        for (int mi = 0; mi < 2; mi++)
            #pragma unroll
            for (int h = 0; h < 2; h++)
                swsum[wc * 128 + wr * 32 + mi * 16 + h * 8 + gid] = rs[mi * 2 + h];
    }
    #pragma unroll
    for (int v = 0; v < 4; v++) {
        int idx = tid + v * 512;
        int r = idx >> 4, cu = (idx & 15) << 2;
        cpa16(smb + (KS_OFF + r * 68 + cu) * 4, Kh + (size_t)r * 64 + cu);
        cpa16(smb + (VS_OFF + r * 72 + cu) * 4, Vh + (size_t)r * 64 + cu);
    }
    cpa_commit();
    __syncthreads();
    if (tid < 128)
        sinv[tid] = 1.0f / (swsum[tid] + swsum[128 + tid] + swsum[256 + tid] + swsum[384 + tid]);
    cpa_wait0();
    __syncthreads();

    // ===================  PASS 2: E write + PV  ===================
    float c_o[2][2][4];
    #pragma unroll
    for (int mi = 0; mi < 2; mi++)
        #pragma unroll
        for (int ni = 0; ni < 2; ni++)
            #pragma unroll
            for (int r = 0; r < 4; r++) c_o[mi][ni][r] = 0.f;

    for (int ji = 0; ji < 16; ji++) {
        const int jt = ji * 128;
        if (ji > 0) {       // K(ji) arrived (V(ji) may still be in flight)
            cpa_wait1();
            __syncthreads();
        }
        float c_s[2][4][4];
        s_compute128(Qs, sh + KS_OFF, wr, wc, gid, tig, c_s);

        cpa_wait0();        // V(ji) resident
        __syncthreads();    // all warps done reading KS -> safe to refill
        if (ji < 15) {
            #pragma unroll
            for (int v = 0; v < 4; v++) {
                int idx = tid + v * 512;
                int r = idx >> 4, cu = (idx & 15) << 2;
                cpa16(smb + (KS_OFF + r * 68 + cu) * 4,
                      Kh + (size_t)(jt + 128 + r) * 64 + cu);
            }
            cpa_commit();
        }

        const bool use_mask = mf[ji] != 0;
        #pragma unroll
        for (int mi = 0; mi < 2; mi++)
            #pragma unroll
            for (int h = 0; h < 2; h++) {
                int row = wr * 32 + mi * 16 + h * 8 + gid;
                float iv = sinv[row];
                #pragma unroll
                for (int ni = 0; ni < 4; ni++) {
                    int col = wc * 32 + ni * 8 + tig * 2;
                    float s0 = c_s[mi][ni][h * 2 + 0];
                    float s1 = c_s[mi][ni][h * 2 + 1];
                    if (use_mask) {
                        size_t gi = (size_t)(i0 + row) * 2048 + jt + col;
                        if (mb[gi])     s0 = -1e9f;
                        if (mb[gi + 1]) s1 = -1e9f;
                    }
                    float e0 = __expf(s0 * 0.125f) * iv;
                    float e1 = __expf(s1 * 0.125f) * iv;
                    *(uint2*)&Es[row * 132 + col] = make_uint2(f2tf(e0), f2tf(e1));
                }
            }
        __syncthreads();    // Es tile complete

        // coalesced normalized-E output, 128x128 tile
        #pragma unroll
        for (int v = 0; v < 8; v++) {
            int idx = tid + v * 512;
            int r = idx >> 5, c4 = (idx & 31) * 4;
            float4 val = *(const float4*)((const float*)&Es[r * 132 + c4]);
            *(float4*)(Eh + (size_t)(i0 + r) * 2048 + jt + c4) = val;
        }

        // PV: O += Es(128x128) @ Vs(128x64), warp tile 32x16
        #pragma unroll
        for (int kk = 0; kk < 128; kk += 8) {
            uint32_t af[2][4], bf[2][2];
            #pragma unroll
            for (int mi = 0; mi < 2; mi++) {
                int m = wr * 32 + mi * 16 + gid;
                af[mi][0] = Es[m * 132 + kk + tig];
                af[mi][1] = Es[(m + 8) * 132 + kk + tig];
                af[mi][2] = Es[m * 132 + kk + tig + 4];
                af[mi][3] = Es[(m + 8) * 132 + kk + tig + 4];
            }
            #pragma unroll
            for (int ni = 0; ni < 2; ni++) {
                int n = wc * 16 + ni * 8 + gid;
                bf[ni][0] = sh[VS_OFF + (kk + tig) * 72 + n];
                bf[ni][1] = sh[VS_OFF + (kk + tig + 4) * 72 + n];
            }
            #pragma unroll
            for (int mi = 0; mi < 2; mi++)
                #pragma unroll
                for (int ni = 0; ni < 2; ni++)
                    mma8(c_o[mi][ni], af[mi], bf[ni]);
        }
        __syncthreads();    // done with Es and Vs
        if (ji < 15) {
            #pragma unroll
            for (int v = 0; v < 4; v++) {
                int idx = tid + v * 512;
                int r = idx >> 4, cu = (idx & 15) << 2;
                cpa16(smb + (VS_OFF + r * 72 + cu) * 4,
                      Vh + (size_t)(jt + 128 + r) * 64 + cu);
            }
            cpa_commit();
        }
    }

    // ---- write O (tf32-rounded: feeds cp.async out-GEMM) ----
    #pragma unroll
    for (int mi = 0; mi < 2; mi++)
        #pragma unroll
        for (int h = 0; h < 2; h++) {
            int i = i0 + wr * 32 + mi * 16 + h * 8 + gid;
            float* Xr = g_x + (size_t)b * IW + (size_t)i * 1024 + hd * 64;
            #pragma unroll
            for (int ni = 0; ni < 2; ni++) {
                int d = wc * 16 + ni * 8 + tig * 2;
                *(float2*)(Xr + d) = make_float2(rtf(c_o[mi][ni][h * 2]),
                                                 rtf(c_o[mi][ni][h * 2 + 1]));
            }
        }
}

extern "C" void kernel_launch(void* const* d_in, const int* in_sizes, int n_in,
                              void* d_out, int out_size)
{
    const float* q  = (const float*)d_in[0];
    const float* k  = (const float*)d_in[1];
    const float* v  = (const float*)d_in[2];
    const unsigned char* mask = (const unsigned char*)d_in[3];
    const float* Wq = (const float*)d_in[4];
    const float* Wk = (const float*)d_in[5];
    const float* Wv = (const float*)d_in[6];
    const float* Wo = (const float*)d_in[7];

    float* out  = (float*)d_out;            // [4,2048,1024]
    float* attn = out + 8388608;            // [4,16,2048,2048]

    cudaFuncSetAttribute(fused_attn_kernel,
                         cudaFuncAttributeMaxDynamicSharedMemorySize, FUSED_SMEM_BYTES);
    cudaFuncSetAttribute(proj_all_kernel,
                         cudaFuncAttributeMaxDynamicSharedMemorySize, GEMM_SMEM_BYTES);
    cudaFuncSetAttribute(out_kernel,
                         cudaFuncAttributeMaxDynamicSharedMemorySize, GEMM_SMEM_BYTES);

    preround_kernel<<<2048, 256>>>((const float4*)q, (const float4*)k, (const float4*)v,
                                   (const float4*)Wq, (const float4*)Wk,
                                   (const float4*)Wv, (const float4*)Wo);
    mask_any_kernel<<<1024, 256>>>(mask);

    proj_all_kernel<<<dim3(8, 64, 3), 256, GEMM_SMEM_BYTES>>>();
    fused_attn_kernel<<<dim3(16, 64), 512, FUSED_SMEM_BYTES>>>(mask, attn);
    out_kernel<<<dim3(8, 64), 256, GEMM_SMEM_BYTES>>>(out);
}

// round 10
// speedup vs baseline: 1.4699x; 1.0469x over previous
#include <cuda_runtime.h>
#include <cuda_bf16.h>
#include <cstdint>

// MultiHeadAttention: B=4, I=J=2048, WIDTH=1024, HEADS=16, HEAD_DIM=64
// Outputs: out [4,2048,1024] fp32, attn_weight [4,16,2048,2048] fp32
//
//   0. preround:   tf32-round q/k/v and weights (cp.async-ready)
//   1. mask_any:   per-(b,128x128) OR-flag
//   2. proj_all:   Qp/Kp/Vp = x @ W^T (cp.async 2-stage GEMM); Q/K also
//                  emitted as packed bf16 copies for pass-1 rowsums
//   3. fused_attn: pass1 rowsums via bf16 m16n8k16 (2x tensor rate, half LDS);
//                  pass2 tf32 recompute+normalize+E store+PV (unchanged)
//   4. out:        out = g_x @ Wo^T

#define IW 2097152ULL
#define HEADELEMS 131072ULL
#define ATTN_PER_HEAD 4194304ULL

__device__ float g_qp[8388608];
__device__ float g_kp[8388608];
__device__ float g_vp[8388608];
__device__ float g_x [8388608];
__device__ float g_qr[8388608];
__device__ float g_kr[8388608];
__device__ float g_vr[8388608];
__device__ float g_wq[1048576];
__device__ float g_wk[1048576];
__device__ float g_wv[1048576];
__device__ float g_wo[1048576];
__device__ __nv_bfloat16 g_qb[8388608];
__device__ __nv_bfloat16 g_kb[8388608];
__device__ int   g_mflag[1024];

__device__ __forceinline__ uint32_t f2tf(float x) {
    uint32_t u;
    asm("cvt.rna.tf32.f32 %0, %1;" : "=r"(u) : "f"(x));
    return u;
}
__device__ __forceinline__ float rtf(float x) { return __uint_as_float(f2tf(x)); }

__device__ __forceinline__ void mma8(float* c, const uint32_t* a, const uint32_t* b) {
    asm("mma.sync.aligned.m16n8k8.row.col.f32.tf32.tf32.f32 "
        "{%0,%1,%2,%3}, {%4,%5,%6,%7}, {%8,%9}, {%0,%1,%2,%3};"
        : "+f"(c[0]), "+f"(c[1]), "+f"(c[2]), "+f"(c[3])
        : "r"(a[0]), "r"(a[1]), "r"(a[2]), "r"(a[3]), "r"(b[0]), "r"(b[1]));
}
__device__ __forceinline__ void mma16bf(float* c, const uint32_t* a, const uint32_t* b) {
    asm("mma.sync.aligned.m16n8k16.row.col.f32.bf16.bf16.f32 "
        "{%0,%1,%2,%3}, {%4,%5,%6,%7}, {%8,%9}, {%0,%1,%2,%3};"
        : "+f"(c[0]), "+f"(c[1]), "+f"(c[2]), "+f"(c[3])
        : "r"(a[0]), "r"(a[1]), "r"(a[2]), "r"(a[3]), "r"(b[0]), "r"(b[1]));
}

__device__ __forceinline__ uint32_t s2u(const void* p) {
    return (uint32_t)__cvta_generic_to_shared(p);
}
__device__ __forceinline__ void cpa16(uint32_t dst, const void* src) {
    asm volatile("cp.async.cg.shared.global [%0], [%1], 16;" :: "r"(dst), "l"(src));
}
__device__ __forceinline__ void cpa_commit() { asm volatile("cp.async.commit_group;"); }
__device__ __forceinline__ void cpa_wait0()  { asm volatile("cp.async.wait_group 0;"); }
__device__ __forceinline__ void cpa_wait1()  { asm volatile("cp.async.wait_group 1;"); }

// ---------------------------------------------------------------------------
__global__ void preround_kernel(const float4* __restrict__ q, const float4* __restrict__ k,
                                const float4* __restrict__ v, const float4* __restrict__ wq,
                                const float4* __restrict__ wk, const float4* __restrict__ wv,
                                const float4* __restrict__ wo)
{
    const int stride = gridDim.x * blockDim.x;
    for (int i = blockIdx.x * blockDim.x + threadIdx.x; i < 2097152; i += stride) {
        float4 a = q[i];
        ((float4*)g_qr)[i] = make_float4(rtf(a.x), rtf(a.y), rtf(a.z), rtf(a.w));
        float4 b = k[i];
        ((float4*)g_kr)[i] = make_float4(rtf(b.x), rtf(b.y), rtf(b.z), rtf(b.w));
        float4 c = v[i];
        ((float4*)g_vr)[i] = make_float4(rtf(c.x), rtf(c.y), rtf(c.z), rtf(c.w));
        if (i < 262144) {
            float4 w0 = wq[i];
            ((float4*)g_wq)[i] = make_float4(rtf(w0.x), rtf(w0.y), rtf(w0.z), rtf(w0.w));
            float4 w1 = wk[i];
            ((float4*)g_wk)[i] = make_float4(rtf(w1.x), rtf(w1.y), rtf(w1.z), rtf(w1.w));
            float4 w2 = wv[i];
            ((float4*)g_wv)[i] = make_float4(rtf(w2.x), rtf(w2.y), rtf(w2.z), rtf(w2.w));
            float4 w3 = wo[i];
            ((float4*)g_wo)[i] = make_float4(rtf(w3.x), rtf(w3.y), rtf(w3.z), rtf(w3.w));
        }
    }
}

// ---------------------------------------------------------------------------
__global__ void mask_any_kernel(const unsigned char* __restrict__ mask)
{
    int bid = blockIdx.x;
    int b = bid >> 8, rem = bid & 255, ib = rem >> 4, jb = rem & 15;
    const unsigned char* base = mask + (size_t)b * ATTN_PER_HEAD
                                     + (size_t)ib * 128 * 2048 + (size_t)jb * 128;
    unsigned acc = 0;
    #pragma unroll
    for (int v = 0; v < 4; v++) {
        int idx = threadIdx.x + v * 256;
        int r = idx >> 3, c = (idx & 7) * 16;
        uint4 m = *(const uint4*)(base + (size_t)r * 2048 + c);
        acc |= m.x | m.y | m.z | m.w;
    }
    int any = __syncthreads_or(acc != 0);
    if (threadIdx.x == 0) g_mflag[bid] = any;
}

// ---------------------------------------------------------------------------
// 128x128-tile TN GEMM, M=8192, N=1024, K=1024. cp.async 2-stage pipeline.
// Optional packed-bf16 secondary output (for pass-1 rowsum operands).
// ---------------------------------------------------------------------------
#define GEMM_SMEM_BYTES 73728

__device__ __forceinline__ void gemm1024_body(const float* __restrict__ A,
                                              const float* __restrict__ W,
                                              float* __restrict__ C, bool round_out,
                                              __nv_bfloat16* __restrict__ Cb)
{
    extern __shared__ uint32_t dsm[];
    const int tid  = threadIdx.x;
    const int wid  = tid >> 5, lane = tid & 31;
    const int gid  = lane >> 2, tig = lane & 3;
    const int wrow = wid >> 2, wcol = wid & 3;
    const float* Ab = A + (size_t)blockIdx.y * 128 * 1024;
    const float* Bb = W + (size_t)blockIdx.x * 128 * 1024;
    const uint32_t smb = s2u(dsm);

    float c[4][4][4];
    #pragma unroll
    for (int mi = 0; mi < 4; mi++)
        #pragma unroll
        for (int ni = 0; ni < 4; ni++)
            #pragma unroll
            for (int r = 0; r < 4; r++) c[mi][ni][r] = 0.f;

    #pragma unroll
    for (int v = 0; v < 4; v++) {
        int i = tid + v * 256;
        int r = i >> 3, cu = (i & 7) << 2;
        cpa16(smb + (r * 36 + cu) * 4,        Ab + (size_t)r * 1024 + cu);
        cpa16(smb + (4608 + r * 36 + cu) * 4, Bb + (size_t)r * 1024 + cu);
    }
    cpa_commit();

    for (int kti = 0; kti < 32; kti++) {
        if (kti < 31) {
            const int s = (kti + 1) & 1;
            const int kn = (kti + 1) * 32;
            #pragma unroll
            for (int v = 0; v < 4; v++) {
                int i = tid + v * 256;
                int r = i >> 3, cu = (i & 7) << 2;
                cpa16(smb + (s * 9216 + r * 36 + cu) * 4,        Ab + (size_t)r * 1024 + kn + cu);
                cpa16(smb + (s * 9216 + 4608 + r * 36 + cu) * 4, Bb + (size_t)r * 1024 + kn + cu);
            }
            cpa_commit();
            cpa_wait1();
        } else {
            cpa_wait0();
        }
        __syncthreads();

        const uint32_t* As = dsm + (kti & 1) * 9216;
        const uint32_t* Bs = As + 4608;
        #pragma unroll
        for (int kk = 0; kk < 32; kk += 8) {
            uint32_t af[4][4], bf[4][2];
            #pragma unroll
            for (int mi = 0; mi < 4; mi++) {
                int m = wrow * 64 + mi * 16 + gid;
                af[mi][0] = As[m * 36 + kk + tig];
                af[mi][1] = As[(m + 8) * 36 + kk + tig];
                af[mi][2] = As[m * 36 + kk + tig + 4];
                af[mi][3] = As[(m + 8) * 36 + kk + tig + 4];
            }
            #pragma unroll
            for (int ni = 0; ni < 4; ni++) {
                int n = wcol * 32 + ni * 8 + gid;
                bf[ni][0] = Bs[n * 36 + kk + tig];
                bf[ni][1] = Bs[n * 36 + kk + tig + 4];
            }
            #pragma unroll
            for (int mi = 0; mi < 4; mi++)
                #pragma unroll
                for (int ni = 0; ni < 4; ni++)
                    mma8(c[mi][ni], af[mi], bf[ni]);
        }
        __syncthreads();
    }

    #pragma unroll
    for (int mi = 0; mi < 4; mi++)
        #pragma unroll
        for (int ni = 0; ni < 4; ni++) {
            int row = blockIdx.y * 128 + wrow * 64 + mi * 16 + gid;
            int col = blockIdx.x * 128 + wcol * 32 + ni * 8 + tig * 2;
            if (round_out) {
                *(float2*)(C + (size_t)row * 1024 + col)       = make_float2(rtf(c[mi][ni][0]), rtf(c[mi][ni][1]));
                *(float2*)(C + (size_t)(row + 8) * 1024 + col) = make_float2(rtf(c[mi][ni][2]), rtf(c[mi][ni][3]));
            } else {
                *(float2*)(C + (size_t)row * 1024 + col)       = make_float2(c[mi][ni][0], c[mi][ni][1]);
                *(float2*)(C + (size_t)(row + 8) * 1024 + col) = make_float2(c[mi][ni][2], c[mi][ni][3]);
            }
            if (Cb) {
                *(__nv_bfloat162*)(Cb + (size_t)row * 1024 + col) =
                    __float22bfloat162_rn(make_float2(c[mi][ni][0], c[mi][ni][1]));
                *(__nv_bfloat162*)(Cb + (size_t)(row + 8) * 1024 + col) =
                    __float22bfloat162_rn(make_float2(c[mi][ni][2], c[mi][ni][3]));
            }
        }
}

__global__ __launch_bounds__(256, 2)
void proj_all_kernel()
{
    const int which = blockIdx.z;
    const float* A = (which == 0) ? g_qr : (which == 1) ? g_kr : g_vr;
    const float* W = (which == 0) ? g_wq : (which == 1) ? g_wk : g_wv;
    float* C = (which == 0) ? g_qp : (which == 1) ? g_kp : g_vp;
    __nv_bfloat16* Cb = (which == 0) ? g_qb : (which == 1) ? g_kb : (__nv_bfloat16*)0;
    gemm1024_body(A, W, C, true, Cb);
}

__global__ __launch_bounds__(256, 2)
void out_kernel(float* __restrict__ C)
{
    gemm1024_body(g_x, g_wo, C, false, (__nv_bfloat16*)0);
}

// ---------------------------------------------------------------------------
// Fused attention v3. 512 threads (16 warps 4x4), per (iblk=128, head z).
// j-tile 128. Pass1: bf16 m16n8k16 QK^T (rowsums only). Pass2: tf32 (E + PV).
// smem u32: Qs 128x68 | Ks 128x68 | Vs 128x72 | Es 128x132 | sinv 128
// Pass1 aliases Es region: Qb 128x36 | Kb0 128x36 | Kb1 128x36 (bf16 packed)
// ---------------------------------------------------------------------------
#define QS_OFF   0
#define KS_OFF   8704
#define VS_OFF   17408
#define ES_OFF   26624
#define SINV_OFF 43520
#define QB_OFF   (ES_OFF)
#define KB0_OFF  (ES_OFF + 4608)
#define KB1_OFF  (ES_OFF + 9216)
#define FUSED_SMEM_U32 (43520 + 128)
#define FUSED_SMEM_BYTES (FUSED_SMEM_U32 * 4)

// tf32: S = Q(128x64) x K(128x64)^T, warp tile 32x32
__device__ __forceinline__ void s_compute128(const uint32_t* __restrict__ Qs,
                                             const uint32_t* __restrict__ Ksb,
                                             int wr, int wc, int gid, int tig,
                                             float c_s[2][4][4])
{
    #pragma unroll
    for (int mi = 0; mi < 2; mi++)
        #pragma unroll
        for (int ni = 0; ni < 4; ni++)
            #pragma unroll
            for (int r = 0; r < 4; r++) c_s[mi][ni][r] = 0.f;
    #pragma unroll
    for (int kk = 0; kk < 64; kk += 8) {
        uint32_t af[2][4], bf[4][2];
        #pragma unroll
        for (int mi = 0; mi < 2; mi++) {
            int m = wr * 32 + mi * 16 + gid;
            af[mi][0] = Qs[m * 68 + kk + tig];
            af[mi][1] = Qs[(m + 8) * 68 + kk + tig];
            af[mi][2] = Qs[m * 68 + kk + tig + 4];
            af[mi][3] = Qs[(m + 8) * 68 + kk + tig + 4];
        }
        #pragma unroll
        for (int ni = 0; ni < 4; ni++) {
            int n = wc * 32 + ni * 8 + gid;
            bf[ni][0] = Ksb[n * 68 + kk + tig];
            bf[ni][1] = Ksb[n * 68 + kk + tig + 4];
        }
        #pragma unroll
        for (int mi = 0; mi < 2; mi++)
            #pragma unroll
            for (int ni = 0; ni < 4; ni++)
                mma8(c_s[mi][ni], af[mi], bf[ni]);
    }
}

// bf16: same tile via m16n8k16; operands packed 2-per-u32, stride 36 u32.
__device__ __forceinline__ void s_compute128_bf16(const uint32_t* __restrict__ Qb,
                                                  const uint32_t* __restrict__ Kb,
                                                  int wr, int wc, int gid, int tig,
                                                  float c_s[2][4][4])
{
    #pragma unroll
    for (int mi = 0; mi < 2; mi++)
        #pragma unroll
        for (int ni = 0; ni < 4; ni++)
            #pragma unroll
            for (int r = 0; r < 4; r++) c_s[mi][ni][r] = 0.f;
    #pragma unroll
    for (int kk = 0; kk < 32; kk += 8) {       // u32 units: 4 steps of k=16
        uint32_t af[2][4], bf[4][2];
        #pragma unroll
        for (int mi = 0; mi < 2; mi++) {
            int m = wr * 32 + mi * 16 + gid;
            af[mi][0] = Qb[m * 36 + kk + tig];
            af[mi][1] = Qb[(m + 8) * 36 + kk + tig];
            af[mi][2] = Qb[m * 36 + kk + tig + 4];
            af[mi][3] = Qb[(m + 8) * 36 + kk + tig + 4];
        }
        #pragma unroll
        for (int ni = 0; ni < 4; ni++) {
            int n = wc * 32 + ni * 8 + gid;
            bf[ni][0] = Kb[n * 36 + kk + tig];
            bf[ni][1] = Kb[n * 36 + kk + tig + 4];
        }
        #pragma unroll
        for (int mi = 0; mi < 2; mi++)
            #pragma unroll
            for (int ni = 0; ni < 4; ni++)
                mma16bf(c_s[mi][ni], af[mi], bf[ni]);
    }
}

__global__ __launch_bounds__(512, 1)
void fused_attn_kernel(const unsigned char* __restrict__ mask, float* __restrict__ E)
{
    extern __shared__ uint32_t sh[];
    uint32_t* Qs = sh + QS_OFF;
    uint32_t* Es = sh + ES_OFF;
    float* sinv  = (float*)(sh + SINV_OFF);
    float* swsum = (float*)(sh + ES_OFF);      // reused after pass-1 K reads
    const uint32_t smb = s2u(sh);

    const int tid  = threadIdx.x;
    const int wid  = tid >> 5, lane = tid & 31;
    const int gid  = lane >> 2, tig = lane & 3;
    const int wr   = wid >> 2, wc = wid & 3;
    const int iblk = blockIdx.x;
    const int z    = blockIdx.y;
    const int b    = z >> 4, hd = z & 15;
    const int i0   = iblk * 128;

    const float* Qh = g_qp + (size_t)z * HEADELEMS + (size_t)i0 * 64;
    const float* Kh = g_kp + (size_t)z * HEADELEMS;
    const float* Vh = g_vp + (size_t)z * HEADELEMS;
    const __nv_bfloat16* Qbh = g_qb + (size_t)z * HEADELEMS + (size_t)i0 * 64;
    const __nv_bfloat16* Kbh = g_kb + (size_t)z * HEADELEMS;
    const unsigned char* mb = mask + (size_t)b * ATTN_PER_HEAD;
    const int* mf = &g_mflag[b * 256 + iblk * 16];
    float* Eh = E + (size_t)z * ATTN_PER_HEAD;

    // ---- initial: Qb (128x64 bf16) + Kb tile 0 ----
    #pragma unroll
    for (int v = 0; v < 2; v++) {
        int idx = tid + v * 512;               // 1024 chunks of 16B (8 bf16)
        int r = idx >> 3, ch = idx & 7;
        cpa16(smb + (QB_OFF + r * 36 + ch * 4) * 4, Qbh + (size_t)r * 64 + ch * 8);
        cpa16(smb + (KB0_OFF + r * 36 + ch * 4) * 4, Kbh + (size_t)r * 64 + ch * 8);
    }
    cpa_commit();
    cpa_wait0();
    __syncthreads();

    // =================  PASS 1: rowsums (bf16 QK^T)  =================
    float rs[4] = {0.f, 0.f, 0.f, 0.f};
    for (int ji = 0; ji < 16; ji++) {
        const int jt = ji * 128;
        const uint32_t kb = (ji & 1) ? KB1_OFF : KB0_OFF;
        const uint32_t nb = (ji & 1) ? KB0_OFF : KB1_OFF;
        if (ji < 15) {
            #pragma unroll
            for (int v = 0; v < 2; v++) {
                int idx = tid + v * 512;
                int r = idx >> 3, ch = idx & 7;
                cpa16(smb + (nb + r * 36 + ch * 4) * 4,
                      Kbh + (size_t)(jt + 128 + r) * 64 + ch * 8);
            }
            cpa_commit();
        }
        float c_s[2][4][4];
        s_compute128_bf16(sh + QB_OFF, sh + kb, wr, wc, gid, tig, c_s);

        const bool use_mask = mf[ji] != 0;
        #pragma unroll
        for (int mi = 0; mi < 2; mi++)
            #pragma unroll
            for (int h = 0; h < 2; h++) {
                int row = wr * 32 + mi * 16 + h * 8 + gid;
                float acc = 0.f;
                #pragma unroll
                for (int ni = 0; ni < 4; ni++) {
                    int col = wc * 32 + ni * 8 + tig * 2;
                    float s0 = c_s[mi][ni][h * 2 + 0];
                    float s1 = c_s[mi][ni][h * 2 + 1];
                    if (use_mask) {
                        size_t gi = (size_t)(i0 + row) * 2048 + jt + col;
                        if (mb[gi])     s0 = -1e9f;
                        if (mb[gi + 1]) s1 = -1e9f;
                    }
                    acc += __expf(s0 * 0.125f) + __expf(s1 * 0.125f);
                }
                rs[mi * 2 + h] += acc;
            }
        if (ji < 15) cpa_wait0();
        __syncthreads();
    }

    // ---- reduce rowsums; kick off pass-2 tf32 loads (Qs, K0, V0) ----
    #pragma unroll
    for (int p = 0; p < 4; p++) {
        rs[p] += __shfl_xor_sync(0xffffffffu, rs[p], 1);
        rs[p] += __shfl_xor_sync(0xffffffffu, rs[p], 2);
    }
    #pragma unroll
    for (int v = 0; v < 4; v++) {
        int idx = tid + v * 512;
        int r = idx >> 4, cu = (idx & 15) << 2;
        cpa16(smb + (QS_OFF + r * 68 + cu) * 4, Qh + (size_t)r * 64 + cu);
        cpa16(smb + (KS_OFF + r * 68 + cu) * 4, Kh + (size_t)r * 64 + cu);
        cpa16(smb + (VS_OFF + r * 72 + cu) * 4, Vh + (size_t)r * 64 + cu);
    }
    cpa_commit();
    if (tig == 0) {
        #pragma unroll
        for (int mi = 0; mi < 2; mi++)
            #pragma unroll
            for (int h = 0; h < 2; h++)
                swsum[wc * 128 + wr * 32 + mi * 16 + h * 8 + gid] = rs[mi * 2 + h];
    }
    __syncthreads();
    if (tid < 128)
        sinv[tid] = 1.0f / (swsum[tid] + swsum[128 + tid] + swsum[256 + tid] + swsum[384 + tid]);
    cpa_wait0();
    __syncthreads();

    // ===================  PASS 2: E write + PV (tf32)  ===================
    float c_o[2][2][4];
    #pragma unroll
    for (int mi = 0; mi < 2; mi++)
        #pragma unroll
        for (int ni = 0; ni < 2; ni++)
            #pragma unroll
            for (int r = 0; r < 4; r++) c_o[mi][ni][r] = 0.f;

    for (int ji = 0; ji < 16; ji++) {
        const int jt = ji * 128;
        if (ji > 0) {       // K(ji) arrived (V(ji) may still be in flight)
            cpa_wait1();
            __syncthreads();
        }
        float c_s[2][4][4];
        s_compute128(Qs, sh + KS_OFF, wr, wc, gid, tig, c_s);

        cpa_wait0();        // V(ji) resident
        __syncthreads();    // all warps done reading KS -> safe to refill
        if (ji < 15) {
            #pragma unroll
            for (int v = 0; v < 4; v++) {
                int idx = tid + v * 512;
                int r = idx >> 4, cu = (idx & 15) << 2;
                cpa16(smb + (KS_OFF + r * 68 + cu) * 4,
                      Kh + (size_t)(jt + 128 + r) * 64 + cu);
            }
            cpa_commit();
        }

        const bool use_mask = mf[ji] != 0;
        #pragma unroll
        for (int mi = 0; mi < 2; mi++)
            #pragma unroll
            for (int h = 0; h < 2; h++) {
                int row = wr * 32 + mi * 16 + h * 8 + gid;
                float iv = sinv[row];
                #pragma unroll
                for (int ni = 0; ni < 4; ni++) {
                    int col = wc * 32 + ni * 8 + tig * 2;
                    float s0 = c_s[mi][ni][h * 2 + 0];
                    float s1 = c_s[mi][ni][h * 2 + 1];
                    if (use_mask) {
                        size_t gi = (size_t)(i0 + row) * 2048 + jt + col;
                        if (mb[gi])     s0 = -1e9f;
                        if (mb[gi + 1]) s1 = -1e9f;
                    }
                    float e0 = __expf(s0 * 0.125f) * iv;
                    float e1 = __expf(s1 * 0.125f) * iv;
                    *(uint2*)&Es[row * 132 + col] = make_uint2(f2tf(e0), f2tf(e1));
                }
            }
        __syncthreads();    // Es tile complete

        // coalesced normalized-E output, 128x128 tile
        #pragma unroll
        for (int v = 0; v < 8; v++) {
            int idx = tid + v * 512;
            int r = idx >> 5, c4 = (idx & 31) * 4;
            float4 val = *(const float4*)((const float*)&Es[r * 132 + c4]);
            *(float4*)(Eh + (size_t)(i0 + r) * 2048 + jt + c4) = val;
        }

        // PV: O += Es(128x128) @ Vs(128x64), warp tile 32x16
        #pragma unroll
        for (int kk = 0; kk < 128; kk += 8) {
            uint32_t af[2][4], bf[2][2];
            #pragma unroll
            for (int mi = 0; mi < 2; mi++) {
                int m = wr * 32 + mi * 16 + gid;
                af[mi][0] = Es[m * 132 + kk + tig];
                af[mi][1] = Es[(m + 8) * 132 + kk + tig];
                af[mi][2] = Es[m * 132 + kk + tig + 4];
                af[mi][3] = Es[(m + 8) * 132 + kk + tig + 4];
            }
            #pragma unroll
            for (int ni = 0; ni < 2; ni++) {
                int n = wc * 16 + ni * 8 + gid;
                bf[ni][0] = sh[VS_OFF + (kk + tig) * 72 + n];
                bf[ni][1] = sh[VS_OFF + (kk + tig + 4) * 72 + n];
            }
            #pragma unroll
            for (int mi = 0; mi < 2; mi++)
                #pragma unroll
                for (int ni = 0; ni < 2; ni++)
                    mma8(c_o[mi][ni], af[mi], bf[ni]);
        }
        __syncthreads();    // done with Es and Vs
        if (ji < 15) {
            #pragma unroll
            for (int v = 0; v < 4; v++) {
                int idx = tid + v * 512;
                int r = idx >> 4, cu = (idx & 15) << 2;
                cpa16(smb + (VS_OFF + r * 72 + cu) * 4,
                      Vh + (size_t)(jt + 128 + r) * 64 + cu);
            }
            cpa_commit();
        }
    }

    // ---- write O (tf32-rounded: feeds cp.async out-GEMM) ----
    #pragma unroll
    for (int mi = 0; mi < 2; mi++)
        #pragma unroll
        for (int h = 0; h < 2; h++) {
            int i = i0 + wr * 32 + mi * 16 + h * 8 + gid;
            float* Xr = g_x + (size_t)b * IW + (size_t)i * 1024 + hd * 64;
            #pragma unroll
            for (int ni = 0; ni < 2; ni++) {
                int d = wc * 16 + ni * 8 + tig * 2;
                *(float2*)(Xr + d) = make_float2(rtf(c_o[mi][ni][h * 2]),
                                                 rtf(c_o[mi][ni][h * 2 + 1]));
            }
        }
}

extern "C" void kernel_launch(void* const* d_in, const int* in_sizes, int n_in,
                              void* d_out, int out_size)
{
    const float* q  = (const float*)d_in[0];
    const float* k  = (const float*)d_in[1];
    const float* v  = (const float*)d_in[2];
    const unsigned char* mask = (const unsigned char*)d_in[3];
    const float* Wq = (const float*)d_in[4];
    const float* Wk = (const float*)d_in[5];
    const float* Wv = (const float*)d_in[6];
    const float* Wo = (const float*)d_in[7];

    float* out  = (float*)d_out;            // [4,2048,1024]
    float* attn = out + 8388608;            // [4,16,2048,2048]

    cudaFuncSetAttribute(fused_attn_kernel,
                         cudaFuncAttributeMaxDynamicSharedMemorySize, FUSED_SMEM_BYTES);
    cudaFuncSetAttribute(proj_all_kernel,
                         cudaFuncAttributeMaxDynamicSharedMemorySize, GEMM_SMEM_BYTES);
    cudaFuncSetAttribute(out_kernel,
                         cudaFuncAttributeMaxDynamicSharedMemorySize, GEMM_SMEM_BYTES);

    preround_kernel<<<2048, 256>>>((const float4*)q, (const float4*)k, (const float4*)v,
                                   (const float4*)Wq, (const float4*)Wk,
                                   (const float4*)Wv, (const float4*)Wo);
    mask_any_kernel<<<1024, 256>>>(mask);

    proj_all_kernel<<<dim3(8, 64, 3), 256, GEMM_SMEM_BYTES>>>();
    fused_attn_kernel<<<dim3(16, 64), 512, FUSED_SMEM_BYTES>>>(mask, attn);
    out_kernel<<<dim3(8, 64), 256, GEMM_SMEM_BYTES>>>(out);
}

// round 12
// speedup vs baseline: 1.5796x; 1.0747x over previous
#include <cuda_runtime.h>
#include <cuda_fp16.h>
#include <cstdint>

// MultiHeadAttention: B=4, I=J=2048, WIDTH=1024, HEADS=16, HEAD_DIM=64
// Outputs: out [4,2048,1024] fp32, attn_weight [4,16,2048,2048] fp32
//
//   0. preround:   tf32-round q/k/v and weights (cp.async-ready)
//   1. mask_any:   per-(b,128x128) OR-flag
//   2. proj_all:   Q/K: fp32(tf32-rounded) + fp16 copies.  V: ONLY packed-fp16
//                  j-pair layout [z][kp][d] (PV B-operand-ready)
//   3. fused_attn: pass1 rowsums via fp16 m16n8k16; pass2 tf32 QK^T + E store
//                  + fp16 PV (Es16/Vs16 operands, half the fragment bytes)
//   4. out:        out = g_x @ Wo^T

#define IW 2097152ULL
#define HEADELEMS 131072ULL
#define ATTN_PER_HEAD 4194304ULL

__device__ float g_qp[8388608];
__device__ float g_kp[8388608];
__device__ float g_x [8388608];
__device__ float g_qr[8388608];
__device__ float g_kr[8388608];
__device__ float g_vr[8388608];
__device__ float g_wq[1048576];
__device__ float g_wk[1048576];
__device__ float g_wv[1048576];
__device__ float g_wo[1048576];
__device__ __half g_qb[8388608];
__device__ __half g_kb[8388608];
__device__ uint32_t g_vh[4194304];   // packed fp16 V: [z][kp][d], u32=(V[2kp][d],V[2kp+1][d])
__device__ int   g_mflag[1024];

__device__ __forceinline__ uint32_t f2tf(float x) {
    uint32_t u;
    asm("cvt.rna.tf32.f32 %0, %1;" : "=r"(u) : "f"(x));
    return u;
}
__device__ __forceinline__ float rtf(float x) { return __uint_as_float(f2tf(x)); }
__device__ __forceinline__ uint32_t fpack(float a, float b) {
    __half2 h = __floats2half2_rn(a, b);
    return *(uint32_t*)&h;
}

__device__ __forceinline__ void mma8(float* c, const uint32_t* a, const uint32_t* b) {
    asm("mma.sync.aligned.m16n8k8.row.col.f32.tf32.tf32.f32 "
        "{%0,%1,%2,%3}, {%4,%5,%6,%7}, {%8,%9}, {%0,%1,%2,%3};"
        : "+f"(c[0]), "+f"(c[1]), "+f"(c[2]), "+f"(c[3])
        : "r"(a[0]), "r"(a[1]), "r"(a[2]), "r"(a[3]), "r"(b[0]), "r"(b[1]));
}
__device__ __forceinline__ void mma16h(float* c, const uint32_t* a, const uint32_t* b) {
    asm("mma.sync.aligned.m16n8k16.row.col.f32.f16.f16.f32 "
        "{%0,%1,%2,%3}, {%4,%5,%6,%7}, {%8,%9}, {%0,%1,%2,%3};"
        : "+f"(c[0]), "+f"(c[1]), "+f"(c[2]), "+f"(c[3])
        : "r"(a[0]), "r"(a[1]), "r"(a[2]), "r"(a[3]), "r"(b[0]), "r"(b[1]));
}

__device__ __forceinline__ uint32_t s2u(const void* p) {
    return (uint32_t)__cvta_generic_to_shared(p);
}
__device__ __forceinline__ void cpa16(uint32_t dst, const void* src) {
    asm volatile("cp.async.cg.shared.global [%0], [%1], 16;" :: "r"(dst), "l"(src));
}
__device__ __forceinline__ void cpa_commit() { asm volatile("cp.async.commit_group;"); }
__device__ __forceinline__ void cpa_wait0()  { asm volatile("cp.async.wait_group 0;"); }
__device__ __forceinline__ void cpa_wait1()  { asm volatile("cp.async.wait_group 1;"); }

// ---------------------------------------------------------------------------
__global__ void preround_kernel(const float4* __restrict__ q, const float4* __restrict__ k,
                                const float4* __restrict__ v, const float4* __restrict__ wq,
                                const float4* __restrict__ wk, const float4* __restrict__ wv,
                                const float4* __restrict__ wo)
{
    const int stride = gridDim.x * blockDim.x;
    for (int i = blockIdx.x * blockDim.x + threadIdx.x; i < 2097152; i += stride) {
        float4 a = q[i];
        ((float4*)g_qr)[i] = make_float4(rtf(a.x), rtf(a.y), rtf(a.z), rtf(a.w));
        float4 b = k[i];
        ((float4*)g_kr)[i] = make_float4(rtf(b.x), rtf(b.y), rtf(b.z), rtf(b.w));
        float4 c = v[i];
        ((float4*)g_vr)[i] = make_float4(rtf(c.x), rtf(c.y), rtf(c.z), rtf(c.w));
        if (i < 262144) {
            float4 w0 = wq[i];
            ((float4*)g_wq)[i] = make_float4(rtf(w0.x), rtf(w0.y), rtf(w0.z), rtf(w0.w));
            float4 w1 = wk[i];
            ((float4*)g_wk)[i] = make_float4(rtf(w1.x), rtf(w1.y), rtf(w1.z), rtf(w1.w));
            float4 w2 = wv[i];
            ((float4*)g_wv)[i] = make_float4(rtf(w2.x), rtf(w2.y), rtf(w2.z), rtf(w2.w));
            float4 w3 = wo[i];
            ((float4*)g_wo)[i] = make_float4(rtf(w3.x), rtf(w3.y), rtf(w3.z), rtf(w3.w));
        }
    }
}

// ---------------------------------------------------------------------------
__global__ void mask_any_kernel(const unsigned char* __restrict__ mask)
{
    int bid = blockIdx.x;
    int b = bid >> 8, rem = bid & 255, ib = rem >> 4, jb = rem & 15;
    const unsigned char* base = mask + (size_t)b * ATTN_PER_HEAD
                                     + (size_t)ib * 128 * 2048 + (size_t)jb * 128;
    unsigned acc = 0;
    #pragma unroll
    for (int v = 0; v < 4; v++) {
        int idx = threadIdx.x + v * 256;
        int r = idx >> 3, c = (idx & 7) * 16;
        uint4 m = *(const uint4*)(base + (size_t)r * 2048 + c);
        acc |= m.x | m.y | m.z | m.w;
    }
    int any = __syncthreads_or(acc != 0);
    if (threadIdx.x == 0) g_mflag[bid] = any;
}

// ---------------------------------------------------------------------------
// 128x128-tile TN GEMM, M=8192, N=1024, K=1024. cp.async 2-stage pipeline.
// mode 0: fp32 raw out.  mode 1: fp32 tf32-rounded + fp16 copy (Cb).
// mode 2: ONLY packed-fp16 V output (j-pair layout via smem restage).
// ---------------------------------------------------------------------------
#define GEMM_SMEM_BYTES 73728

__device__ __forceinline__ void gemm1024_body(const float* __restrict__ A,
                                              const float* __restrict__ W,
                                              float* __restrict__ C, int mode,
                                              __half* __restrict__ Cb)
{
    extern __shared__ uint32_t dsm[];
    const int tid  = threadIdx.x;
    const int wid  = tid >> 5, lane = tid & 31;
    const int gid  = lane >> 2, tig = lane & 3;
    const int wrow = wid >> 2, wcol = wid & 3;
    const float* Ab = A + (size_t)blockIdx.y * 128 * 1024;
    const float* Bb = W + (size_t)blockIdx.x * 128 * 1024;
    const uint32_t smb = s2u(dsm);

    float c[4][4][4];
    #pragma unroll
    for (int mi = 0; mi < 4; mi++)
        #pragma unroll
        for (int ni = 0; ni < 4; ni++)
            #pragma unroll
            for (int r = 0; r < 4; r++) c[mi][ni][r] = 0.f;

    #pragma unroll
    for (int v = 0; v < 4; v++) {
        int i = tid + v * 256;
        int r = i >> 3, cu = (i & 7) << 2;
        cpa16(smb + (r * 36 + cu) * 4,        Ab + (size_t)r * 1024 + cu);
        cpa16(smb + (4608 + r * 36 + cu) * 4, Bb + (size_t)r * 1024 + cu);
    }
    cpa_commit();

    for (int kti = 0; kti < 32; kti++) {
        if (kti < 31) {
            const int s = (kti + 1) & 1;
            const int kn = (kti + 1) * 32;
            #pragma unroll
            for (int v = 0; v < 4; v++) {
                int i = tid + v * 256;
                int r = i >> 3, cu = (i & 7) << 2;
                cpa16(smb + (s * 9216 + r * 36 + cu) * 4,        Ab + (size_t)r * 1024 + kn + cu);
                cpa16(smb + (s * 9216 + 4608 + r * 36 + cu) * 4, Bb + (size_t)r * 1024 + kn + cu);
            }
            cpa_commit();
            cpa_wait1();
        } else {
            cpa_wait0();
        }
        __syncthreads();

        const uint32_t* As = dsm + (kti & 1) * 9216;
        const uint32_t* Bs = As + 4608;
        #pragma unroll
        for (int kk = 0; kk < 32; kk += 8) {
            uint32_t af[4][4], bf[4][2];
            #pragma unroll
            for (int mi = 0; mi < 4; mi++) {
                int m = wrow * 64 + mi * 16 + gid;
                af[mi][0] = As[m * 36 + kk + tig];
                af[mi][1] = As[(m + 8) * 36 + kk + tig];
                af[mi][2] = As[m * 36 + kk + tig + 4];
                af[mi][3] = As[(m + 8) * 36 + kk + tig + 4];
            }
            #pragma unroll
            for (int ni = 0; ni < 4; ni++) {
                int n = wcol * 32 + ni * 8 + gid;
                bf[ni][0] = Bs[n * 36 + kk + tig];
                bf[ni][1] = Bs[n * 36 + kk + tig + 4];
            }
            #pragma unroll
            for (int mi = 0; mi < 4; mi++)
                #pragma unroll
                for (int ni = 0; ni < 4; ni++)
                    mma8(c[mi][ni], af[mi], bf[ni]);
        }
        __syncthreads();
    }

    if (mode == 2) {
        // ---- V: restage fp32 tile to smem, emit packed fp16 j-pairs ----
        float* S = (float*)dsm;                    // 128 x 132
        #pragma unroll
        for (int mi = 0; mi < 4; mi++)
            #pragma unroll
            for (int ni = 0; ni < 4; ni++) {
                int rl = wrow * 64 + mi * 16 + gid;
                int cl = wcol * 32 + ni * 8 + tig * 2;
                S[rl * 132 + cl]            = c[mi][ni][0];
                S[rl * 132 + cl + 1]        = c[mi][ni][1];
                S[(rl + 8) * 132 + cl]      = c[mi][ni][2];
                S[(rl + 8) * 132 + cl + 1]  = c[mi][ni][3];
            }
        __syncthreads();
        // rows of this tile all belong to head z = blockIdx.y; kp = r*8 + bx
        // 4096 uint2 total, 256 threads -> 16 per thread  (R11 bug: used v*512)
        const size_t zb = (size_t)blockIdx.y * 65536;
        #pragma unroll
        for (int v = 0; v < 16; v++) {
            int i2 = tid + v * 256;                // 4096 uint2
            int r = i2 >> 5, dp = (i2 & 31) * 2;
            uint32_t u0 = fpack(S[r * 132 + dp],     S[r * 132 + 64 + dp]);
            uint32_t u1 = fpack(S[r * 132 + dp + 1], S[r * 132 + 65 + dp]);
            size_t gi = zb + (size_t)(r * 8 + blockIdx.x) * 64 + dp;
            *(uint2*)(g_vh + gi) = make_uint2(u0, u1);
        }
        return;
    }

    #pragma unroll
    for (int mi = 0; mi < 4; mi++)
        #pragma unroll
        for (int ni = 0; ni < 4; ni++) {
            int row = blockIdx.y * 128 + wrow * 64 + mi * 16 + gid;
            int col = blockIdx.x * 128 + wcol * 32 + ni * 8 + tig * 2;
            if (mode == 1) {
                *(float2*)(C + (size_t)row * 1024 + col)       = make_float2(rtf(c[mi][ni][0]), rtf(c[mi][ni][1]));
                *(float2*)(C + (size_t)(row + 8) * 1024 + col) = make_float2(rtf(c[mi][ni][2]), rtf(c[mi][ni][3]));
                *(uint32_t*)(Cb + (size_t)row * 1024 + col)       = fpack(c[mi][ni][0], c[mi][ni][1]);
                *(uint32_t*)(Cb + (size_t)(row + 8) * 1024 + col) = fpack(c[mi][ni][2], c[mi][ni][3]);
            } else {
                *(float2*)(C + (size_t)row * 1024 + col)       = make_float2(c[mi][ni][0], c[mi][ni][1]);
                *(float2*)(C + (size_t)(row + 8) * 1024 + col) = make_float2(c[mi][ni][2], c[mi][ni][3]);
            }
        }
}

__global__ __launch_bounds__(256, 2)
void proj_all_kernel()
{
    const int which = blockIdx.z;
    if (which == 2) {
        gemm1024_body(g_vr, g_wv, (float*)0, 2, (__half*)0);
    } else {
        const float* A = (which == 0) ? g_qr : g_kr;
        const float* W = (which == 0) ? g_wq : g_wk;
        float* C = (which == 0) ? g_qp : g_kp;
        __half* Cb = (which == 0) ? g_qb : g_kb;
        gemm1024_body(A, W, C, 1, Cb);
    }
}

__global__ __launch_bounds__(256, 2)
void out_kernel(float* __restrict__ C)
{
    gemm1024_body(g_x, g_wo, C, 0, (__half*)0);
}

// ---------------------------------------------------------------------------
// Fused attention v4. 512 threads (16 warps 4x4), per (iblk=128, head z).
// j-tile 128. Pass1: fp16 m16n8k16 QK^T (rowsums). Pass2: tf32 QK^T + E store
// + fp16 PV (A=Es16, B=Vs16 packed).
// smem u32: Qs 128x68 | Ks 128x68 | Vs16 64x72 | Es 128x132 | Es16 128x68 | sinv
// Pass1 aliases Es region: Qh16 128x36 | Kh16 buf0/buf1 128x36
// ---------------------------------------------------------------------------
#define QS_OFF   0
#define KS_OFF   8704
#define VS_OFF   17408
#define ES_OFF   22016
#define ES16_OFF 38912
#define SINV_OFF 47616
#define QB_OFF   (ES_OFF)
#define KB0_OFF  (ES_OFF + 4608)
#define KB1_OFF  (ES_OFF + 9216)
#define FUSED_SMEM_U32 (47616 + 128)
#define FUSED_SMEM_BYTES (FUSED_SMEM_U32 * 4)

// tf32: S = Q(128x64) x K(128x64)^T, warp tile 32x32
__device__ __forceinline__ void s_compute128(const uint32_t* __restrict__ Qs,
                                             const uint32_t* __restrict__ Ksb,
                                             int wr, int wc, int gid, int tig,
                                             float c_s[2][4][4])
{
    #pragma unroll
    for (int mi = 0; mi < 2; mi++)
        #pragma unroll
        for (int ni = 0; ni < 4; ni++)
            #pragma unroll
            for (int r = 0; r < 4; r++) c_s[mi][ni][r] = 0.f;
    #pragma unroll
    for (int kk = 0; kk < 64; kk += 8) {
        uint32_t af[2][4], bf[4][2];
        #pragma unroll
        for (int mi = 0; mi < 2; mi++) {
            int m = wr * 32 + mi * 16 + gid;
            af[mi][0] = Qs[m * 68 + kk + tig];
            af[mi][1] = Qs[(m + 8) * 68 + kk + tig];
            af[mi][2] = Qs[m * 68 + kk + tig + 4];
            af[mi][3] = Qs[(m + 8) * 68 + kk + tig + 4];
        }
        #pragma unroll
        for (int ni = 0; ni < 4; ni++) {
            int n = wc * 32 + ni * 8 + gid;
            bf[ni][0] = Ksb[n * 68 + kk + tig];
            bf[ni][1] = Ksb[n * 68 + kk + tig + 4];
        }
        #pragma unroll
        for (int mi = 0; mi < 2; mi++)
            #pragma unroll
            for (int ni = 0; ni < 4; ni++)
                mma8(c_s[mi][ni], af[mi], bf[ni]);
    }
}

// fp16: same logical tile via m16n8k16; operands packed 2/u32, stride 36.
__device__ __forceinline__ void s_compute128_f16(const uint32_t* __restrict__ Qb,
                                                 const uint32_t* __restrict__ Kb,
                                                 int wr, int wc, int gid, int tig,
                                                 float c_s[2][4][4])
{
    #pragma unroll
    for (int mi = 0; mi < 2; mi++)
        #pragma unroll
        for (int ni = 0; ni < 4; ni++)
            #pragma unroll
            for (int r = 0; r < 4; r++) c_s[mi][ni][r] = 0.f;
    #pragma unroll
    for (int kk = 0; kk < 32; kk += 8) {
        uint32_t af[2][4], bf[4][2];
        #pragma unroll
        for (int mi = 0; mi < 2; mi++) {
            int m = wr * 32 + mi * 16 + gid;
            af[mi][0] = Qb[m * 36 + kk + tig];
            af[mi][1] = Qb[(m + 8) * 36 + kk + tig];
            af[mi][2] = Qb[m * 36 + kk + tig + 4];
            af[mi][3] = Qb[(m + 8) * 36 + kk + tig + 4];
        }
        #pragma unroll
        for (int ni = 0; ni < 4; ni++) {
            int n = wc * 32 + ni * 8 + gid;
            bf[ni][0] = Kb[n * 36 + kk + tig];
            bf[ni][1] = Kb[n * 36 + kk + tig + 4];
        }
        #pragma unroll
        for (int mi = 0; mi < 2; mi++)
            #pragma unroll
            for (int ni = 0; ni < 4; ni++)
                mma16h(c_s[mi][ni], af[mi], bf[ni]);
    }
}

__global__ __launch_bounds__(512, 1)
void fused_attn_kernel(const unsigned char* __restrict__ mask, float* __restrict__ E)
{
    extern __shared__ uint32_t sh[];
    uint32_t* Qs   = sh + QS_OFF;
    uint32_t* Es   = sh + ES_OFF;
    uint32_t* Es16 = sh + ES16_OFF;
    float* sinv  = (float*)(sh + SINV_OFF);
    float* swsum = (float*)(sh + ES_OFF);      // aliases Qh16 (free after pass1)
    const uint32_t smb = s2u(sh);

    const int tid  = threadIdx.x;
    const int wid  = tid >> 5, lane = tid & 31;
    const int gid  = lane >> 2, tig = lane & 3;
    const int wr   = wid >> 2, wc = wid & 3;
    const int iblk = blockIdx.x;
    const int z    = blockIdx.y;
    const int b    = z >> 4, hd = z & 15;
    const int i0   = iblk * 128;

    const float* Qh = g_qp + (size_t)z * HEADELEMS + (size_t)i0 * 64;
    const float* Kh = g_kp + (size_t)z * HEADELEMS;
    const __half* Qbh = g_qb + (size_t)z * HEADELEMS + (size_t)i0 * 64;
    const __half* Kbh = g_kb + (size_t)z * HEADELEMS;
    const uint32_t* Vph = g_vh + (size_t)z * 65536;
    const unsigned char* mb = mask + (size_t)b * ATTN_PER_HEAD;
    const int* mf = &g_mflag[b * 256 + iblk * 16];
    float* Eh = E + (size_t)z * ATTN_PER_HEAD;

    // ---- initial: Qh16 (128x64 fp16) + Kh16 tile 0 ----
    #pragma unroll
    for (int v = 0; v < 2; v++) {
        int idx = tid + v * 512;               // 1024 chunks of 16B (8 fp16)
        int r = idx >> 3, ch = idx & 7;
        cpa16(smb + (QB_OFF + r * 36 + ch * 4) * 4, Qbh + (size_t)r * 64 + ch * 8);
        cpa16(smb + (KB0_OFF + r * 36 + ch * 4) * 4, Kbh + (size_t)r * 64 + ch * 8);
    }
    cpa_commit();
    cpa_wait0();
    __syncthreads();

    // =================  PASS 1: rowsums (fp16 QK^T)  =================
    float rs[4] = {0.f, 0.f, 0.f, 0.f};
    for (int ji = 0; ji < 16; ji++) {
        const int jt = ji * 128;
        const uint32_t kb = (ji & 1) ? KB1_OFF : KB0_OFF;
        const uint32_t nb = (ji & 1) ? KB0_OFF : KB1_OFF;
        if (ji < 15) {
            #pragma unroll
            for (int v = 0; v < 2; v++) {
                int idx = tid + v * 512;
                int r = idx >> 3, ch = idx & 7;
                cpa16(smb + (nb + r * 36 + ch * 4) * 4,
                      Kbh + (size_t)(jt + 128 + r) * 64 + ch * 8);
            }
            cpa_commit();
        }
        float c_s[2][4][4];
        s_compute128_f16(sh + QB_OFF, sh + kb, wr, wc, gid, tig, c_s);

        const bool use_mask = mf[ji] != 0;
        #pragma unroll
        for (int mi = 0; mi < 2; mi++)
            #pragma unroll
            for (int h = 0; h < 2; h++) {
                int row = wr * 32 + mi * 16 + h * 8 + gid;
                float acc = 0.f;
                #pragma unroll
                for (int ni = 0; ni < 4; ni++) {
                    int col = wc * 32 + ni * 8 + tig * 2;
                    float s0 = c_s[mi][ni][h * 2 + 0];
                    float s1 = c_s[mi][ni][h * 2 + 1];
                    if (use_mask) {
                        size_t gi = (size_t)(i0 + row) * 2048 + jt + col;
                        if (mb[gi])     s0 = -1e9f;
                        if (mb[gi + 1]) s1 = -1e9f;
                    }
                    acc += __expf(s0 * 0.125f) + __expf(s1 * 0.125f);
                }
                rs[mi * 2 + h] += acc;
            }
        if (ji < 15) cpa_wait0();
        __syncthreads();
    }

    // ---- reduce rowsums; kick off pass-2 loads (Qs, K0 tf32, V0 fp16) ----
    #pragma unroll
    for (int p = 0; p < 4; p++) {
        rs[p] += __shfl_xor_sync(0xffffffffu, rs[p], 1);
        rs[p] += __shfl_xor_sync(0xffffffffu, rs[p], 2);
    }
    #pragma unroll
    for (int v = 0; v < 4; v++) {
        int idx = tid + v * 512;
        int r = idx >> 4, cu = (idx & 15) << 2;
        cpa16(smb + (QS_OFF + r * 68 + cu) * 4, Qh + (size_t)r * 64 + cu);
        cpa16(smb + (KS_OFF + r * 68 + cu) * 4, Kh + (size_t)r * 64 + cu);
    }
    #pragma unroll
    for (int v = 0; v < 2; v++) {
        int ci = tid + v * 512;                // 1024 chunks: V tile 64x64 u32
        int r = ci >> 4, off = (ci & 15) * 4;
        cpa16(smb + (VS_OFF + r * 72 + off) * 4, Vph + r * 64 + off);
    }
    cpa_commit();
    if (tig == 0) {
        #pragma unroll
        for (int mi = 0; mi < 2; mi++)
            #pragma unroll
            for (int h = 0; h < 2; h++)
                swsum[wc * 128 + wr * 32 + mi * 16 + h * 8 + gid] = rs[mi * 2 + h];
    }
    __syncthreads();
    if (tid < 128)
        sinv[tid] = 1.0f / (swsum[tid] + swsum[128 + tid] + swsum[256 + tid] + swsum[384 + tid]);
    cpa_wait0();
    __syncthreads();

    // ==========  PASS 2: tf32 QK^T, E store, fp16 PV  ==========
    float c_o[2][2][4];
    #pragma unroll
    for (int mi = 0; mi < 2; mi++)
        #pragma unroll
        for (int ni = 0; ni < 2; ni++)
            #pragma unroll
            for (int r = 0; r < 4; r++) c_o[mi][ni][r] = 0.f;

    for (int ji = 0; ji < 16; ji++) {
        const int jt = ji * 128;
        if (ji > 0) {       // K(ji) arrived (V(ji) may still be in flight)
            cpa_wait1();
            __syncthreads();
        }
        float c_s[2][4][4];
        s_compute128(Qs, sh + KS_OFF, wr, wc, gid, tig, c_s);

        cpa_wait0();        // V(ji) resident
        __syncthreads();    // all warps done reading KS -> safe to refill
        if (ji < 15) {
            #pragma unroll
            for (int v = 0; v < 4; v++) {
                int idx = tid + v * 512;
                int r = idx >> 4, cu = (idx & 15) << 2;
                cpa16(smb + (KS_OFF + r * 68 + cu) * 4,
                      Kh + (size_t)(jt + 128 + r) * 64 + cu);
            }
            cpa_commit();
        }

        const bool use_mask = mf[ji] != 0;
        #pragma unroll
        for (int mi = 0; mi < 2; mi++)
            #pragma unroll
            for (int h = 0; h < 2; h++) {
                int row = wr * 32 + mi * 16 + h * 8 + gid;
                float iv = sinv[row];
                #pragma unroll
                for (int ni = 0; ni < 4; ni++) {
                    int col = wc * 32 + ni * 8 + tig * 2;
                    float s0 = c_s[mi][ni][h * 2 + 0];
                    float s1 = c_s[mi][ni][h * 2 + 1];
                    if (use_mask) {
                        size_t gi = (size_t)(i0 + row) * 2048 + jt + col;
                        if (mb[gi])     s0 = -1e9f;
                        if (mb[gi + 1]) s1 = -1e9f;
                    }
                    float e0 = __expf(s0 * 0.125f) * iv;
                    float e1 = __expf(s1 * 0.125f) * iv;
                    *(uint2*)&Es[row * 132 + col] = make_uint2(f2tf(e0), f2tf(e1));
                    Es16[row * 68 + (col >> 1)] = fpack(e0, e1);
                }
            }
        __syncthreads();    // Es / Es16 tiles complete

        // coalesced normalized-E output, 128x128 tile
        #pragma unroll
        for (int v = 0; v < 8; v++) {
            int idx = tid + v * 512;
            int r = idx >> 5, c4 = (idx & 31) * 4;
            float4 val = *(const float4*)((const float*)&Es[r * 132 + c4]);
            *(float4*)(Eh + (size_t)(i0 + r) * 2048 + jt + c4) = val;
        }

        // PV: O += Es16(128x128 fp16) @ Vs16(128x64 fp16), warp tile 32x16
        #pragma unroll
        for (int s = 0; s < 8; s++) {
            uint32_t af[2][4], bf[2][2];
            #pragma unroll
            for (int mi = 0; mi < 2; mi++) {
                int m = wr * 32 + mi * 16 + gid;
                af[mi][0] = Es16[m * 68 + s * 8 + tig];
                af[mi][1] = Es16[(m + 8) * 68 + s * 8 + tig];
                af[mi][2] = Es16[m * 68 + s * 8 + tig + 4];
                af[mi][3] = Es16[(m + 8) * 68 + s * 8 + tig + 4];
            }
            #pragma unroll
            for (int ni = 0; ni < 2; ni++) {
                int n = wc * 16 + ni * 8 + gid;
                bf[ni][0] = sh[VS_OFF + (s * 8 + tig) * 72 + n];
                bf[ni][1] = sh[VS_OFF + (s * 8 + tig + 4) * 72 + n];
            }
            #pragma unroll
            for (int mi = 0; mi < 2; mi++)
                #pragma unroll
                for (int ni = 0; ni < 2; ni++)
                    mma16h(c_o[mi][ni], af[mi], bf[ni]);
        }
        __syncthreads();    // done with Es16 and Vs16
        if (ji < 15) {
            const uint32_t* vsrc = Vph + ((jt + 128) >> 1) * 64;
            #pragma unroll
            for (int v = 0; v < 2; v++) {
                int ci = tid + v * 512;
                int r = ci >> 4, off = (ci & 15) * 4;
                cpa16(smb + (VS_OFF + r * 72 + off) * 4, vsrc + r * 64 + off);
            }
            cpa_commit();
        }
    }

    // ---- write O (tf32-rounded: feeds cp.async out-GEMM) ----
    #pragma unroll
    for (int mi = 0; mi < 2; mi++)
        #pragma unroll
        for (int h = 0; h < 2; h++) {
            int i = i0 + wr * 32 + mi * 16 + h * 8 + gid;
            float* Xr = g_x + (size_t)b * IW + (size_t)i * 1024 + hd * 64;
            #pragma unroll
            for (int ni = 0; ni < 2; ni++) {
                int d = wc * 16 + ni * 8 + tig * 2;
                *(float2*)(Xr + d) = make_float2(rtf(c_o[mi][ni][h * 2]),
                                                 rtf(c_o[mi][ni][h * 2 + 1]));
            }
        }
}

extern "C" void kernel_launch(void* const* d_in, const int* in_sizes, int n_in,
                              void* d_out, int out_size)
{
    const float* q  = (const float*)d_in[0];
    const float* k  = (const float*)d_in[1];
    const float* v  = (const float*)d_in[2];
    const unsigned char* mask = (const unsigned char*)d_in[3];
    const float* Wq = (const float*)d_in[4];
    const float* Wk = (const float*)d_in[5];
    const float* Wv = (const float*)d_in[6];
    const float* Wo = (const float*)d_in[7];

    float* out  = (float*)d_out;            // [4,2048,1024]
    float* attn = out + 8388608;            // [4,16,2048,2048]

    cudaFuncSetAttribute(fused_attn_kernel,
                         cudaFuncAttributeMaxDynamicSharedMemorySize, FUSED_SMEM_BYTES);
    cudaFuncSetAttribute(proj_all_kernel,
                         cudaFuncAttributeMaxDynamicSharedMemorySize, GEMM_SMEM_BYTES);
    cudaFuncSetAttribute(out_kernel,
                         cudaFuncAttributeMaxDynamicSharedMemorySize, GEMM_SMEM_BYTES);

    preround_kernel<<<2048, 256>>>((const float4*)q, (const float4*)k, (const float4*)v,
                                   (const float4*)Wq, (const float4*)Wk,
                                   (const float4*)Wv, (const float4*)Wo);
    mask_any_kernel<<<1024, 256>>>(mask);

    proj_all_kernel<<<dim3(8, 64, 3), 256, GEMM_SMEM_BYTES>>>();
    fused_attn_kernel<<<dim3(16, 64), 512, FUSED_SMEM_BYTES>>>(mask, attn);
    out_kernel<<<dim3(8, 64), 256, GEMM_SMEM_BYTES>>>(out);
}

// round 14
// speedup vs baseline: 1.7573x; 1.1125x over previous
#include <cuda_runtime.h>
#include <cuda_fp16.h>
#include <cstdint>

// MultiHeadAttention: B=4, I=J=2048, WIDTH=1024, HEADS=16, HEAD_DIM=64
// Outputs: out [4,2048,1024] fp32, attn_weight [4,16,2048,2048] fp32
//
//   0. preround:   tf32-round q/k/v and weights (proj GEMM inputs)
//   1. mask_any:   per-(b,128x128) OR-flag
//   2. proj_all:   Q/K -> fp16 ONLY.  V -> packed-fp16 j-pair layout [z][kp][d]
//   3. fused_attn: BOTH passes fp16 m16n8k16 QK^T (bitwise-identical S);
//                  pass1 rowsums, pass2 E store (fp32) + fp16 PV.
//                  Pass2: clean 2-stage K+V double-buffered pipeline.
//   4. out:        out = g_x @ Wo^T (tf32 GEMM)

#define IW 2097152ULL
#define HEADELEMS 131072ULL
#define ATTN_PER_HEAD 4194304ULL

__device__ float g_x [8388608];
__device__ float g_qr[8388608];
__device__ float g_kr[8388608];
__device__ float g_vr[8388608];
__device__ float g_wq[1048576];
__device__ float g_wk[1048576];
__device__ float g_wv[1048576];
__device__ float g_wo[1048576];
__device__ __half g_qb[8388608];
__device__ __half g_kb[8388608];
__device__ uint32_t g_vh[4194304];   // packed fp16 V: [z][kp][d], u32=(V[2kp][d],V[2kp+1][d])
__device__ int   g_mflag[1024];

__device__ __forceinline__ uint32_t f2tf(float x) {
    uint32_t u;
    asm("cvt.rna.tf32.f32 %0, %1;" : "=r"(u) : "f"(x));
    return u;
}
__device__ __forceinline__ float rtf(float x) { return __uint_as_float(f2tf(x)); }
__device__ __forceinline__ uint32_t fpack(float a, float b) {
    __half2 h = __floats2half2_rn(a, b);
    return *(uint32_t*)&h;
}

__device__ __forceinline__ void mma8(float* c, const uint32_t* a, const uint32_t* b) {
    asm("mma.sync.aligned.m16n8k8.row.col.f32.tf32.tf32.f32 "
        "{%0,%1,%2,%3}, {%4,%5,%6,%7}, {%8,%9}, {%0,%1,%2,%3};"
        : "+f"(c[0]), "+f"(c[1]), "+f"(c[2]), "+f"(c[3])
        : "r"(a[0]), "r"(a[1]), "r"(a[2]), "r"(a[3]), "r"(b[0]), "r"(b[1]));
}
__device__ __forceinline__ void mma16h(float* c, const uint32_t* a, const uint32_t* b) {
    asm("mma.sync.aligned.m16n8k16.row.col.f32.f16.f16.f32 "
        "{%0,%1,%2,%3}, {%4,%5,%6,%7}, {%8,%9}, {%0,%1,%2,%3};"
        : "+f"(c[0]), "+f"(c[1]), "+f"(c[2]), "+f"(c[3])
        : "r"(a[0]), "r"(a[1]), "r"(a[2]), "r"(a[3]), "r"(b[0]), "r"(b[1]));
}

__device__ __forceinline__ uint32_t s2u(const void* p) {
    return (uint32_t)__cvta_generic_to_shared(p);
}
__device__ __forceinline__ void cpa16(uint32_t dst, const void* src) {
    asm volatile("cp.async.cg.shared.global [%0], [%1], 16;" :: "r"(dst), "l"(src));
}
__device__ __forceinline__ void cpa_commit() { asm volatile("cp.async.commit_group;"); }
__device__ __forceinline__ void cpa_wait0()  { asm volatile("cp.async.wait_group 0;"); }
__device__ __forceinline__ void cpa_wait1()  { asm volatile("cp.async.wait_group 1;"); }

// ---------------------------------------------------------------------------
__global__ void preround_kernel(const float4* __restrict__ q, const float4* __restrict__ k,
                                const float4* __restrict__ v, const float4* __restrict__ wq,
                                const float4* __restrict__ wk, const float4* __restrict__ wv,
                                const float4* __restrict__ wo)
{
    const int stride = gridDim.x * blockDim.x;
    for (int i = blockIdx.x * blockDim.x + threadIdx.x; i < 2097152; i += stride) {
        float4 a = q[i];
        ((float4*)g_qr)[i] = make_float4(rtf(a.x), rtf(a.y), rtf(a.z), rtf(a.w));
        float4 b = k[i];
        ((float4*)g_kr)[i] = make_float4(rtf(b.x), rtf(b.y), rtf(b.z), rtf(b.w));
        float4 c = v[i];
        ((float4*)g_vr)[i] = make_float4(rtf(c.x), rtf(c.y), rtf(c.z), rtf(c.w));
        if (i < 262144) {
            float4 w0 = wq[i];
            ((float4*)g_wq)[i] = make_float4(rtf(w0.x), rtf(w0.y), rtf(w0.z), rtf(w0.w));
            float4 w1 = wk[i];
            ((float4*)g_wk)[i] = make_float4(rtf(w1.x), rtf(w1.y), rtf(w1.z), rtf(w1.w));
            float4 w2 = wv[i];
            ((float4*)g_wv)[i] = make_float4(rtf(w2.x), rtf(w2.y), rtf(w2.z), rtf(w2.w));
            float4 w3 = wo[i];
            ((float4*)g_wo)[i] = make_float4(rtf(w3.x), rtf(w3.y), rtf(w3.z), rtf(w3.w));
        }
    }
}

// ---------------------------------------------------------------------------
__global__ void mask_any_kernel(const unsigned char* __restrict__ mask)
{
    int bid = blockIdx.x;
    int b = bid >> 8, rem = bid & 255, ib = rem >> 4, jb = rem & 15;
    const unsigned char* base = mask + (size_t)b * ATTN_PER_HEAD
                                     + (size_t)ib * 128 * 2048 + (size_t)jb * 128;
    unsigned acc = 0;
    #pragma unroll
    for (int v = 0; v < 4; v++) {
        int idx = threadIdx.x + v * 256;
        int r = idx >> 3, c = (idx & 7) * 16;
        uint4 m = *(const uint4*)(base + (size_t)r * 2048 + c);
        acc |= m.x | m.y | m.z | m.w;
    }
    int any = __syncthreads_or(acc != 0);
    if (threadIdx.x == 0) g_mflag[bid] = any;
}

// ---------------------------------------------------------------------------
// 128x128-tile TN GEMM, M=8192, N=1024, K=1024. cp.async 2-stage pipeline.
// mode 0: fp32 raw out (C).  mode 1: fp16 ONLY (Cb).
// mode 2: packed-fp16 V output (j-pair layout via smem restage).
// ---------------------------------------------------------------------------
#define GEMM_SMEM_BYTES 73728

__device__ __forceinline__ void gemm1024_body(const float* __restrict__ A,
                                              const float* __restrict__ W,
                                              float* __restrict__ C, int mode,
                                              __half* __restrict__ Cb)
{
    extern __shared__ uint32_t dsm[];
    const int tid  = threadIdx.x;
    const int wid  = tid >> 5, lane = tid & 31;
    const int gid  = lane >> 2, tig = lane & 3;
    const int wrow = wid >> 2, wcol = wid & 3;
    const float* Ab = A + (size_t)blockIdx.y * 128 * 1024;
    const float* Bb = W + (size_t)blockIdx.x * 128 * 1024;
    const uint32_t smb = s2u(dsm);

    float c[4][4][4];
    #pragma unroll
    for (int mi = 0; mi < 4; mi++)
        #pragma unroll
        for (int ni = 0; ni < 4; ni++)
            #pragma unroll
            for (int r = 0; r < 4; r++) c[mi][ni][r] = 0.f;

    #pragma unroll
    for (int v = 0; v < 4; v++) {
        int i = tid + v * 256;
        int r = i >> 3, cu = (i & 7) << 2;
        cpa16(smb + (r * 36 + cu) * 4,        Ab + (size_t)r * 1024 + cu);
        cpa16(smb + (4608 + r * 36 + cu) * 4, Bb + (size_t)r * 1024 + cu);
    }
    cpa_commit();

    for (int kti = 0; kti < 32; kti++) {
        if (kti < 31) {
            const int s = (kti + 1) & 1;
            const int kn = (kti + 1) * 32;
            #pragma unroll
            for (int v = 0; v < 4; v++) {
                int i = tid + v * 256;
                int r = i >> 3, cu = (i & 7) << 2;
                cpa16(smb + (s * 9216 + r * 36 + cu) * 4,        Ab + (size_t)r * 1024 + kn + cu);
                cpa16(smb + (s * 9216 + 4608 + r * 36 + cu) * 4, Bb + (size_t)r * 1024 + kn + cu);
            }
            cpa_commit();
            cpa_wait1();
        } else {
            cpa_wait0();
        }
        __syncthreads();

        const uint32_t* As = dsm + (kti & 1) * 9216;
        const uint32_t* Bs = As + 4608;
        #pragma unroll
        for (int kk = 0; kk < 32; kk += 8) {
            uint32_t af[4][4], bf[4][2];
            #pragma unroll
            for (int mi = 0; mi < 4; mi++) {
                int m = wrow * 64 + mi * 16 + gid;
                af[mi][0] = As[m * 36 + kk + tig];
                af[mi][1] = As[(m + 8) * 36 + kk + tig];
                af[mi][2] = As[m * 36 + kk + tig + 4];
                af[mi][3] = As[(m + 8) * 36 + kk + tig + 4];
            }
            #pragma unroll
            for (int ni = 0; ni < 4; ni++) {
                int n = wcol * 32 + ni * 8 + gid;
                bf[ni][0] = Bs[n * 36 + kk + tig];
                bf[ni][1] = Bs[n * 36 + kk + tig + 4];
            }
            #pragma unroll
            for (int mi = 0; mi < 4; mi++)
                #pragma unroll
                for (int ni = 0; ni < 4; ni++)
                    mma8(c[mi][ni], af[mi], bf[ni]);
        }
        __syncthreads();
    }

    if (mode == 2) {
        // ---- V: restage fp32 tile to smem, emit packed fp16 j-pairs ----
        float* S = (float*)dsm;                    // 128 x 132
        #pragma unroll
        for (int mi = 0; mi < 4; mi++)
            #pragma unroll
            for (int ni = 0; ni < 4; ni++) {
                int rl = wrow * 64 + mi * 16 + gid;
                int cl = wcol * 32 + ni * 8 + tig * 2;
                S[rl * 132 + cl]            = c[mi][ni][0];
                S[rl * 132 + cl + 1]        = c[mi][ni][1];
                S[(rl + 8) * 132 + cl]      = c[mi][ni][2];
                S[(rl + 8) * 132 + cl + 1]  = c[mi][ni][3];
            }
        __syncthreads();
        const size_t zb = (size_t)blockIdx.y * 65536;
        #pragma unroll
        for (int v = 0; v < 16; v++) {
            int i2 = tid + v * 256;                // 4096 uint2, 256 threads
            int r = i2 >> 5, dp = (i2 & 31) * 2;
            uint32_t u0 = fpack(S[r * 132 + dp],     S[r * 132 + 64 + dp]);
            uint32_t u1 = fpack(S[r * 132 + dp + 1], S[r * 132 + 65 + dp]);
            size_t gi = zb + (size_t)(r * 8 + blockIdx.x) * 64 + dp;
            *(uint2*)(g_vh + gi) = make_uint2(u0, u1);
        }
        return;
    }

    #pragma unroll
    for (int mi = 0; mi < 4; mi++)
        #pragma unroll
        for (int ni = 0; ni < 4; ni++) {
            int row = blockIdx.y * 128 + wrow * 64 + mi * 16 + gid;
            int col = blockIdx.x * 128 + wcol * 32 + ni * 8 + tig * 2;
            if (mode == 1) {
                *(uint32_t*)(Cb + (size_t)row * 1024 + col)       = fpack(c[mi][ni][0], c[mi][ni][1]);
                *(uint32_t*)(Cb + (size_t)(row + 8) * 1024 + col) = fpack(c[mi][ni][2], c[mi][ni][3]);
            } else {
                *(float2*)(C + (size_t)row * 1024 + col)       = make_float2(c[mi][ni][0], c[mi][ni][1]);
                *(float2*)(C + (size_t)(row + 8) * 1024 + col) = make_float2(c[mi][ni][2], c[mi][ni][3]);
            }
        }
}

__global__ __launch_bounds__(256, 2)
void proj_all_kernel()
{
    const int which = blockIdx.z;
    if (which == 2) {
        gemm1024_body(g_vr, g_wv, (float*)0, 2, (__half*)0);
    } else {
        const float* A = (which == 0) ? g_qr : g_kr;
        const float* W = (which == 0) ? g_wq : g_wk;
        __half* Cb = (which == 0) ? g_qb : g_kb;
        gemm1024_body(A, W, (float*)0, 1, Cb);
    }
}

__global__ __launch_bounds__(256, 2)
void out_kernel(float* __restrict__ C)
{
    gemm1024_body(g_x, g_wo, C, 0, (__half*)0);
}

// ---------------------------------------------------------------------------
// Fused attention v5. 512 threads (16 warps 4x4), per (iblk=128, head z).
// j-tile 128. BOTH passes: fp16 m16n8k16 QK^T from persistent Qb + dbl-buf Kb.
// Pass2 adds: E epilogue (fp32 Es + fp16 Es16), coalesced E STG, fp16 PV with
// double-buffered V. One cp.async group (K+V) per iter -> wait0 pipeline.
// smem u32: Qb 128x36 | Kb0 | Kb1 | Vs0 64x72 | Vs1 | Es 128x132 | Es16 128x68 | sinv
// ---------------------------------------------------------------------------
#define QB_OFF   0
#define KB0_OFF  4608
#define KB1_OFF  9216
#define VS0_OFF  13824
#define VS1_OFF  18432
#define ES_OFF   23040
#define ES16_OFF 39936
#define SINV_OFF 48640
#define FUSED_SMEM_U32 48768
#define FUSED_SMEM_BYTES (FUSED_SMEM_U32 * 4)

// fp16 S = Q(128x64) x K(128x64)^T, warp tile 32x32; operands packed 2/u32.
__device__ __forceinline__ void s_compute128_f16(const uint32_t* __restrict__ Qb,
                                                 const uint32_t* __restrict__ Kb,
                                                 int wr, int wc, int gid, int tig,
                                                 float c_s[2][4][4])
{
    #pragma unroll
    for (int mi = 0; mi < 2; mi++)
        #pragma unroll
        for (int ni = 0; ni < 4; ni++)
            #pragma unroll
            for (int r = 0; r < 4; r++) c_s[mi][ni][r] = 0.f;
    #pragma unroll
    for (int kk = 0; kk < 32; kk += 8) {
        uint32_t af[2][4], bf[4][2];
        #pragma unroll
        for (int mi = 0; mi < 2; mi++) {
            int m = wr * 32 + mi * 16 + gid;
            af[mi][0] = Qb[m * 36 + kk + tig];
            af[mi][1] = Qb[(m + 8) * 36 + kk + tig];
            af[mi][2] = Qb[m * 36 + kk + tig + 4];
            af[mi][3] = Qb[(m + 8) * 36 + kk + tig + 4];
        }
        #pragma unroll
        for (int ni = 0; ni < 4; ni++) {
            int n = wc * 32 + ni * 8 + gid;
            bf[ni][0] = Kb[n * 36 + kk + tig];
            bf[ni][1] = Kb[n * 36 + kk + tig + 4];
        }
        #pragma unroll
        for (int mi = 0; mi < 2; mi++)
            #pragma unroll
            for (int ni = 0; ni < 4; ni++)
                mma16h(c_s[mi][ni], af[mi], bf[ni]);
    }
}

__global__ __launch_bounds__(512, 1)
void fused_attn_kernel(const unsigned char* __restrict__ mask, float* __restrict__ E)
{
    extern __shared__ uint32_t sh[];
    uint32_t* Es   = sh + ES_OFF;
    uint32_t* Es16 = sh + ES16_OFF;
    float* sinv  = (float*)(sh + SINV_OFF);
    float* swsum = (float*)(sh + ES_OFF);      // scratch (pass-1 only)
    const uint32_t smb = s2u(sh);

    const int tid  = threadIdx.x;
    const int wid  = tid >> 5, lane = tid & 31;
    const int gid  = lane >> 2, tig = lane & 3;
    const int wr   = wid >> 2, wc = wid & 3;
    const int iblk = blockIdx.x;
    const int z    = blockIdx.y;
    const int b    = z >> 4, hd = z & 15;
    const int i0   = iblk * 128;

    const __half* Qbh = g_qb + (size_t)z * HEADELEMS + (size_t)i0 * 64;
    const __half* Kbh = g_kb + (size_t)z * HEADELEMS;
    const uint32_t* Vph = g_vh + (size_t)z * 65536;
    const unsigned char* mb = mask + (size_t)b * ATTN_PER_HEAD;
    const int* mf = &g_mflag[b * 256 + iblk * 16];
    float* Eh = E + (size_t)z * ATTN_PER_HEAD;

    // ---- initial: Qb (128x64 fp16) + Kb tile 0 -> KB0 ----
    #pragma unroll
    for (int v = 0; v < 2; v++) {
        int idx = tid + v * 512;               // 1024 chunks of 16B (8 fp16)
        int r = idx >> 3, ch = idx & 7;
        cpa16(smb + (QB_OFF + r * 36 + ch * 4) * 4, Qbh + (size_t)r * 64 + ch * 8);
        cpa16(smb + (KB0_OFF + r * 36 + ch * 4) * 4, Kbh + (size_t)r * 64 + ch * 8);
    }
    cpa_commit();
    cpa_wait0();
    __syncthreads();

    // =================  PASS 1: rowsums  =================
    float rs[4] = {0.f, 0.f, 0.f, 0.f};
    for (int ji = 0; ji < 16; ji++) {
        const int jt = ji * 128;
        const uint32_t kb = (ji & 1) ? KB1_OFF : KB0_OFF;
        const uint32_t nb = (ji & 1) ? KB0_OFF : KB1_OFF;
        if (ji < 15) {
            #pragma unroll
            for (int v = 0; v < 2; v++) {
                int idx = tid + v * 512;
                int r = idx >> 3, ch = idx & 7;
                cpa16(smb + (nb + r * 36 + ch * 4) * 4,
                      Kbh + (size_t)(jt + 128 + r) * 64 + ch * 8);
            }
            cpa_commit();
        }
        float c_s[2][4][4];
        s_compute128_f16(sh + QB_OFF, sh + kb, wr, wc, gid, tig, c_s);

        const bool use_mask = mf[ji] != 0;
        #pragma unroll
        for (int mi = 0; mi < 2; mi++)
            #pragma unroll
            for (int h = 0; h < 2; h++) {
                int row = wr * 32 + mi * 16 + h * 8 + gid;
                float acc = 0.f;
                #pragma unroll
                for (int ni = 0; ni < 4; ni++) {
                    int col = wc * 32 + ni * 8 + tig * 2;
                    float s0 = c_s[mi][ni][h * 2 + 0];
                    float s1 = c_s[mi][ni][h * 2 + 1];
                    if (use_mask) {
                        size_t gi = (size_t)(i0 + row) * 2048 + jt + col;
                        if (mb[gi])     s0 = -1e9f;
                        if (mb[gi + 1]) s1 = -1e9f;
                    }
                    acc += __expf(s0 * 0.125f) + __expf(s1 * 0.125f);
                }
                rs[mi * 2 + h] += acc;
            }
        if (ji < 15) cpa_wait0();
        __syncthreads();
    }

    // ---- reduce rowsums; reload K0 -> KB0, V0 -> VS0 for pass 2 ----
    #pragma unroll
    for (int p = 0; p < 4; p++) {
        rs[p] += __shfl_xor_sync(0xffffffffu, rs[p], 1);
        rs[p] += __shfl_xor_sync(0xffffffffu, rs[p], 2);
    }
    #pragma unroll
    for (int v = 0; v < 2; v++) {
        int idx = tid + v * 512;
        int r = idx >> 3, ch = idx & 7;
        cpa16(smb + (KB0_OFF + r * 36 + ch * 4) * 4, Kbh + (size_t)r * 64 + ch * 8);
        int ci = idx;                          // 1024 chunks: V tile 64x64 u32
        int vr = ci >> 4, off = (ci & 15) * 4;
        cpa16(smb + (VS0_OFF + vr * 72 + off) * 4, Vph + (size_t)vr * 64 + off);
    }
    cpa_commit();
    if (tig == 0) {
        #pragma unroll
        for (int mi = 0; mi < 2; mi++)
            #pragma unroll
            for (int h = 0; h < 2; h++)
                swsum[wc * 128 + wr * 32 + mi * 16 + h * 8 + gid] = rs[mi * 2 + h];
    }
    __syncthreads();
    if (tid < 128)
        sinv[tid] = 1.0f / (swsum[tid] + swsum[128 + tid] + swsum[256 + tid] + swsum[384 + tid]);
    cpa_wait0();
    __syncthreads();

    // ==========  PASS 2: E store + fp16 PV (2-stage K+V pipeline)  ==========
    float c_o[2][2][4];
    #pragma unroll
    for (int mi = 0; mi < 2; mi++)
        #pragma unroll
        for (int ni = 0; ni < 2; ni++)
            #pragma unroll
            for (int r = 0; r < 4; r++) c_o[mi][ni][r] = 0.f;

    for (int ji = 0; ji < 16; ji++) {
        const int jt = ji * 128;
        const uint32_t kb = (ji & 1) ? KB1_OFF : KB0_OFF;
        const uint32_t vb = (ji & 1) ? VS1_OFF : VS0_OFF;
        if (ji < 15) {
            const uint32_t nkb = (ji & 1) ? KB0_OFF : KB1_OFF;
            const uint32_t nvb = (ji & 1) ? VS0_OFF : VS1_OFF;
            const uint32_t* vsrc = Vph + (size_t)(jt / 2 + 64) * 64;
            #pragma unroll
            for (int v = 0; v < 2; v++) {
                int idx = tid + v * 512;
                int r = idx >> 3, ch = idx & 7;
                cpa16(smb + (nkb + r * 36 + ch * 4) * 4,
                      Kbh + (size_t)(jt + 128 + r) * 64 + ch * 8);
                int vr = idx >> 4, off = (idx & 15) * 4;
                cpa16(smb + (nvb + vr * 72 + off) * 4, vsrc + (size_t)vr * 64 + off);
            }
            cpa_commit();
        }
        float c_s[2][4][4];
        s_compute128_f16(sh + QB_OFF, sh + kb, wr, wc, gid, tig, c_s);

        const bool use_mask = mf[ji] != 0;
        #pragma unroll
        for (int mi = 0; mi < 2; mi++)
            #pragma unroll
            for (int h = 0; h < 2; h++) {
                int row = wr * 32 + mi * 16 + h * 8 + gid;
                float iv = sinv[row];
                #pragma unroll
                for (int ni = 0; ni < 4; ni++) {
                    int col = wc * 32 + ni * 8 + tig * 2;
                    float s0 = c_s[mi][ni][h * 2 + 0];
                    float s1 = c_s[mi][ni][h * 2 + 1];
                    if (use_mask) {
                        size_t gi = (size_t)(i0 + row) * 2048 + jt + col;
                        if (mb[gi])     s0 = -1e9f;
                        if (mb[gi + 1]) s1 = -1e9f;
                    }
                    float e0 = __expf(s0 * 0.125f) * iv;
                    float e1 = __expf(s1 * 0.125f) * iv;
                    *(float2*)&Es[row * 132 + col] = make_float2(e0, e1);
                    Es16[row * 68 + (col >> 1)] = fpack(e0, e1);
                }
            }
        __syncthreads();    // Es / Es16 complete

        // coalesced normalized-E output, 128x128 tile
        #pragma unroll
        for (int v = 0; v < 8; v++) {
            int idx = tid + v * 512;
            int r = idx >> 5, c4 = (idx & 31) * 4;
            float4 val = *(const float4*)((const float*)&Es[r * 132 + c4]);
            *(float4*)(Eh + (size_t)(i0 + r) * 2048 + jt + c4) = val;
        }

        // PV: O += Es16(128x128) @ Vs16(128x64), warp tile 32x16
        #pragma unroll
        for (int s = 0; s < 8; s++) {
            uint32_t af[2][4], bf[2][2];
            #pragma unroll
            for (int mi = 0; mi < 2; mi++) {
                int m = wr * 32 + mi * 16 + gid;
                af[mi][0] = Es16[m * 68 + s * 8 + tig];
                af[mi][1] = Es16[(m + 8) * 68 + s * 8 + tig];
                af[mi][2] = Es16[m * 68 + s * 8 + tig + 4];
                af[mi][3] = Es16[(m + 8) * 68 + s * 8 + tig + 4];
            }
            #pragma unroll
            for (int ni = 0; ni < 2; ni++) {
                int n = wc * 16 + ni * 8 + gid;
                bf[ni][0] = sh[vb + (s * 8 + tig) * 72 + n];
                bf[ni][1] = sh[vb + (s * 8 + tig + 4) * 72 + n];
            }
            #pragma unroll
            for (int mi = 0; mi < 2; mi++)
                #pragma unroll
                for (int ni = 0; ni < 2; ni++)
                    mma16h(c_o[mi][ni], af[mi], bf[ni]);
        }
        if (ji < 15) cpa_wait0();   // next K+V resident
        __syncthreads();            // Es16 free; buffers visible to all
    }

    // ---- write O (tf32-rounded: feeds cp.async out-GEMM) ----
    #pragma unroll
    for (int mi = 0; mi < 2; mi++)
        #pragma unroll
        for (int h = 0; h < 2; h++) {
            int i = i0 + wr * 32 + mi * 16 + h * 8 + gid;
            float* Xr = g_x + (size_t)b * IW + (size_t)i * 1024 + hd * 64;
            #pragma unroll
            for (int ni = 0; ni < 2; ni++) {
                int d = wc * 16 + ni * 8 + tig * 2;
                *(float2*)(Xr + d) = make_float2(rtf(c_o[mi][ni][h * 2]),
                                                 rtf(c_o[mi][ni][h * 2 + 1]));
            }
        }
}

extern "C" void kernel_launch(void* const* d_in, const int* in_sizes, int n_in,
                              void* d_out, int out_size)
{
    const float* q  = (const float*)d_in[0];
    const float* k  = (const float*)d_in[1];
    const float* v  = (const float*)d_in[2];
    const unsigned char* mask = (const unsigned char*)d_in[3];
    const float* Wq = (const float*)d_in[4];
    const float* Wk = (const float*)d_in[5];
    const float* Wv = (const float*)d_in[6];
    const float* Wo = (const float*)d_in[7];

    float* out  = (float*)d_out;            // [4,2048,1024]
    float* attn = out + 8388608;            // [4,16,2048,2048]

    cudaFuncSetAttribute(fused_attn_kernel,
                         cudaFuncAttributeMaxDynamicSharedMemorySize, FUSED_SMEM_BYTES);
    cudaFuncSetAttribute(proj_all_kernel,
                         cudaFuncAttributeMaxDynamicSharedMemorySize, GEMM_SMEM_BYTES);
    cudaFuncSetAttribute(out_kernel,
                         cudaFuncAttributeMaxDynamicSharedMemorySize, GEMM_SMEM_BYTES);

    preround_kernel<<<2048, 256>>>((const float4*)q, (const float4*)k, (const float4*)v,
                                   (const float4*)Wq, (const float4*)Wk,
                                   (const float4*)Wv, (const float4*)Wo);
    mask_any_kernel<<<1024, 256>>>(mask);

    proj_all_kernel<<<dim3(8, 64, 3), 256, GEMM_SMEM_BYTES>>>();
    fused_attn_kernel<<<dim3(16, 64), 512, FUSED_SMEM_BYTES>>>(mask, attn);
    out_kernel<<<dim3(8, 64), 256, GEMM_SMEM_BYTES>>>(out);
}

// round 15
// speedup vs baseline: 1.8131x; 1.0317x over previous
#include <cuda_runtime.h>
#include <cuda_fp16.h>
#include <cstdint>

// MultiHeadAttention: B=4, I=J=2048, WIDTH=1024, HEADS=16, HEAD_DIM=64
// Outputs: out [4,2048,1024] fp32, attn_weight [4,16,2048,2048] fp32
//
//   0. preround:   tf32-round q/k/v and weights (proj GEMM inputs)
//   1. mask_any:   per-(b,128x128) OR-flag
//   2. proj_all:   Q -> fp16 PRE-SCALED by 0.125; K -> fp16; V -> packed-fp16
//                  j-pair layout [z][kp][d]
//   3. fused_attn: both passes fp16 m16n8k16 QK^T; E emitted from fp16 tile
//                  (cvt at STG); fp16 PV. 2-stage K+V pipeline in pass 2.
//   4. out:        out = g_x @ Wo^T (tf32 GEMM)

#define IW 2097152ULL
#define HEADELEMS 131072ULL
#define ATTN_PER_HEAD 4194304ULL

__device__ float g_x [8388608];
__device__ float g_qr[8388608];
__device__ float g_kr[8388608];
__device__ float g_vr[8388608];
__device__ float g_wq[1048576];
__device__ float g_wk[1048576];
__device__ float g_wv[1048576];
__device__ float g_wo[1048576];
__device__ __half g_qb[8388608];
__device__ __half g_kb[8388608];
__device__ uint32_t g_vh[4194304];   // packed fp16 V: [z][kp][d]
__device__ int   g_mflag[1024];

__device__ __forceinline__ uint32_t f2tf(float x) {
    uint32_t u;
    asm("cvt.rna.tf32.f32 %0, %1;" : "=r"(u) : "f"(x));
    return u;
}
__device__ __forceinline__ float rtf(float x) { return __uint_as_float(f2tf(x)); }
__device__ __forceinline__ uint32_t fpack(float a, float b) {
    __half2 h = __floats2half2_rn(a, b);
    return *(uint32_t*)&h;
}

__device__ __forceinline__ void mma8(float* c, const uint32_t* a, const uint32_t* b) {
    asm("mma.sync.aligned.m16n8k8.row.col.f32.tf32.tf32.f32 "
        "{%0,%1,%2,%3}, {%4,%5,%6,%7}, {%8,%9}, {%0,%1,%2,%3};"
        : "+f"(c[0]), "+f"(c[1]), "+f"(c[2]), "+f"(c[3])
        : "r"(a[0]), "r"(a[1]), "r"(a[2]), "r"(a[3]), "r"(b[0]), "r"(b[1]));
}
__device__ __forceinline__ void mma16h(float* c, const uint32_t* a, const uint32_t* b) {
    asm("mma.sync.aligned.m16n8k16.row.col.f32.f16.f16.f32 "
        "{%0,%1,%2,%3}, {%4,%5,%6,%7}, {%8,%9}, {%0,%1,%2,%3};"
        : "+f"(c[0]), "+f"(c[1]), "+f"(c[2]), "+f"(c[3])
        : "r"(a[0]), "r"(a[1]), "r"(a[2]), "r"(a[3]), "r"(b[0]), "r"(b[1]));
}

__device__ __forceinline__ uint32_t s2u(const void* p) {
    return (uint32_t)__cvta_generic_to_shared(p);
}
__device__ __forceinline__ void cpa16(uint32_t dst, const void* src) {
    asm volatile("cp.async.cg.shared.global [%0], [%1], 16;" :: "r"(dst), "l"(src));
}
__device__ __forceinline__ void cpa_commit() { asm volatile("cp.async.commit_group;"); }
__device__ __forceinline__ void cpa_wait0()  { asm volatile("cp.async.wait_group 0;"); }
__device__ __forceinline__ void cpa_wait1()  { asm volatile("cp.async.wait_group 1;"); }

// ---------------------------------------------------------------------------
__global__ void preround_kernel(const float4* __restrict__ q, const float4* __restrict__ k,
                                const float4* __restrict__ v, const float4* __restrict__ wq,
                                const float4* __restrict__ wk, const float4* __restrict__ wv,
                                const float4* __restrict__ wo)
{
    const int stride = gridDim.x * blockDim.x;
    for (int i = blockIdx.x * blockDim.x + threadIdx.x; i < 2097152; i += stride) {
        float4 a = q[i];
        ((float4*)g_qr)[i] = make_float4(rtf(a.x), rtf(a.y), rtf(a.z), rtf(a.w));
        float4 b = k[i];
        ((float4*)g_kr)[i] = make_float4(rtf(b.x), rtf(b.y), rtf(b.z), rtf(b.w));
        float4 c = v[i];
        ((float4*)g_vr)[i] = make_float4(rtf(c.x), rtf(c.y), rtf(c.z), rtf(c.w));
        if (i < 262144) {
            float4 w0 = wq[i];
            ((float4*)g_wq)[i] = make_float4(rtf(w0.x), rtf(w0.y), rtf(w0.z), rtf(w0.w));
            float4 w1 = wk[i];
            ((float4*)g_wk)[i] = make_float4(rtf(w1.x), rtf(w1.y), rtf(w1.z), rtf(w1.w));
            float4 w2 = wv[i];
            ((float4*)g_wv)[i] = make_float4(rtf(w2.x), rtf(w2.y), rtf(w2.z), rtf(w2.w));
            float4 w3 = wo[i];
            ((float4*)g_wo)[i] = make_float4(rtf(w3.x), rtf(w3.y), rtf(w3.z), rtf(w3.w));
        }
    }
}

// ---------------------------------------------------------------------------
__global__ void mask_any_kernel(const unsigned char* __restrict__ mask)
{
    int bid = blockIdx.x;
    int b = bid >> 8, rem = bid & 255, ib = rem >> 4, jb = rem & 15;
    const unsigned char* base = mask + (size_t)b * ATTN_PER_HEAD
                                     + (size_t)ib * 128 * 2048 + (size_t)jb * 128;
    unsigned acc = 0;
    #pragma unroll
    for (int v = 0; v < 4; v++) {
        int idx = threadIdx.x + v * 256;
        int r = idx >> 3, c = (idx & 7) * 16;
        uint4 m = *(const uint4*)(base + (size_t)r * 2048 + c);
        acc |= m.x | m.y | m.z | m.w;
    }
    int any = __syncthreads_or(acc != 0);
    if (threadIdx.x == 0) g_mflag[bid] = any;
}

// ---------------------------------------------------------------------------
// 128x128-tile TN GEMM, M=8192, N=1024, K=1024. cp.async 2-stage pipeline.
// mode 0: fp32 raw out (C).  mode 1: fp16 ONLY (Cb), scaled by qsc.
// mode 2: packed-fp16 V output (j-pair layout via smem restage).
// ---------------------------------------------------------------------------
#define GEMM_SMEM_BYTES 73728

__device__ __forceinline__ void gemm1024_body(const float* __restrict__ A,
                                              const float* __restrict__ W,
                                              float* __restrict__ C, int mode,
                                              __half* __restrict__ Cb, float qsc)
{
    extern __shared__ uint32_t dsm[];
    const int tid  = threadIdx.x;
    const int wid  = tid >> 5, lane = tid & 31;
    const int gid  = lane >> 2, tig = lane & 3;
    const int wrow = wid >> 2, wcol = wid & 3;
    const float* Ab = A + (size_t)blockIdx.y * 128 * 1024;
    const float* Bb = W + (size_t)blockIdx.x * 128 * 1024;
    const uint32_t smb = s2u(dsm);

    float c[4][4][4];
    #pragma unroll
    for (int mi = 0; mi < 4; mi++)
        #pragma unroll
        for (int ni = 0; ni < 4; ni++)
            #pragma unroll
            for (int r = 0; r < 4; r++) c[mi][ni][r] = 0.f;

    #pragma unroll
    for (int v = 0; v < 4; v++) {
        int i = tid + v * 256;
        int r = i >> 3, cu = (i & 7) << 2;
        cpa16(smb + (r * 36 + cu) * 4,        Ab + (size_t)r * 1024 + cu);
        cpa16(smb + (4608 + r * 36 + cu) * 4, Bb + (size_t)r * 1024 + cu);
    }
    cpa_commit();

    for (int kti = 0; kti < 32; kti++) {
        if (kti < 31) {
            const int s = (kti + 1) & 1;
            const int kn = (kti + 1) * 32;
            #pragma unroll
            for (int v = 0; v < 4; v++) {
                int i = tid + v * 256;
                int r = i >> 3, cu = (i & 7) << 2;
                cpa16(smb + (s * 9216 + r * 36 + cu) * 4,        Ab + (size_t)r * 1024 + kn + cu);
                cpa16(smb + (s * 9216 + 4608 + r * 36 + cu) * 4, Bb + (size_t)r * 1024 + kn + cu);
            }
            cpa_commit();
            cpa_wait1();
        } else {
            cpa_wait0();
        }
        __syncthreads();

        const uint32_t* As = dsm + (kti & 1) * 9216;
        const uint32_t* Bs = As + 4608;
        #pragma unroll
        for (int kk = 0; kk < 32; kk += 8) {
            uint32_t af[4][4], bf[4][2];
            #pragma unroll
            for (int mi = 0; mi < 4; mi++) {
                int m = wrow * 64 + mi * 16 + gid;
                af[mi][0] = As[m * 36 + kk + tig];
                af[mi][1] = As[(m + 8) * 36 + kk + tig];
                af[mi][2] = As[m * 36 + kk + tig + 4];
                af[mi][3] = As[(m + 8) * 36 + kk + tig + 4];
            }
            #pragma unroll
            for (int ni = 0; ni < 4; ni++) {
                int n = wcol * 32 + ni * 8 + gid;
                bf[ni][0] = Bs[n * 36 + kk + tig];
                bf[ni][1] = Bs[n * 36 + kk + tig + 4];
            }
            #pragma unroll
            for (int mi = 0; mi < 4; mi++)
                #pragma unroll
                for (int ni = 0; ni < 4; ni++)
                    mma8(c[mi][ni], af[mi], bf[ni]);
        }
        __syncthreads();
    }

    if (mode == 2) {
        // ---- V: restage fp32 tile to smem, emit packed fp16 j-pairs ----
        float* S = (float*)dsm;                    // 128 x 132
        #pragma unroll
        for (int mi = 0; mi < 4; mi++)
            #pragma unroll
            for (int ni = 0; ni < 4; ni++) {
                int rl = wrow * 64 + mi * 16 + gid;
                int cl = wcol * 32 + ni * 8 + tig * 2;
                S[rl * 132 + cl]            = c[mi][ni][0];
                S[rl * 132 + cl + 1]        = c[mi][ni][1];
                S[(rl + 8) * 132 + cl]      = c[mi][ni][2];
                S[(rl + 8) * 132 + cl + 1]  = c[mi][ni][3];
            }
        __syncthreads();
        const size_t zb = (size_t)blockIdx.y * 65536;
        #pragma unroll
        for (int v = 0; v < 16; v++) {
            int i2 = tid + v * 256;                // 4096 uint2, 256 threads
            int r = i2 >> 5, dp = (i2 & 31) * 2;
            uint32_t u0 = fpack(S[r * 132 + dp],     S[r * 132 + 64 + dp]);
            uint32_t u1 = fpack(S[r * 132 + dp + 1], S[r * 132 + 65 + dp]);
            size_t gi = zb + (size_t)(r * 8 + blockIdx.x) * 64 + dp;
            *(uint2*)(g_vh + gi) = make_uint2(u0, u1);
        }
        return;
    }

    #pragma unroll
    for (int mi = 0; mi < 4; mi++)
        #pragma unroll
        for (int ni = 0; ni < 4; ni++) {
            int row = blockIdx.y * 128 + wrow * 64 + mi * 16 + gid;
            int col = blockIdx.x * 128 + wcol * 32 + ni * 8 + tig * 2;
            if (mode == 1) {
                *(uint32_t*)(Cb + (size_t)row * 1024 + col)       = fpack(c[mi][ni][0] * qsc, c[mi][ni][1] * qsc);
                *(uint32_t*)(Cb + (size_t)(row + 8) * 1024 + col) = fpack(c[mi][ni][2] * qsc, c[mi][ni][3] * qsc);
            } else {
                *(float2*)(C + (size_t)row * 1024 + col)       = make_float2(c[mi][ni][0], c[mi][ni][1]);
                *(float2*)(C + (size_t)(row + 8) * 1024 + col) = make_float2(c[mi][ni][2], c[mi][ni][3]);
            }
        }
}

__global__ __launch_bounds__(256, 2)
void proj_all_kernel()
{
    const int which = blockIdx.z;
    if (which == 2) {
        gemm1024_body(g_vr, g_wv, (float*)0, 2, (__half*)0, 1.0f);
    } else {
        const float* A = (which == 0) ? g_qr : g_kr;
        const float* W = (which == 0) ? g_wq : g_wk;
        __half* Cb = (which == 0) ? g_qb : g_kb;
        const float sc = (which == 0) ? 0.125f : 1.0f;   // fold 1/sqrt(d) into Q
        gemm1024_body(A, W, (float*)0, 1, Cb, sc);
    }
}

__global__ __launch_bounds__(256, 2)
void out_kernel(float* __restrict__ C)
{
    gemm1024_body(g_x, g_wo, C, 0, (__half*)0, 1.0f);
}

// ---------------------------------------------------------------------------
// Fused attention v6. 512 threads (16 warps 4x4), per (iblk=128, head z).
// j-tile 128. Both passes fp16 m16n8k16 QK^T (Q pre-scaled by 1/8 -> no FMUL).
// E emitted from fp16 Es16 tile via cvt at STG (fp32 Es buffer REMOVED).
// smem u32: Qb 128x36 | Kb0 | Kb1 | Vs0 64x72 | Vs1 | Es16 128x68 | sinv
// ---------------------------------------------------------------------------
#define QB_OFF   0
#define KB0_OFF  4608
#define KB1_OFF  9216
#define VS0_OFF  13824
#define VS1_OFF  18432
#define ES16_OFF 23040
#define SINV_OFF 31744
#define FUSED_SMEM_U32 31872
#define FUSED_SMEM_BYTES (FUSED_SMEM_U32 * 4)

// fp16 S = Q(128x64) x K(128x64)^T, warp tile 32x32; operands packed 2/u32.
__device__ __forceinline__ void s_compute128_f16(const uint32_t* __restrict__ Qb,
                                                 const uint32_t* __restrict__ Kb,
                                                 int wr, int wc, int gid, int tig,
                                                 float c_s[2][4][4])
{
    #pragma unroll
    for (int mi = 0; mi < 2; mi++)
        #pragma unroll
        for (int ni = 0; ni < 4; ni++)
            #pragma unroll
            for (int r = 0; r < 4; r++) c_s[mi][ni][r] = 0.f;
    #pragma unroll
    for (int kk = 0; kk < 32; kk += 8) {
        uint32_t af[2][4], bf[4][2];
        #pragma unroll
        for (int mi = 0; mi < 2; mi++) {
            int m = wr * 32 + mi * 16 + gid;
            af[mi][0] = Qb[m * 36 + kk + tig];
            af[mi][1] = Qb[(m + 8) * 36 + kk + tig];
            af[mi][2] = Qb[m * 36 + kk + tig + 4];
            af[mi][3] = Qb[(m + 8) * 36 + kk + tig + 4];
        }
        #pragma unroll
        for (int ni = 0; ni < 4; ni++) {
            int n = wc * 32 + ni * 8 + gid;
            bf[ni][0] = Kb[n * 36 + kk + tig];
            bf[ni][1] = Kb[n * 36 + kk + tig + 4];
        }
        #pragma unroll
        for (int mi = 0; mi < 2; mi++)
            #pragma unroll
            for (int ni = 0; ni < 4; ni++)
                mma16h(c_s[mi][ni], af[mi], bf[ni]);
    }
}

__global__ __launch_bounds__(512, 1)
void fused_attn_kernel(const unsigned char* __restrict__ mask, float* __restrict__ E)
{
    extern __shared__ uint32_t sh[];
    uint32_t* Es16 = sh + ES16_OFF;
    float* sinv  = (float*)(sh + SINV_OFF);
    float* swsum = (float*)(sh + ES16_OFF);    // scratch (pass-1 only; Es16 idle)
    const uint32_t smb = s2u(sh);

    const int tid  = threadIdx.x;
    const int wid  = tid >> 5, lane = tid & 31;
    const int gid  = lane >> 2, tig = lane & 3;
    const int wr   = wid >> 2, wc = wid & 3;
    const int iblk = blockIdx.x;
    const int z    = blockIdx.y;
    const int b    = z >> 4, hd = z & 15;
    const int i0   = iblk * 128;

    const __half* Qbh = g_qb + (size_t)z * HEADELEMS + (size_t)i0 * 64;
    const __half* Kbh = g_kb + (size_t)z * HEADELEMS;
    const uint32_t* Vph = g_vh + (size_t)z * 65536;
    const unsigned char* mb = mask + (size_t)b * ATTN_PER_HEAD;
    const int* mf = &g_mflag[b * 256 + iblk * 16];
    float* Eh = E + (size_t)z * ATTN_PER_HEAD;

    // ---- initial: Qb (128x64 fp16, pre-scaled) + Kb tile 0 -> KB0 ----
    #pragma unroll
    for (int v = 0; v < 2; v++) {
        int idx = tid + v * 512;               // 1024 chunks of 16B (8 fp16)
        int r = idx >> 3, ch = idx & 7;
        cpa16(smb + (QB_OFF + r * 36 + ch * 4) * 4, Qbh + (size_t)r * 64 + ch * 8);
        cpa16(smb + (KB0_OFF + r * 36 + ch * 4) * 4, Kbh + (size_t)r * 64 + ch * 8);
    }
    cpa_commit();
    cpa_wait0();
    __syncthreads();

    // =================  PASS 1: rowsums  =================
    float rs[4] = {0.f, 0.f, 0.f, 0.f};
    for (int ji = 0; ji < 16; ji++) {
        const int jt = ji * 128;
        const uint32_t kb = (ji & 1) ? KB1_OFF : KB0_OFF;
        const uint32_t nb = (ji & 1) ? KB0_OFF : KB1_OFF;
        if (ji < 15) {
            #pragma unroll
            for (int v = 0; v < 2; v++) {
                int idx = tid + v * 512;
                int r = idx >> 3, ch = idx & 7;
                cpa16(smb + (nb + r * 36 + ch * 4) * 4,
                      Kbh + (size_t)(jt + 128 + r) * 64 + ch * 8);
            }
            cpa_commit();
        }
        float c_s[2][4][4];
        s_compute128_f16(sh + QB_OFF, sh + kb, wr, wc, gid, tig, c_s);

        const bool use_mask = mf[ji] != 0;
        #pragma unroll
        for (int mi = 0; mi < 2; mi++)
            #pragma unroll
            for (int h = 0; h < 2; h++) {
                int row = wr * 32 + mi * 16 + h * 8 + gid;
                float acc = 0.f;
                #pragma unroll
                for (int ni = 0; ni < 4; ni++) {
                    int col = wc * 32 + ni * 8 + tig * 2;
                    float s0 = c_s[mi][ni][h * 2 + 0];
                    float s1 = c_s[mi][ni][h * 2 + 1];
                    if (use_mask) {
                        size_t gi = (size_t)(i0 + row) * 2048 + jt + col;
                        if (mb[gi])     s0 = -1e9f;
                        if (mb[gi + 1]) s1 = -1e9f;
                    }
                    acc += __expf(s0) + __expf(s1);
                }
                rs[mi * 2 + h] += acc;
            }
        if (ji < 15) cpa_wait0();
        __syncthreads();
    }

    // ---- reduce rowsums; reload K0 -> KB0, V0 -> VS0 for pass 2 ----
    #pragma unroll
    for (int p = 0; p < 4; p++) {
        rs[p] += __shfl_xor_sync(0xffffffffu, rs[p], 1);
        rs[p] += __shfl_xor_sync(0xffffffffu, rs[p], 2);
    }
    #pragma unroll
    for (int v = 0; v < 2; v++) {
        int idx = tid + v * 512;
        int r = idx >> 3, ch = idx & 7;
        cpa16(smb + (KB0_OFF + r * 36 + ch * 4) * 4, Kbh + (size_t)r * 64 + ch * 8);
        int vr = idx >> 4, off = (idx & 15) * 4;
        cpa16(smb + (VS0_OFF + vr * 72 + off) * 4, Vph + (size_t)vr * 64 + off);
    }
    cpa_commit();
    if (tig == 0) {
        #pragma unroll
        for (int mi = 0; mi < 2; mi++)
            #pragma unroll
            for (int h = 0; h < 2; h++)
                swsum[wc * 128 + wr * 32 + mi * 16 + h * 8 + gid] = rs[mi * 2 + h];
    }
    __syncthreads();
    float inv_local = 0.f;
    if (tid < 128)
        inv_local = 1.0f / (swsum[tid] + swsum[128 + tid] + swsum[256 + tid] + swsum[384 + tid]);
    __syncthreads();                           // swsum reads done (Es16 reusable)
    if (tid < 128) sinv[tid] = inv_local;
    cpa_wait0();
    __syncthreads();

    // ==========  PASS 2: E store + fp16 PV (2-stage K+V pipeline)  ==========
    float c_o[2][2][4];
    #pragma unroll
    for (int mi = 0; mi < 2; mi++)
        #pragma unroll
        for (int ni = 0; ni < 2; ni++)
            #pragma unroll
            for (int r = 0; r < 4; r++) c_o[mi][ni][r] = 0.f;

    for (int ji = 0; ji < 16; ji++) {
        const int jt = ji * 128;
        const uint32_t kb = (ji & 1) ? KB1_OFF : KB0_OFF;
        const uint32_t vb = (ji & 1) ? VS1_OFF : VS0_OFF;
        if (ji < 15) {
            const uint32_t nkb = (ji & 1) ? KB0_OFF : KB1_OFF;
            const uint32_t nvb = (ji & 1) ? VS0_OFF : VS1_OFF;
            const uint32_t* vsrc = Vph + (size_t)(jt / 2 + 64) * 64;
            #pragma unroll
            for (int v = 0; v < 2; v++) {
                int idx = tid + v * 512;
                int r = idx >> 3, ch = idx & 7;
                cpa16(smb + (nkb + r * 36 + ch * 4) * 4,
                      Kbh + (size_t)(jt + 128 + r) * 64 + ch * 8);
                int vr = idx >> 4, off = (idx & 15) * 4;
                cpa16(smb + (nvb + vr * 72 + off) * 4, vsrc + (size_t)vr * 64 + off);
            }
            cpa_commit();
        }
        float c_s[2][4][4];
        s_compute128_f16(sh + QB_OFF, sh + kb, wr, wc, gid, tig, c_s);

        const bool use_mask = mf[ji] != 0;
        #pragma unroll
        for (int mi = 0; mi < 2; mi++)
            #pragma unroll
            for (int h = 0; h < 2; h++) {
                int row = wr * 32 + mi * 16 + h * 8 + gid;
                float iv = sinv[row];
                #pragma unroll
                for (int ni = 0; ni < 4; ni++) {
                    int col = wc * 32 + ni * 8 + tig * 2;
                    float s0 = c_s[mi][ni][h * 2 + 0];
                    float s1 = c_s[mi][ni][h * 2 + 1];
                    if (use_mask) {
                        size_t gi = (size_t)(i0 + row) * 2048 + jt + col;
                        if (mb[gi])     s0 = -1e9f;
                        if (mb[gi + 1]) s1 = -1e9f;
                    }
                    float e0 = __expf(s0) * iv;
                    float e1 = __expf(s1) * iv;
                    Es16[row * 68 + (col >> 1)] = fpack(e0, e1);
                }
            }
        __syncthreads();    // Es16 complete

        // E output: cvt fp16 tile -> fp32, coalesced STG.128
        #pragma unroll
        for (int v = 0; v < 8; v++) {
            int idx = tid + v * 512;               // 4096 uint2
            int r = idx >> 5, cp = (idx & 31) * 2;
            uint2 two = *(const uint2*)&Es16[r * 68 + cp];
            float2 f0 = __half22float2(*(__half2*)&two.x);
            float2 f1 = __half22float2(*(__half2*)&two.y);
            *(float4*)(Eh + (size_t)(i0 + r) * 2048 + jt + cp * 2) =
                make_float4(f0.x, f0.y, f1.x, f1.y);
        }

        // PV: O += Es16(128x128) @ Vs16(128x64), warp tile 32x16
        #pragma unroll
        for (int s = 0; s < 8; s++) {
            uint32_t af[2][4], bf[2][2];
            #pragma unroll
            for (int mi = 0; mi < 2; mi++) {
                int m = wr * 32 + mi * 16 + gid;
                af[mi][0] = Es16[m * 68 + s * 8 + tig];
                af[mi][1] = Es16[(m + 8) * 68 + s * 8 + tig];
                af[mi][2] = Es16[m * 68 + s * 8 + tig + 4];
                af[mi][3] = Es16[(m + 8) * 68 + s * 8 + tig + 4];
            }
            #pragma unroll
            for (int ni = 0; ni < 2; ni++) {
                int n = wc * 16 + ni * 8 + gid;
                bf[ni][0] = sh[vb + (s * 8 + tig) * 72 + n];
                bf[ni][1] = sh[vb + (s * 8 + tig + 4) * 72 + n];
            }
            #pragma unroll
            for (int mi = 0; mi < 2; mi++)
                #pragma unroll
                for (int ni = 0; ni < 2; ni++)
                    mma16h(c_o[mi][ni], af[mi], bf[ni]);
        }
        if (ji < 15) cpa_wait0();   // next K+V resident
        __syncthreads();            // Es16 free; buffers visible to all
    }

    // ---- write O (tf32-rounded: feeds cp.async out-GEMM) ----
    #pragma unroll
    for (int mi = 0; mi < 2; mi++)
        #pragma unroll
        for (int h = 0; h < 2; h++) {
            int i = i0 + wr * 32 + mi * 16 + h * 8 + gid;
            float* Xr = g_x + (size_t)b * IW + (size_t)i * 1024 + hd * 64;
            #pragma unroll
            for (int ni = 0; ni < 2; ni++) {
                int d = wc * 16 + ni * 8 + tig * 2;
                *(float2*)(Xr + d) = make_float2(rtf(c_o[mi][ni][h * 2]),
                                                 rtf(c_o[mi][ni][h * 2 + 1]));
            }
        }
}

extern "C" void kernel_launch(void* const* d_in, const int* in_sizes, int n_in,
                              void* d_out, int out_size)
{
    const float* q  = (const float*)d_in[0];
    const float* k  = (const float*)d_in[1];
    const float* v  = (const float*)d_in[2];
    const unsigned char* mask = (const unsigned char*)d_in[3];
    const float* Wq = (const float*)d_in[4];
    const float* Wk = (const float*)d_in[5];
    const float* Wv = (const float*)d_in[6];
    const float* Wo = (const float*)d_in[7];

    float* out  = (float*)d_out;            // [4,2048,1024]
    float* attn = out + 8388608;            // [4,16,2048,2048]

    cudaFuncSetAttribute(fused_attn_kernel,
                         cudaFuncAttributeMaxDynamicSharedMemorySize, FUSED_SMEM_BYTES);
    cudaFuncSetAttribute(proj_all_kernel,
                         cudaFuncAttributeMaxDynamicSharedMemorySize, GEMM_SMEM_BYTES);
    cudaFuncSetAttribute(out_kernel,
                         cudaFuncAttributeMaxDynamicSharedMemorySize, GEMM_SMEM_BYTES);

    preround_kernel<<<2048, 256>>>((const float4*)q, (const float4*)k, (const float4*)v,
                                   (const float4*)Wq, (const float4*)Wk,
                                   (const float4*)Wv, (const float4*)Wo);
    mask_any_kernel<<<1024, 256>>>(mask);

    proj_all_kernel<<<dim3(8, 64, 3), 256, GEMM_SMEM_BYTES>>>();
    fused_attn_kernel<<<dim3(16, 64), 512, FUSED_SMEM_BYTES>>>(mask, attn);
    out_kernel<<<dim3(8, 64), 256, GEMM_SMEM_BYTES>>>(out);
}

// round 16
// speedup vs baseline: 2.2634x; 1.2483x over previous
#include <cuda_runtime.h>
#include <cuda_fp16.h>
#include <cstdint>

// MultiHeadAttention: B=4, I=J=2048, WIDTH=1024, HEADS=16, HEAD_DIM=64
// Outputs: out [4,2048,1024] fp32, attn_weight [4,16,2048,2048] fp32
//
//   0. preround:   convert q/k/v and weights to fp16 (same 10-bit mantissa as
//                  tf32 -> precision-neutral), cp.async-ready
//   1. mask_any:   per-(b,128x128) OR-flag
//   2. proj_all:   fp16 m16n8k16 GEMMs. Q -> fp16 pre-scaled 0.125; K -> fp16;
//                  V -> packed-fp16 j-pair layout [z][kp][d]
//   3. fused_attn: both passes fp16 QK^T; E from fp16 tile; fp16 PV;
//                  O written as fp16 (g_xh)
//   4. out:        out = g_xh @ Wo^T (fp16 GEMM, fp32 out)

#define IW 2097152ULL
#define HEADELEMS 131072ULL
#define ATTN_PER_HEAD 4194304ULL

__device__ __align__(16) __half g_qi[8388608];
__device__ __align__(16) __half g_ki[8388608];
__device__ __align__(16) __half g_vi[8388608];
__device__ __align__(16) __half g_wq16[1048576];
__device__ __align__(16) __half g_wk16[1048576];
__device__ __align__(16) __half g_wv16[1048576];
__device__ __align__(16) __half g_wo16[1048576];
__device__ __align__(16) __half g_qb[8388608];
__device__ __align__(16) __half g_kb[8388608];
__device__ __align__(16) __half g_xh[8388608];
__device__ uint32_t g_vh[4194304];   // packed fp16 V: [z][kp][d]
__device__ int   g_mflag[1024];

__device__ __forceinline__ uint32_t fpack(float a, float b) {
    __half2 h = __floats2half2_rn(a, b);
    return *(uint32_t*)&h;
}

__device__ __forceinline__ void mma16h(float* c, const uint32_t* a, const uint32_t* b) {
    asm("mma.sync.aligned.m16n8k16.row.col.f32.f16.f16.f32 "
        "{%0,%1,%2,%3}, {%4,%5,%6,%7}, {%8,%9}, {%0,%1,%2,%3};"
        : "+f"(c[0]), "+f"(c[1]), "+f"(c[2]), "+f"(c[3])
        : "r"(a[0]), "r"(a[1]), "r"(a[2]), "r"(a[3]), "r"(b[0]), "r"(b[1]));
}

__device__ __forceinline__ uint32_t s2u(const void* p) {
    return (uint32_t)__cvta_generic_to_shared(p);
}
__device__ __forceinline__ void cpa16(uint32_t dst, const void* src) {
    asm volatile("cp.async.cg.shared.global [%0], [%1], 16;" :: "r"(dst), "l"(src));
}
__device__ __forceinline__ void cpa_commit() { asm volatile("cp.async.commit_group;"); }
__device__ __forceinline__ void cpa_wait0()  { asm volatile("cp.async.wait_group 0;"); }
__device__ __forceinline__ void cpa_wait1()  { asm volatile("cp.async.wait_group 1;"); }

// ---------------------------------------------------------------------------
__global__ void preround_kernel(const float4* __restrict__ q, const float4* __restrict__ k,
                                const float4* __restrict__ v, const float4* __restrict__ wq,
                                const float4* __restrict__ wk, const float4* __restrict__ wv,
                                const float4* __restrict__ wo)
{
    const int stride = gridDim.x * blockDim.x;
    for (int i = blockIdx.x * blockDim.x + threadIdx.x; i < 2097152; i += stride) {
        float4 a = q[i];
        ((uint2*)g_qi)[i] = make_uint2(fpack(a.x, a.y), fpack(a.z, a.w));
        float4 b = k[i];
        ((uint2*)g_ki)[i] = make_uint2(fpack(b.x, b.y), fpack(b.z, b.w));
        float4 c = v[i];
        ((uint2*)g_vi)[i] = make_uint2(fpack(c.x, c.y), fpack(c.z, c.w));
        if (i < 262144) {
            float4 w0 = wq[i];
            ((uint2*)g_wq16)[i] = make_uint2(fpack(w0.x, w0.y), fpack(w0.z, w0.w));
            float4 w1 = wk[i];
            ((uint2*)g_wk16)[i] = make_uint2(fpack(w1.x, w1.y), fpack(w1.z, w1.w));
            float4 w2 = wv[i];
            ((uint2*)g_wv16)[i] = make_uint2(fpack(w2.x, w2.y), fpack(w2.z, w2.w));
            float4 w3 = wo[i];
            ((uint2*)g_wo16)[i] = make_uint2(fpack(w3.x, w3.y), fpack(w3.z, w3.w));
        }
    }
}

// ---------------------------------------------------------------------------
__global__ void mask_any_kernel(const unsigned char* __restrict__ mask)
{
    int bid = blockIdx.x;
    int b = bid >> 8, rem = bid & 255, ib = rem >> 4, jb = rem & 15;
    const unsigned char* base = mask + (size_t)b * ATTN_PER_HEAD
                                     + (size_t)ib * 128 * 2048 + (size_t)jb * 128;
    unsigned acc = 0;
    #pragma unroll
    for (int v = 0; v < 4; v++) {
        int idx = threadIdx.x + v * 256;
        int r = idx >> 3, c = (idx & 7) * 16;
        uint4 m = *(const uint4*)(base + (size_t)r * 2048 + c);
        acc |= m.x | m.y | m.z | m.w;
    }
    int any = __syncthreads_or(acc != 0);
    if (threadIdx.x == 0) g_mflag[bid] = any;
}

// ---------------------------------------------------------------------------
// fp16 128x128-tile TN GEMM, M=8192, N=1024, K=1024. BK=64, cp.async 2-stage.
// mode 0: fp32 out (C).  mode 1: fp16 out (Cb) scaled by qsc.
// mode 2: packed-fp16 V output (j-pair layout via smem restage).
// smem: 2 stages x (A 4608 + B 4608) u32 = 73728 B. Row stride 36 u32 (64 fp16 + pad).
// ---------------------------------------------------------------------------
#define GEMM_SMEM_BYTES 73728

__device__ __forceinline__ void gemm1024h_body(const __half* __restrict__ A,
                                               const __half* __restrict__ W,
                                               float* __restrict__ C, int mode,
                                               __half* __restrict__ Cb, float qsc)
{
    extern __shared__ uint32_t dsm[];
    const int tid  = threadIdx.x;
    const int wid  = tid >> 5, lane = tid & 31;
    const int gid  = lane >> 2, tig = lane & 3;
    const int wrow = wid >> 2, wcol = wid & 3;
    const __half* Ab = A + (size_t)blockIdx.y * 128 * 1024;
    const __half* Bb = W + (size_t)blockIdx.x * 128 * 1024;
    const uint32_t smb = s2u(dsm);

    float c[4][4][4];
    #pragma unroll
    for (int mi = 0; mi < 4; mi++)
        #pragma unroll
        for (int ni = 0; ni < 4; ni++)
            #pragma unroll
            for (int r = 0; r < 4; r++) c[mi][ni][r] = 0.f;

    // prologue: stage 0 <- k[0:64)
    #pragma unroll
    for (int v = 0; v < 4; v++) {
        int i = tid + v * 256;
        int r = i >> 3, ch = i & 7;
        cpa16(smb + (r * 36 + ch * 4) * 4,        Ab + (size_t)r * 1024 + ch * 8);
        cpa16(smb + (4608 + r * 36 + ch * 4) * 4, Bb + (size_t)r * 1024 + ch * 8);
    }
    cpa_commit();

    for (int kti = 0; kti < 16; kti++) {
        if (kti < 15) {
            const int s = (kti + 1) & 1;
            const int kn = (kti + 1) * 64;
            #pragma unroll
            for (int v = 0; v < 4; v++) {
                int i = tid + v * 256;
                int r = i >> 3, ch = i & 7;
                cpa16(smb + (s * 9216 + r * 36 + ch * 4) * 4,        Ab + (size_t)r * 1024 + kn + ch * 8);
                cpa16(smb + (s * 9216 + 4608 + r * 36 + ch * 4) * 4, Bb + (size_t)r * 1024 + kn + ch * 8);
            }
            cpa_commit();
            cpa_wait1();
        } else {
            cpa_wait0();
        }
        __syncthreads();

        const uint32_t* As = dsm + (kti & 1) * 9216;
        const uint32_t* Bs = As + 4608;
        #pragma unroll
        for (int kk = 0; kk < 32; kk += 8) {       // u32 units: 4 steps of k=16
            uint32_t af[4][4], bf[4][2];
            #pragma unroll
            for (int mi = 0; mi < 4; mi++) {
                int m = wrow * 64 + mi * 16 + gid;
                af[mi][0] = As[m * 36 + kk + tig];
                af[mi][1] = As[(m + 8) * 36 + kk + tig];
                af[mi][2] = As[m * 36 + kk + tig + 4];
                af[mi][3] = As[(m + 8) * 36 + kk + tig + 4];
            }
            #pragma unroll
            for (int ni = 0; ni < 4; ni++) {
                int n = wcol * 32 + ni * 8 + gid;
                bf[ni][0] = Bs[n * 36 + kk + tig];
                bf[ni][1] = Bs[n * 36 + kk + tig + 4];
            }
            #pragma unroll
            for (int mi = 0; mi < 4; mi++)
                #pragma unroll
                for (int ni = 0; ni < 4; ni++)
                    mma16h(c[mi][ni], af[mi], bf[ni]);
        }
        __syncthreads();
    }

    if (mode == 2) {
        // ---- V: restage fp32 tile to smem, emit packed fp16 j-pairs ----
        float* S = (float*)dsm;                    // 128 x 132
        #pragma unroll
        for (int mi = 0; mi < 4; mi++)
            #pragma unroll
            for (int ni = 0; ni < 4; ni++) {
                int rl = wrow * 64 + mi * 16 + gid;
                int cl = wcol * 32 + ni * 8 + tig * 2;
                S[rl * 132 + cl]            = c[mi][ni][0];
                S[rl * 132 + cl + 1]        = c[mi][ni][1];
                S[(rl + 8) * 132 + cl]      = c[mi][ni][2];
                S[(rl + 8) * 132 + cl + 1]  = c[mi][ni][3];
            }
        __syncthreads();
        const size_t zb = (size_t)blockIdx.y * 65536;
        #pragma unroll
        for (int v = 0; v < 16; v++) {
            int i2 = tid + v * 256;                // 4096 uint2, 256 threads
            int r = i2 >> 5, dp = (i2 & 31) * 2;
            uint32_t u0 = fpack(S[r * 132 + dp],     S[r * 132 + 64 + dp]);
            uint32_t u1 = fpack(S[r * 132 + dp + 1], S[r * 132 + 65 + dp]);
            size_t gi = zb + (size_t)(r * 8 + blockIdx.x) * 64 + dp;
            *(uint2*)(g_vh + gi) = make_uint2(u0, u1);
        }
        return;
    }

    #pragma unroll
    for (int mi = 0; mi < 4; mi++)
        #pragma unroll
        for (int ni = 0; ni < 4; ni++) {
            int row = blockIdx.y * 128 + wrow * 64 + mi * 16 + gid;
            int col = blockIdx.x * 128 + wcol * 32 + ni * 8 + tig * 2;
            if (mode == 1) {
                *(uint32_t*)(Cb + (size_t)row * 1024 + col)       = fpack(c[mi][ni][0] * qsc, c[mi][ni][1] * qsc);
                *(uint32_t*)(Cb + (size_t)(row + 8) * 1024 + col) = fpack(c[mi][ni][2] * qsc, c[mi][ni][3] * qsc);
            } else {
                *(float2*)(C + (size_t)row * 1024 + col)       = make_float2(c[mi][ni][0], c[mi][ni][1]);
                *(float2*)(C + (size_t)(row + 8) * 1024 + col) = make_float2(c[mi][ni][2], c[mi][ni][3]);
            }
        }
}

__global__ __launch_bounds__(256, 2)
void proj_all_kernel()
{
    const int which = blockIdx.z;
    if (which == 2) {
        gemm1024h_body(g_vi, g_wv16, (float*)0, 2, (__half*)0, 1.0f);
    } else {
        const __half* A = (which == 0) ? g_qi : g_ki;
        const __half* W = (which == 0) ? g_wq16 : g_wk16;
        __half* Cb = (which == 0) ? g_qb : g_kb;
        const float sc = (which == 0) ? 0.125f : 1.0f;   // fold 1/sqrt(d) into Q
        gemm1024h_body(A, W, (float*)0, 1, Cb, sc);
    }
}

__global__ __launch_bounds__(256, 2)
void out_kernel(float* __restrict__ C)
{
    gemm1024h_body(g_xh, g_wo16, C, 0, (__half*)0, 1.0f);
}

// ---------------------------------------------------------------------------
// Fused attention v6 (unchanged from R15 except O stored as fp16).
// 512 threads (16 warps 4x4), per (iblk=128, head z). j-tile 128.
// smem u32: Qb 128x36 | Kb0 | Kb1 | Vs0 64x72 | Vs1 | Es16 128x68 | sinv
// ---------------------------------------------------------------------------
#define QB_OFF   0
#define KB0_OFF  4608
#define KB1_OFF  9216
#define VS0_OFF  13824
#define VS1_OFF  18432
#define ES16_OFF 23040
#define SINV_OFF 31744
#define FUSED_SMEM_U32 31872
#define FUSED_SMEM_BYTES (FUSED_SMEM_U32 * 4)

__device__ __forceinline__ void s_compute128_f16(const uint32_t* __restrict__ Qb,
                                                 const uint32_t* __restrict__ Kb,
                                                 int wr, int wc, int gid, int tig,
                                                 float c_s[2][4][4])
{
    #pragma unroll
    for (int mi = 0; mi < 2; mi++)
        #pragma unroll
        for (int ni = 0; ni < 4; ni++)
            #pragma unroll
            for (int r = 0; r < 4; r++) c_s[mi][ni][r] = 0.f;
    #pragma unroll
    for (int kk = 0; kk < 32; kk += 8) {
        uint32_t af[2][4], bf[4][2];
        #pragma unroll
        for (int mi = 0; mi < 2; mi++) {
            int m = wr * 32 + mi * 16 + gid;
            af[mi][0] = Qb[m * 36 + kk + tig];
            af[mi][1] = Qb[(m + 8) * 36 + kk + tig];
            af[mi][2] = Qb[m * 36 + kk + tig + 4];
            af[mi][3] = Qb[(m + 8) * 36 + kk + tig + 4];
        }
        #pragma unroll
        for (int ni = 0; ni < 4; ni++) {
            int n = wc * 32 + ni * 8 + gid;
            bf[ni][0] = Kb[n * 36 + kk + tig];
            bf[ni][1] = Kb[n * 36 + kk + tig + 4];
        }
        #pragma unroll
        for (int mi = 0; mi < 2; mi++)
            #pragma unroll
            for (int ni = 0; ni < 4; ni++)
                mma16h(c_s[mi][ni], af[mi], bf[ni]);
    }
}

__global__ __launch_bounds__(512, 1)
void fused_attn_kernel(const unsigned char* __restrict__ mask, float* __restrict__ E)
{
    extern __shared__ uint32_t sh[];
    uint32_t* Es16 = sh + ES16_OFF;
    float* sinv  = (float*)(sh + SINV_OFF);
    float* swsum = (float*)(sh + ES16_OFF);    // scratch (pass-1 only; Es16 idle)
    const uint32_t smb = s2u(sh);

    const int tid  = threadIdx.x;
    const int wid  = tid >> 5, lane = tid & 31;
    const int gid  = lane >> 2, tig = lane & 3;
    const int wr   = wid >> 2, wc = wid & 3;
    const int iblk = blockIdx.x;
    const int z    = blockIdx.y;
    const int b    = z >> 4, hd = z & 15;
    const int i0   = iblk * 128;

    const __half* Qbh = g_qb + (size_t)z * HEADELEMS + (size_t)i0 * 64;
    const __half* Kbh = g_kb + (size_t)z * HEADELEMS;
    const uint32_t* Vph = g_vh + (size_t)z * 65536;
    const unsigned char* mb = mask + (size_t)b * ATTN_PER_HEAD;
    const int* mf = &g_mflag[b * 256 + iblk * 16];
    float* Eh = E + (size_t)z * ATTN_PER_HEAD;

    // ---- initial: Qb (128x64 fp16, pre-scaled) + Kb tile 0 -> KB0 ----
    #pragma unroll
    for (int v = 0; v < 2; v++) {
        int idx = tid + v * 512;               // 1024 chunks of 16B (8 fp16)
        int r = idx >> 3, ch = idx & 7;
        cpa16(smb + (QB_OFF + r * 36 + ch * 4) * 4, Qbh + (size_t)r * 64 + ch * 8);
        cpa16(smb + (KB0_OFF + r * 36 + ch * 4) * 4, Kbh + (size_t)r * 64 + ch * 8);
    }
    cpa_commit();
    cpa_wait0();
    __syncthreads();

    // =================  PASS 1: rowsums  =================
    float rs[4] = {0.f, 0.f, 0.f, 0.f};
    for (int ji = 0; ji < 16; ji++) {
        const int jt = ji * 128;
        const uint32_t kb = (ji & 1) ? KB1_OFF : KB0_OFF;
        const uint32_t nb = (ji & 1) ? KB0_OFF : KB1_OFF;
        if (ji < 15) {
            #pragma unroll
            for (int v = 0; v < 2; v++) {
                int idx = tid + v * 512;
                int r = idx >> 3, ch = idx & 7;
                cpa16(smb + (nb + r * 36 + ch * 4) * 4,
                      Kbh + (size_t)(jt + 128 + r) * 64 + ch * 8);
            }
            cpa_commit();
        }
        float c_s[2][4][4];
        s_compute128_f16(sh + QB_OFF, sh + kb, wr, wc, gid, tig, c_s);

        const bool use_mask = mf[ji] != 0;
        #pragma unroll
        for (int mi = 0; mi < 2; mi++)
            #pragma unroll
            for (int h = 0; h < 2; h++) {
                int row = wr * 32 + mi * 16 + h * 8 + gid;
                float acc = 0.f;
                #pragma unroll
                for (int ni = 0; ni < 4; ni++) {
                    int col = wc * 32 + ni * 8 + tig * 2;
                    float s0 = c_s[mi][ni][h * 2 + 0];
                    float s1 = c_s[mi][ni][h * 2 + 1];
                    if (use_mask) {
                        size_t gi = (size_t)(i0 + row) * 2048 + jt + col;
                        if (mb[gi])     s0 = -1e9f;
                        if (mb[gi + 1]) s1 = -1e9f;
                    }
                    acc += __expf(s0) + __expf(s1);
                }
                rs[mi * 2 + h] += acc;
            }
        if (ji < 15) cpa_wait0();
        __syncthreads();
    }

    // ---- reduce rowsums; reload K0 -> KB0, V0 -> VS0 for pass 2 ----
    #pragma unroll
    for (int p = 0; p < 4; p++) {
        rs[p] += __shfl_xor_sync(0xffffffffu, rs[p], 1);
        rs[p] += __shfl_xor_sync(0xffffffffu, rs[p], 2);
    }
    #pragma unroll
    for (int v = 0; v < 2; v++) {
        int idx = tid + v * 512;
        int r = idx >> 3, ch = idx & 7;
        cpa16(smb + (KB0_OFF + r * 36 + ch * 4) * 4, Kbh + (size_t)r * 64 + ch * 8);
        int vr = idx >> 4, off = (idx & 15) * 4;
        cpa16(smb + (VS0_OFF + vr * 72 + off) * 4, Vph + (size_t)vr * 64 + off);
    }
    cpa_commit();
    if (tig == 0) {
        #pragma unroll
        for (int mi = 0; mi < 2; mi++)
            #pragma unroll
            for (int h = 0; h < 2; h++)
                swsum[wc * 128 + wr * 32 + mi * 16 + h * 8 + gid] = rs[mi * 2 + h];
    }
    __syncthreads();
    float inv_local = 0.f;
    if (tid < 128)
        inv_local = 1.0f / (swsum[tid] + swsum[128 + tid] + swsum[256 + tid] + swsum[384 + tid]);
    __syncthreads();                           // swsum reads done (Es16 reusable)
    if (tid < 128) sinv[tid] = inv_local;
    cpa_wait0();
    __syncthreads();

    // ==========  PASS 2: E store + fp16 PV (2-stage K+V pipeline)  ==========
    float c_o[2][2][4];
    #pragma unroll
    for (int mi = 0; mi < 2; mi++)
        #pragma unroll
        for (int ni = 0; ni < 2; ni++)
            #pragma unroll
            for (int r = 0; r < 4; r++) c_o[mi][ni][r] = 0.f;

    for (int ji = 0; ji < 16; ji++) {
        const int jt = ji * 128;
        const uint32_t kb = (ji & 1) ? KB1_OFF : KB0_OFF;
        const uint32_t vb = (ji & 1) ? VS1_OFF : VS0_OFF;
        if (ji < 15) {
            const uint32_t nkb = (ji & 1) ? KB0_OFF : KB1_OFF;
            const uint32_t nvb = (ji & 1) ? VS0_OFF : VS1_OFF;
            const uint32_t* vsrc = Vph + (size_t)(jt / 2 + 64) * 64;
            #pragma unroll
            for (int v = 0; v < 2; v++) {
                int idx = tid + v * 512;
                int r = idx >> 3, ch = idx & 7;
                cpa16(smb + (nkb + r * 36 + ch * 4) * 4,
                      Kbh + (size_t)(jt + 128 + r) * 64 + ch * 8);
                int vr = idx >> 4, off = (idx & 15) * 4;
                cpa16(smb + (nvb + vr * 72 + off) * 4, vsrc + (size_t)vr * 64 + off);
            }
            cpa_commit();
        }
        float c_s[2][4][4];
        s_compute128_f16(sh + QB_OFF, sh + kb, wr, wc, gid, tig, c_s);

        const bool use_mask = mf[ji] != 0;
        #pragma unroll
        for (int mi = 0; mi < 2; mi++)
            #pragma unroll
            for (int h = 0; h < 2; h++) {
                int row = wr * 32 + mi * 16 + h * 8 + gid;
                float iv = sinv[row];
                #pragma unroll
                for (int ni = 0; ni < 4; ni++) {
                    int col = wc * 32 + ni * 8 + tig * 2;
                    float s0 = c_s[mi][ni][h * 2 + 0];
                    float s1 = c_s[mi][ni][h * 2 + 1];
                    if (use_mask) {
                        size_t gi = (size_t)(i0 + row) * 2048 + jt + col;
                        if (mb[gi])     s0 = -1e9f;
                        if (mb[gi + 1]) s1 = -1e9f;
                    }
                    float e0 = __expf(s0) * iv;
                    float e1 = __expf(s1) * iv;
                    Es16[row * 68 + (col >> 1)] = fpack(e0, e1);
                }
            }
        __syncthreads();    // Es16 complete

        // E output: cvt fp16 tile -> fp32, coalesced STG.128
        #pragma unroll
        for (int v = 0; v < 8; v++) {
            int idx = tid + v * 512;               // 4096 uint2
            int r = idx >> 5, cp = (idx & 31) * 2;
            uint2 two = *(const uint2*)&Es16[r * 68 + cp];
            float2 f0 = __half22float2(*(__half2*)&two.x);
            float2 f1 = __half22float2(*(__half2*)&two.y);
            *(float4*)(Eh + (size_t)(i0 + r) * 2048 + jt + cp * 2) =
                make_float4(f0.x, f0.y, f1.x, f1.y);
        }

        // PV: O += Es16(128x128) @ Vs16(128x64), warp tile 32x16
        #pragma unroll
        for (int s = 0; s < 8; s++) {
            uint32_t af[2][4], bf[2][2];
            #pragma unroll
            for (int mi = 0; mi < 2; mi++) {
                int m = wr * 32 + mi * 16 + gid;
                af[mi][0] = Es16[m * 68 + s * 8 + tig];
                af[mi][1] = Es16[(m + 8) * 68 + s * 8 + tig];
                af[mi][2] = Es16[m * 68 + s * 8 + tig + 4];
                af[mi][3] = Es16[(m + 8) * 68 + s * 8 + tig + 4];
            }
            #pragma unroll
            for (int ni = 0; ni < 2; ni++) {
                int n = wc * 16 + ni * 8 + gid;
                bf[ni][0] = sh[vb + (s * 8 + tig) * 72 + n];
                bf[ni][1] = sh[vb + (s * 8 + tig + 4) * 72 + n];
            }
            #pragma unroll
            for (int mi = 0; mi < 2; mi++)
                #pragma unroll
                for (int ni = 0; ni < 2; ni++)
                    mma16h(c_o[mi][ni], af[mi], bf[ni]);
        }
        if (ji < 15) cpa_wait0();   // next K+V resident
        __syncthreads();            // Es16 free; buffers visible to all
    }

    // ---- write O as fp16 (feeds fp16 out-GEMM) ----
    #pragma unroll
    for (int mi = 0; mi < 2; mi++)
        #pragma unroll
        for (int h = 0; h < 2; h++) {
            int i = i0 + wr * 32 + mi * 16 + h * 8 + gid;
            __half* Xr = g_xh + (size_t)b * IW + (size_t)i * 1024 + hd * 64;
            #pragma unroll
            for (int ni = 0; ni < 2; ni++) {
                int d = wc * 16 + ni * 8 + tig * 2;
                *(uint32_t*)(Xr + d) = fpack(c_o[mi][ni][h * 2], c_o[mi][ni][h * 2 + 1]);
            }
        }
}

extern "C" void kernel_launch(void* const* d_in, const int* in_sizes, int n_in,
                              void* d_out, int out_size)
{
    const float* q  = (const float*)d_in[0];
    const float* k  = (const float*)d_in[1];
    const float* v  = (const float*)d_in[2];
    const unsigned char* mask = (const unsigned char*)d_in[3];
    const float* Wq = (const float*)d_in[4];
    const float* Wk = (const float*)d_in[5];
    const float* Wv = (const float*)d_in[6];
    const float* Wo = (const float*)d_in[7];

    float* out  = (float*)d_out;            // [4,2048,1024]
    float* attn = out + 8388608;            // [4,16,2048,2048]

    cudaFuncSetAttribute(fused_attn_kernel,
                         cudaFuncAttributeMaxDynamicSharedMemorySize, FUSED_SMEM_BYTES);
    cudaFuncSetAttribute(proj_all_kernel,
                         cudaFuncAttributeMaxDynamicSharedMemorySize, GEMM_SMEM_BYTES);
    cudaFuncSetAttribute(out_kernel,
                         cudaFuncAttributeMaxDynamicSharedMemorySize, GEMM_SMEM_BYTES);

    preround_kernel<<<2048, 256>>>((const float4*)q, (const float4*)k, (const float4*)v,
                                   (const float4*)Wq, (const float4*)Wk,
                                   (const float4*)Wv, (const float4*)Wo);
    mask_any_kernel<<<1024, 256>>>(mask);

    proj_all_kernel<<<dim3(8, 64, 3), 256, GEMM_SMEM_BYTES>>>();
    fused_attn_kernel<<<dim3(16, 64), 512, FUSED_SMEM_BYTES>>>(mask, attn);
    out_kernel<<<dim3(8, 64), 256, GEMM_SMEM_BYTES>>>(out);
}